// round 2
// baseline (speedup 1.0000x reference)
#include <cuda_runtime.h>
#include <cstdint>

// B=4, S=1024, E=1024, H=16, D=64, DM=1024, BH=64
// Staged fp32 pipeline, packed f32x2 FMA inner loops.

__device__ __align__(128) float g_q[64 * 1024 * 64];
__device__ __align__(128) float g_k[64 * 1024 * 64];
__device__ __align__(128) float g_v[64 * 1024 * 64];
__device__ __align__(128) float g_w[67108864];          // [bh][s][t] logits/weights
__device__ __align__(128) float g_att[4096 * 1024];     // [b*s][h*d]

__device__ __forceinline__ uint64_t rep2(float x) {
    uint64_t r; asm("mov.b64 %0, {%1, %1};" : "=l"(r) : "f"(x)); return r;
}
__device__ __forceinline__ void fma2(uint64_t& d, uint64_t a, uint64_t b) {
    asm("fma.rn.f32x2 %0, %1, %2, %0;" : "+l"(d) : "l"(a), "l"(b));
}
__device__ __forceinline__ float lo32(uint64_t v) { return __uint_as_float((unsigned)v); }
__device__ __forceinline__ float hi32(uint64_t v) { return __uint_as_float((unsigned)(v >> 32)); }

// TM rows x (2*TNP) cols outer product micro-step
template <int TM, int TNP>
__device__ __forceinline__ void mmstep(const float* a, const float* b, uint64_t (&acc)[TM][TNP]) {
    float av[TM];
#pragma unroll
    for (int i = 0; i < TM; i += 4) { float4 t = *(const float4*)(a + i);
        av[i] = t.x; av[i+1] = t.y; av[i+2] = t.z; av[i+3] = t.w; }
    uint64_t bp[TNP];
#pragma unroll
    for (int j = 0; j < TNP; j += 2) { ulonglong2 t = *(const ulonglong2*)(b + 2*j);
        bp[j] = t.x; bp[j+1] = t.y; }
#pragma unroll
    for (int i = 0; i < TM; i++) { uint64_t ar = rep2(av[i]);
#pragma unroll
        for (int j = 0; j < TNP; j++) fma2(acc[i][j], ar, bp[j]); }
}

// load TM x 16 tile (rows of G, row-stride ld) transposed into S[16][TM]
template <int TM>
__device__ __forceinline__ void ldT(float (*S)[TM], const float* G, int ld) {
    for (int i = threadIdx.x; i < 4 * TM; i += 256) {
        int m = i >> 2, k = (i & 3) * 4;
        float4 v = *(const float4*)(G + (size_t)m * ld + k);
        S[k][m] = v.x; S[k+1][m] = v.y; S[k+2][m] = v.z; S[k+3][m] = v.w;
    }
}
// load 16 x TN tile (row-major, row-stride ld) straight into S[16][TN]
template <int TN>
__device__ __forceinline__ void ldN(float (*S)[TN], const float* G, int ld) {
    for (int i = threadIdx.x; i < 4 * TN; i += 256) {
        int k = i / (TN / 4), n = (i % (TN / 4)) * 4;
        *(float4*)&S[k][n] = *(const float4*)(G + (size_t)k * ld + n);
    }
}

// K1: q/k/v = X @ W + b, scatter to [bh][s][d]; q scaled by D^-0.5
__global__ __launch_bounds__(256) void k1_qkv(
    const float* Xq, const float* Xk, const float* Xv,
    const float* Wq, const float* bq, const float* Wk, const float* bk,
    const float* Wv, const float* bv) {
    __shared__ __align__(16) float As[16][128], Bs[16][128];
    const float *X, *W, *bias; float* out; float sc;
    if (blockIdx.z == 0)      { X=Xq; W=Wq; bias=bq; out=g_q; sc=0.125f; }
    else if (blockIdx.z == 1) { X=Xk; W=Wk; bias=bk; out=g_k; sc=1.f; }
    else                      { X=Xv; W=Wv; bias=bv; out=g_v; sc=1.f; }
    int m0 = blockIdx.y * 128, n0 = blockIdx.x * 128;
    int tr = threadIdx.x >> 4, tc = threadIdx.x & 15;
    uint64_t acc[8][4] = {};
    for (int k0 = 0; k0 < 1024; k0 += 16) {
        ldT<128>(As, X + (size_t)m0 * 1024 + k0, 1024);
        ldN<128>(Bs, W + (size_t)k0 * 1024 + n0, 1024);
        __syncthreads();
#pragma unroll
        for (int kk = 0; kk < 16; kk++) mmstep<8,4>(&As[kk][tr*8], &Bs[kk][tc*8], acc);
        __syncthreads();
    }
#pragma unroll
    for (int i = 0; i < 8; i++) { int m = m0 + tr*8 + i, b = m >> 10, s = m & 1023;
#pragma unroll
        for (int j = 0; j < 4; j++) { int n = n0 + tc*8 + 2*j, h = n >> 6, d = n & 63;
            size_t o = ((size_t)(b*16 + h) * 1024 + s) * 64 + d;
            out[o]   = (lo32(acc[i][j]) + bias[n])   * sc;
            out[o+1] = (hi32(acc[i][j]) + bias[n+1]) * sc; } }
}

// K2: per bh, L[s,t] = q.k^T + attn_bias
__global__ __launch_bounds__(256) void k2_content(const float* __restrict__ bias) {
    __shared__ __align__(16) float As[16][128], Bs[16][128];
    int bh = blockIdx.z, m0 = blockIdx.y * 128, n0 = blockIdx.x * 128;
    const float* A = g_q + (size_t)bh * 65536;
    const float* B = g_k + (size_t)bh * 65536;
    int tr = threadIdx.x >> 4, tc = threadIdx.x & 15;
    uint64_t acc[8][4] = {};
    for (int k0 = 0; k0 < 64; k0 += 16) {
        ldT<128>(As, A + (size_t)m0 * 64 + k0, 64);
        ldT<128>(Bs, B + (size_t)n0 * 64 + k0, 64);
        __syncthreads();
#pragma unroll
        for (int kk = 0; kk < 16; kk++) mmstep<8,4>(&As[kk][tr*8], &Bs[kk][tc*8], acc);
        __syncthreads();
    }
    size_t base = (size_t)bh * 1048576;
#pragma unroll
    for (int i = 0; i < 8; i++) { int s = m0 + tr*8 + i;
#pragma unroll
        for (int j = 0; j < 4; j++) { int t = n0 + tc*8 + 2*j;
            size_t idx = base + (size_t)s * 1024 + t;
            g_w[idx]   = lo32(acc[i][j]) + bias[idx];
            g_w[idx+1] = hi32(acc[i][j]) + bias[idx+1]; } }
}

// K3: per s, L[bh,t] += q_s[bh,:] @ EK_s[t,:]^T
__global__ __launch_bounds__(256) void k3_edgelogit(const float* __restrict__ ek) {
    __shared__ __align__(16) float As[16][64], Bs[16][128];
    int s = blockIdx.z, n0 = blockIdx.x * 128;
    const float* eks = ek + (size_t)s * 65536;
    int tr = threadIdx.x >> 4, tc = threadIdx.x & 15;
    uint64_t acc[4][4] = {};
    for (int k0 = 0; k0 < 64; k0 += 16) {
        ldT<64>(As, g_q + (size_t)s * 64 + k0, 65536);
        ldT<128>(Bs, eks + (size_t)n0 * 64 + k0, 64);
        __syncthreads();
#pragma unroll
        for (int kk = 0; kk < 16; kk++) mmstep<4,4>(&As[kk][tr*4], &Bs[kk][tc*8], acc);
        __syncthreads();
    }
#pragma unroll
    for (int i = 0; i < 4; i++) { int bh = tr*4 + i;
#pragma unroll
        for (int j = 0; j < 4; j++) { int t = n0 + tc*8 + 2*j;
            size_t idx = (size_t)bh * 1048576 + (size_t)s * 1024 + t;
            g_w[idx]   += lo32(acc[i][j]);
            g_w[idx+1] += hi32(acc[i][j]); } }
}

// K4: row softmax (65536 rows x 1024)
__global__ __launch_bounds__(256) void k4_softmax() {
    __shared__ float red[8];
    float* p = g_w + (size_t)blockIdx.x * 1024;
    int tid = threadIdx.x;
    float4 v = *(float4*)&p[tid * 4];
    float mx = fmaxf(fmaxf(v.x, v.y), fmaxf(v.z, v.w));
#pragma unroll
    for (int o = 16; o; o >>= 1) mx = fmaxf(mx, __shfl_xor_sync(~0u, mx, o));
    if ((tid & 31) == 0) red[tid >> 5] = mx;
    __syncthreads();
    float bm = red[0];
#pragma unroll
    for (int i = 1; i < 8; i++) bm = fmaxf(bm, red[i]);
    v.x = __expf(v.x - bm); v.y = __expf(v.y - bm);
    v.z = __expf(v.z - bm); v.w = __expf(v.w - bm);
    float sm = v.x + v.y + v.z + v.w;
#pragma unroll
    for (int o = 16; o; o >>= 1) sm += __shfl_xor_sync(~0u, sm, o);
    __syncthreads();
    if ((tid & 31) == 0) red[tid >> 5] = sm;
    __syncthreads();
    float tot = 0.f;
#pragma unroll
    for (int i = 0; i < 8; i++) tot += red[i];
    float inv = 1.0f / tot;
    v.x *= inv; v.y *= inv; v.z *= inv; v.w *= inv;
    *(float4*)&p[tid * 4] = v;
}

// K5: per bh, att[s,d] = W @ V
__global__ __launch_bounds__(256) void k5_pv() {
    __shared__ __align__(16) float As[16][128], Bs[16][64];
    int bh = blockIdx.y, m0 = blockIdx.x * 128;
    const float* Wm = g_w + (size_t)bh * 1048576;
    const float* Vm = g_v + (size_t)bh * 65536;
    int tr = threadIdx.x >> 4, tc = threadIdx.x & 15;
    uint64_t acc[8][2] = {};
    for (int k0 = 0; k0 < 1024; k0 += 16) {
        ldT<128>(As, Wm + (size_t)m0 * 1024 + k0, 1024);
        ldN<64>(Bs, Vm + (size_t)k0 * 64, 64);
        __syncthreads();
#pragma unroll
        for (int kk = 0; kk < 16; kk++) mmstep<8,2>(&As[kk][tr*8], &Bs[kk][tc*4], acc);
        __syncthreads();
    }
    int b = bh >> 4, h = bh & 15;
#pragma unroll
    for (int i = 0; i < 8; i++) { int s = m0 + tr*8 + i;
#pragma unroll
        for (int j = 0; j < 2; j++) { int d = tc*4 + 2*j;
            size_t o = ((size_t)(b*1024 + s)) * 1024 + h*64 + d;
            g_att[o]   = lo32(acc[i][j]);
            g_att[o+1] = hi32(acc[i][j]); } }
}

// K6: per s, att[bh,d] += W[bh,s,:] @ EV_s
__global__ __launch_bounds__(256) void k6_ev(const float* __restrict__ ev) {
    __shared__ __align__(16) float As[16][64], Bs[16][64];
    int s = blockIdx.x;
    const float* evs = ev + (size_t)s * 65536;
    int tr = threadIdx.x >> 4, tc = threadIdx.x & 15;
    uint64_t acc[4][2] = {};
    for (int k0 = 0; k0 < 1024; k0 += 16) {
        ldT<64>(As, g_w + (size_t)s * 1024 + k0, 1048576);
        ldN<64>(Bs, evs + (size_t)k0 * 64, 64);
        __syncthreads();
#pragma unroll
        for (int kk = 0; kk < 16; kk++) mmstep<4,2>(&As[kk][tr*4], &Bs[kk][tc*4], acc);
        __syncthreads();
    }
#pragma unroll
    for (int i = 0; i < 4; i++) { int bh = tr*4 + i, b = bh >> 4, h = bh & 15;
#pragma unroll
        for (int j = 0; j < 2; j++) { int d = tc*4 + 2*j;
            size_t o = ((size_t)(b*1024 + s)) * 1024 + h*64 + d;
            g_att[o]   += lo32(acc[i][j]);
            g_att[o+1] += hi32(acc[i][j]); } }
}

// K7: out = att @ Wp + bp
__global__ __launch_bounds__(256) void k7_proj(const float* __restrict__ Wp,
                                               const float* __restrict__ bp,
                                               float* __restrict__ out) {
    __shared__ __align__(16) float As[16][128], Bs[16][128];
    int m0 = blockIdx.y * 128, n0 = blockIdx.x * 128;
    int tr = threadIdx.x >> 4, tc = threadIdx.x & 15;
    uint64_t acc[8][4] = {};
    for (int k0 = 0; k0 < 1024; k0 += 16) {
        ldT<128>(As, g_att + (size_t)m0 * 1024 + k0, 1024);
        ldN<128>(Bs, Wp + (size_t)k0 * 1024 + n0, 1024);
        __syncthreads();
#pragma unroll
        for (int kk = 0; kk < 16; kk++) mmstep<8,4>(&As[kk][tr*8], &Bs[kk][tc*8], acc);
        __syncthreads();
    }
#pragma unroll
    for (int i = 0; i < 8; i++) { int m = m0 + tr*8 + i;
#pragma unroll
        for (int j = 0; j < 4; j++) { int n = n0 + tc*8 + 2*j;
            out[(size_t)m * 1024 + n]     = lo32(acc[i][j]) + bp[n];
            out[(size_t)m * 1024 + n + 1] = hi32(acc[i][j]) + bp[n+1]; } }
}

extern "C" void kernel_launch(void* const* d_in, const int* in_sizes, int n_in,
                              void* d_out, int out_size) {
    const float* queries     = (const float*)d_in[0];
    const float* keys        = (const float*)d_in[1];
    const float* values      = (const float*)d_in[2];
    const float* edges_key   = (const float*)d_in[3];
    const float* edges_value = (const float*)d_in[4];
    const float* attn_bias   = (const float*)d_in[5];
    const float* Wq = (const float*)d_in[6];  const float* bq = (const float*)d_in[7];
    const float* Wk = (const float*)d_in[8];  const float* bk = (const float*)d_in[9];
    const float* Wv = (const float*)d_in[10]; const float* bv = (const float*)d_in[11];
    const float* Wp = (const float*)d_in[12]; const float* bp = (const float*)d_in[13];

    k1_qkv<<<dim3(8, 32, 3), 256>>>(queries, keys, values, Wq, bq, Wk, bk, Wv, bv);
    k2_content<<<dim3(8, 8, 64), 256>>>(attn_bias);
    k3_edgelogit<<<dim3(8, 1, 1024), 256>>>(edges_key);
    k4_softmax<<<65536, 256>>>();
    k5_pv<<<dim3(8, 64), 256>>>();
    k6_ev<<<1024, 256>>>(edges_value);
    k7_proj<<<dim3(8, 32), 256>>>(Wp, bp, (float*)d_out);
}

// round 4
// speedup vs baseline: 1.7895x; 1.7895x over previous
#include <cuda_runtime.h>
#include <cuda_bf16.h>
#include <cstdint>

// B=4, S=1024, E=1024, H=16, D=64, BH=64.
// All GEMMs on mma.sync m16n8k16 bf16 (compute_103-safe) with 2-term bf16
// split (3 products, fp32 accum). fp32 edge tensors are split to bf16 in-kernel.

#define DI __device__ __forceinline__

// ---------------- device scratch ----------------
__device__ __align__(128) float g_w[67108864];                 // fp32 logits [bh][s][t]
__device__ __align__(128) float g_att[4194304];                // fp32 att [b*s][h*d]
__device__ __align__(128) __nv_bfloat16 g_xh[3*4194304], g_xl[3*4194304];   // X hi/lo
__device__ __align__(128) __nv_bfloat16 g_wth[4*1048576], g_wtl[4*1048576]; // W^T hi/lo [mat][n][k]
__device__ __align__(128) __nv_bfloat16 g_qh[4194304], g_ql[4194304];       // [bh][s][d]
__device__ __align__(128) __nv_bfloat16 g_kh[4194304], g_kl[4194304];       // [bh][t][d]
__device__ __align__(128) __nv_bfloat16 g_vh[4194304], g_vl[4194304];       // [bh][s][d]
__device__ __align__(128) __nv_bfloat16 g_vth[4194304], g_vtl[4194304];     // [bh][d][t]
__device__ __align__(128) __nv_bfloat16 g_wgh[67108864], g_wgl[67108864];   // softmax w hi/lo
__device__ __align__(128) __nv_bfloat16 g_atth[4194304], g_attl[4194304];

// ---------------- helpers ----------------
union BF2 { __nv_bfloat16 b[2]; uint32_t u; };
union BF4 { __nv_bfloat16 b[4]; uint2 u; };

DI void split2(float v, __nv_bfloat16& h, __nv_bfloat16& l) {
    h = __float2bfloat16(v);
    l = __float2bfloat16(v - __bfloat162float(h));
}
DI uint32_t smem_u32(const void* p) {
    uint32_t a;
    asm("{ .reg .u64 t; cvta.to.shared.u64 t, %1; cvt.u32.u64 %0, t; }" : "=r"(a) : "l"(p));
    return a;
}
DI void ldsm4(uint32_t* r, uint32_t a) {
    asm volatile("ldmatrix.sync.aligned.m8n8.x4.shared.b16 {%0,%1,%2,%3}, [%4];"
        : "=r"(r[0]), "=r"(r[1]), "=r"(r[2]), "=r"(r[3]) : "r"(a));
}
DI void ldsm4t(uint32_t* r, uint32_t a) {
    asm volatile("ldmatrix.sync.aligned.m8n8.x4.trans.shared.b16 {%0,%1,%2,%3}, [%4];"
        : "=r"(r[0]), "=r"(r[1]), "=r"(r[2]), "=r"(r[3]) : "r"(a));
}
DI void mma16816(float* d, const uint32_t* a, const uint32_t* b) {
    asm volatile("mma.sync.aligned.m16n8k16.row.col.f32.bf16.bf16.f32 "
        "{%0,%1,%2,%3}, {%4,%5,%6,%7}, {%8,%9}, {%0,%1,%2,%3};"
        : "+f"(d[0]), "+f"(d[1]), "+f"(d[2]), "+f"(d[3])
        : "r"(a[0]), "r"(a[1]), "r"(a[2]), "r"(a[3]), "r"(b[0]), "r"(b[1]));
}

// bf16 hi/lo tile loader: ROWS x KC from gmem (row stride ldg) -> padded smem (stride KC+8)
template <int ROWS, int KC>
DI void load_pair(char* sH, char* sL, const __nv_bfloat16* Gh, const __nv_bfloat16* Gl, size_t ldg) {
    constexpr int SA = KC + 8;
#pragma unroll 4
    for (int i = threadIdx.x; i < ROWS * KC / 8; i += 256) {
        int r = i / (KC / 8), c = (i % (KC / 8)) * 8;
        int so = (r * SA + c) * 2;
        *(uint4*)(sH + so) = *(const uint4*)(Gh + (size_t)r * ldg + c);
        *(uint4*)(sL + so) = *(const uint4*)(Gl + (size_t)r * ldg + c);
    }
}
// fp32 tile loader with on-the-fly hi/lo split
template <int ROWS, int KC>
DI void load_split(char* sH, char* sL, const float* G, size_t ldg) {
    constexpr int SA = KC + 8;
#pragma unroll 4
    for (int i = threadIdx.x; i < ROWS * KC / 4; i += 256) {
        int r = i / (KC / 4), c = (i % (KC / 4)) * 4;
        float4 v = *(const float4*)(G + (size_t)r * ldg + c);
        BF4 Hh, Ll;
        split2(v.x, Hh.b[0], Ll.b[0]); split2(v.y, Hh.b[1], Ll.b[1]);
        split2(v.z, Hh.b[2], Ll.b[2]); split2(v.w, Hh.b[3], Ll.b[3]);
        int so = (r * SA + c) * 2;
        *(uint2*)(sH + so) = Hh.u;
        *(uint2*)(sL + so) = Ll.u;
    }
}

// one K-chunk of split-3 MMA. Warp grid: wm = wid/WN, wn = wid%WN.
// Warp tile: MT m16-tiles x NT n8-tiles. BT: B stored K-major (use ldmatrix.trans).
template <int WN, int MT, int NT, int SA, int SB, int KSTEPS, bool BT>
DI void mma_chunk(uint32_t aH, uint32_t aL, uint32_t bH, uint32_t bL, float (&acc)[MT][NT][4]) {
    int lane = threadIdx.x & 31, wid = threadIdx.x >> 5;
    int wm = wid / WN, wn = wid % WN;
#pragma unroll
    for (int kk = 0; kk < KSTEPS; kk++) {
        uint32_t ah[MT][4], al[MT][4], bh[NT][2], bl[NT][2];
#pragma unroll
        for (int mt = 0; mt < MT; mt++) {
            uint32_t off = (uint32_t)(((wm * MT * 16 + mt * 16 + (lane & 15)) * SA
                                       + kk * 16 + (lane >> 4) * 8) * 2);
            ldsm4(ah[mt], aH + off);
            ldsm4(al[mt], aL + off);
        }
#pragma unroll
        for (int nt = 0; nt < NT; nt += 2) {
            uint32_t off;
            if (BT)
                off = (uint32_t)(((kk * 16 + (lane & 15)) * SB
                                  + wn * NT * 8 + nt * 8 + (lane >> 4) * 8) * 2);
            else
                off = (uint32_t)(((wn * NT * 8 + nt * 8 + ((lane >> 4) << 3) + (lane & 7)) * SB
                                  + kk * 16 + (((lane >> 3) & 1) << 3)) * 2);
            uint32_t r[4];
            if (BT) ldsm4t(r, bH + off); else ldsm4(r, bH + off);
            bh[nt][0] = r[0]; bh[nt][1] = r[1]; bh[nt + 1][0] = r[2]; bh[nt + 1][1] = r[3];
            if (BT) ldsm4t(r, bL + off); else ldsm4(r, bL + off);
            bl[nt][0] = r[0]; bl[nt][1] = r[1]; bl[nt + 1][0] = r[2]; bl[nt + 1][1] = r[3];
        }
#pragma unroll
        for (int mt = 0; mt < MT; mt++)
#pragma unroll
            for (int nt = 0; nt < NT; nt++) {
                mma16816(acc[mt][nt], ah[mt], bh[nt]);
                mma16816(acc[mt][nt], ah[mt], bl[nt]);
                mma16816(acc[mt][nt], al[mt], bh[nt]);
            }
    }
}

// ---------------- conversion kernels ----------------
__global__ __launch_bounds__(256) void c0_wt(const float* Wq, const float* Wk,
                                             const float* Wv, const float* Wp) {
    __shared__ float smt[32][33];
    int mat = blockIdx.z;
    const float* W = mat == 0 ? Wq : mat == 1 ? Wk : mat == 2 ? Wv : Wp;
    int nblk = blockIdx.x * 32, kblk = blockIdx.y * 32;
    for (int i = threadIdx.x; i < 1024; i += 256) {
        int r = i >> 5, c = i & 31;
        smt[r][c] = W[(size_t)(kblk + r) * 1024 + nblk + c];
    }
    __syncthreads();
    for (int i = threadIdx.x; i < 1024; i += 256) {
        int n = i >> 5, k = i & 31;
        float v = smt[k][n];
        size_t o = (size_t)mat * 1048576 + (size_t)(nblk + n) * 1024 + kblk + k;
        split2(v, g_wth[o], g_wtl[o]);
    }
}
__global__ __launch_bounds__(256) void c1_x(const float* q, const float* k, const float* v) {
    int z = blockIdx.y;
    const float* X = z == 0 ? q : z == 1 ? k : v;
    size_t idx = ((size_t)blockIdx.x * 256 + threadIdx.x) * 4;
    float4 t = *(const float4*)&X[idx];
    BF4 Hh, Ll;
    split2(t.x, Hh.b[0], Ll.b[0]); split2(t.y, Hh.b[1], Ll.b[1]);
    split2(t.z, Hh.b[2], Ll.b[2]); split2(t.w, Hh.b[3], Ll.b[3]);
    *(uint2*)&g_xh[(size_t)z * 4194304 + idx] = Hh.u;
    *(uint2*)&g_xl[(size_t)z * 4194304 + idx] = Ll.u;
}
__global__ __launch_bounds__(256) void c2_vt() {
    __shared__ __nv_bfloat16 smh[64][65], sml[64][65];
    int sblk = blockIdx.x * 64, bh = blockIdx.y;
    size_t ibase = (size_t)bh * 65536;
    for (int i = threadIdx.x; i < 4096; i += 256) {
        int s = i >> 6, d = i & 63;
        smh[s][d] = g_vh[ibase + (size_t)(sblk + s) * 64 + d];
        sml[s][d] = g_vl[ibase + (size_t)(sblk + s) * 64 + d];
    }
    __syncthreads();
    for (int i = threadIdx.x; i < 4096; i += 256) {
        int d = i >> 6, s = i & 63;
        g_vth[ibase + (size_t)d * 1024 + sblk + s] = smh[s][d];
        g_vtl[ibase + (size_t)d * 1024 + sblk + s] = sml[s][d];
    }
}

// ---------------- G1: q/k/v = X @ W^T + b ----------------
__global__ __launch_bounds__(256) void g1_qkv(const float* bq, const float* bk, const float* bv) {
    extern __shared__ char sm[];
    constexpr int AB = 128 * 72 * 2;
    char *aH = sm, *aL = sm + AB, *bH = sm + 2 * AB, *bL = sm + 3 * AB;
    uint32_t aHu = smem_u32(aH), aLu = smem_u32(aL), bHu = smem_u32(bH), bLu = smem_u32(bL);
    int z = blockIdx.z, m0 = blockIdx.y * 128, n0 = blockIdx.x * 128;
    const __nv_bfloat16* Ah = g_xh + (size_t)z * 4194304 + (size_t)m0 * 1024;
    const __nv_bfloat16* Al = g_xl + (size_t)z * 4194304 + (size_t)m0 * 1024;
    const __nv_bfloat16* Bh = g_wth + (size_t)z * 1048576 + (size_t)n0 * 1024;
    const __nv_bfloat16* Bl = g_wtl + (size_t)z * 1048576 + (size_t)n0 * 1024;
    float acc[4][4][4] = {};
    for (int c = 0; c < 16; c++) {
        load_pair<128, 64>(aH, aL, Ah + c * 64, Al + c * 64, 1024);
        load_pair<128, 64>(bH, bL, Bh + c * 64, Bl + c * 64, 1024);
        __syncthreads();
        mma_chunk<4, 4, 4, 72, 72, 4, false>(aHu, aLu, bHu, bLu, acc);
        __syncthreads();
    }
    const float* bias = z == 0 ? bq : z == 1 ? bk : bv;
    __nv_bfloat16* dh = z == 0 ? g_qh : z == 1 ? g_kh : g_vh;
    __nv_bfloat16* dl = z == 0 ? g_ql : z == 1 ? g_kl : g_vl;
    float sc = z == 0 ? 0.125f : 1.f;
    int lane = threadIdx.x & 31, wid = threadIdx.x >> 5, wm = wid / 4, wn = wid % 4;
#pragma unroll
    for (int mt = 0; mt < 4; mt++)
#pragma unroll
        for (int nt = 0; nt < 4; nt++)
#pragma unroll
            for (int hf = 0; hf < 2; hf++) {
                int m = m0 + wm * 64 + mt * 16 + (lane >> 2) + hf * 8;
                int n = n0 + wn * 32 + nt * 8 + (lane & 3) * 2;
                float v0 = (acc[mt][nt][hf * 2] + bias[n]) * sc;
                float v1 = (acc[mt][nt][hf * 2 + 1] + bias[n + 1]) * sc;
                BF2 Hh, Ll;
                split2(v0, Hh.b[0], Ll.b[0]); split2(v1, Hh.b[1], Ll.b[1]);
                int b = m >> 10, s = m & 1023, h = n >> 6, d = n & 63;
                size_t o = ((size_t)((b << 4) + h) * 1024 + s) * 64 + d;
                *(uint32_t*)&dh[o] = Hh.u;
                *(uint32_t*)&dl[o] = Ll.u;
            }
}

// ---------------- G2: content logits + attn_bias -> g_w ----------------
__global__ __launch_bounds__(256) void g2_logits(const float* __restrict__ attn_bias) {
    extern __shared__ char sm[];
    constexpr int AB = 128 * 72 * 2;
    char *aH = sm, *aL = sm + AB, *bH = sm + 2 * AB, *bL = sm + 3 * AB;
    uint32_t aHu = smem_u32(aH), aLu = smem_u32(aL), bHu = smem_u32(bH), bLu = smem_u32(bL);
    int bh = blockIdx.z, m0 = blockIdx.y * 128, n0 = blockIdx.x * 128;
    float acc[4][4][4] = {};
    load_pair<128, 64>(aH, aL, g_qh + (size_t)bh * 65536 + (size_t)m0 * 64,
                       g_ql + (size_t)bh * 65536 + (size_t)m0 * 64, 64);
    load_pair<128, 64>(bH, bL, g_kh + (size_t)bh * 65536 + (size_t)n0 * 64,
                       g_kl + (size_t)bh * 65536 + (size_t)n0 * 64, 64);
    __syncthreads();
    mma_chunk<4, 4, 4, 72, 72, 4, false>(aHu, aLu, bHu, bLu, acc);
    int lane = threadIdx.x & 31, wid = threadIdx.x >> 5, wm = wid / 4, wn = wid % 4;
#pragma unroll
    for (int mt = 0; mt < 4; mt++)
#pragma unroll
        for (int nt = 0; nt < 4; nt++)
#pragma unroll
            for (int hf = 0; hf < 2; hf++) {
                int s = m0 + wm * 64 + mt * 16 + (lane >> 2) + hf * 8;
                int t = n0 + wn * 32 + nt * 8 + (lane & 3) * 2;
                size_t idx = (size_t)bh * 1048576 + (size_t)s * 1024 + t;
                float2 bb = *(const float2*)&attn_bias[idx];
                float2 o;
                o.x = acc[mt][nt][hf * 2] + bb.x;
                o.y = acc[mt][nt][hf * 2 + 1] + bb.y;
                *(float2*)&g_w[idx] = o;
            }
}

// ---------------- K3: edge-key logits, g_w += q_s @ EK_s^T ----------------
__global__ __launch_bounds__(256) void k3_edge(const float* __restrict__ ek) {
    extern __shared__ char sm[];
    char *aH = sm, *aL = sm + 9216, *bH = sm + 18432, *bL = sm + 36864;
    uint32_t aHu = smem_u32(aH), aLu = smem_u32(aL), bHu = smem_u32(bH), bLu = smem_u32(bL);
    int s = blockIdx.y, t0 = blockIdx.x * 128;
    float acc[2][4][4] = {};
    load_pair<64, 64>(aH, aL, g_qh + (size_t)s * 64, g_ql + (size_t)s * 64, 65536);
    load_split<128, 64>(bH, bL, ek + (size_t)s * 65536 + (size_t)t0 * 64, 64);
    __syncthreads();
    mma_chunk<4, 2, 4, 72, 72, 4, false>(aHu, aLu, bHu, bLu, acc);
    int lane = threadIdx.x & 31, wid = threadIdx.x >> 5, wm = wid / 4, wn = wid % 4;
#pragma unroll
    for (int mt = 0; mt < 2; mt++)
#pragma unroll
        for (int nt = 0; nt < 4; nt++)
#pragma unroll
            for (int hf = 0; hf < 2; hf++) {
                int bh = wm * 32 + mt * 16 + (lane >> 2) + hf * 8;
                int t = t0 + wn * 32 + nt * 8 + (lane & 3) * 2;
                size_t idx = (size_t)bh * 1048576 + (size_t)s * 1024 + t;
                float2 cur = *(float2*)&g_w[idx];
                cur.x += acc[mt][nt][hf * 2];
                cur.y += acc[mt][nt][hf * 2 + 1];
                *(float2*)&g_w[idx] = cur;
            }
}

// ---------------- K4: softmax, emit bf16 hi/lo weights ----------------
__global__ __launch_bounds__(256) void k4_softmax() {
    __shared__ float red[8];
    size_t row = blockIdx.x;
    float* p = g_w + row * 1024;
    int tid = threadIdx.x;
    float4 v = *(float4*)&p[tid * 4];
    float mx = fmaxf(fmaxf(v.x, v.y), fmaxf(v.z, v.w));
#pragma unroll
    for (int o = 16; o; o >>= 1) mx = fmaxf(mx, __shfl_xor_sync(~0u, mx, o));
    if ((tid & 31) == 0) red[tid >> 5] = mx;
    __syncthreads();
    float bm = red[0];
#pragma unroll
    for (int i = 1; i < 8; i++) bm = fmaxf(bm, red[i]);
    v.x = __expf(v.x - bm); v.y = __expf(v.y - bm);
    v.z = __expf(v.z - bm); v.w = __expf(v.w - bm);
    float smv = v.x + v.y + v.z + v.w;
#pragma unroll
    for (int o = 16; o; o >>= 1) smv += __shfl_xor_sync(~0u, smv, o);
    __syncthreads();
    if ((tid & 31) == 0) red[tid >> 5] = smv;
    __syncthreads();
    float tot = 0.f;
#pragma unroll
    for (int i = 0; i < 8; i++) tot += red[i];
    float inv = 1.0f / tot;
    v.x *= inv; v.y *= inv; v.z *= inv; v.w *= inv;
    BF4 Hh, Ll;
    split2(v.x, Hh.b[0], Ll.b[0]); split2(v.y, Hh.b[1], Ll.b[1]);
    split2(v.z, Hh.b[2], Ll.b[2]); split2(v.w, Hh.b[3], Ll.b[3]);
    *(uint2*)&g_wgh[row * 1024 + tid * 4] = Hh.u;
    *(uint2*)&g_wgl[row * 1024 + tid * 4] = Ll.u;
}

// ---------------- G5: att = W @ V (content) ----------------
__global__ __launch_bounds__(256) void g5_pv() {
    extern __shared__ char sm[];
    char *aH = sm, *aL = sm + 18432, *bH = sm + 36864, *bL = sm + 46080;
    uint32_t aHu = smem_u32(aH), aLu = smem_u32(aL), bHu = smem_u32(bH), bLu = smem_u32(bL);
    int bh = blockIdx.y, m0 = blockIdx.x * 128;
    const __nv_bfloat16* Ah = g_wgh + (size_t)bh * 1048576 + (size_t)m0 * 1024;
    const __nv_bfloat16* Al = g_wgl + (size_t)bh * 1048576 + (size_t)m0 * 1024;
    const __nv_bfloat16* Bh = g_vth + (size_t)bh * 65536;
    const __nv_bfloat16* Bl = g_vtl + (size_t)bh * 65536;
    float acc[2][4][4] = {};
    for (int c = 0; c < 16; c++) {
        load_pair<128, 64>(aH, aL, Ah + c * 64, Al + c * 64, 1024);
        load_pair<64, 64>(bH, bL, Bh + c * 64, Bl + c * 64, 1024);
        __syncthreads();
        mma_chunk<2, 2, 4, 72, 72, 4, false>(aHu, aLu, bHu, bLu, acc);
        __syncthreads();
    }
    int lane = threadIdx.x & 31, wid = threadIdx.x >> 5, wm = wid / 2, wn = wid % 2;
    int b = bh >> 4, h = bh & 15;
#pragma unroll
    for (int mt = 0; mt < 2; mt++)
#pragma unroll
        for (int nt = 0; nt < 4; nt++)
#pragma unroll
            for (int hf = 0; hf < 2; hf++) {
                int s = m0 + wm * 32 + mt * 16 + (lane >> 2) + hf * 8;
                int d = wn * 32 + nt * 8 + (lane & 3) * 2;
                size_t o = ((size_t)(b * 1024 + s)) * 1024 + h * 64 + d;
                float2 vv;
                vv.x = acc[mt][nt][hf * 2];
                vv.y = acc[mt][nt][hf * 2 + 1];
                *(float2*)&g_att[o] = vv;
            }
}

// ---------------- K6: att += W @ EV_s, emit att bf16 hi/lo ----------------
__global__ __launch_bounds__(256) void k6_ev(const float* __restrict__ ev) {
    extern __shared__ char sm[];
    char *aH = sm, *aL = sm + 17408, *bH = sm + 34816, *bL = sm + 53248;
    uint32_t aHu = smem_u32(aH), aLu = smem_u32(aL), bHu = smem_u32(bH), bLu = smem_u32(bL);
    int s = blockIdx.x;
    float acc[1][4][4] = {};
    for (int c = 0; c < 8; c++) {
        load_pair<64, 128>(aH, aL, g_wgh + (size_t)s * 1024 + c * 128,
                           g_wgl + (size_t)s * 1024 + c * 128, 1048576);
        load_split<128, 64>(bH, bL, ev + (size_t)s * 65536 + (size_t)c * 128 * 64, 64);
        __syncthreads();
        mma_chunk<2, 1, 4, 136, 72, 8, true>(aHu, aLu, bHu, bLu, acc);
        __syncthreads();
    }
    int lane = threadIdx.x & 31, wid = threadIdx.x >> 5, wm = wid / 2, wn = wid % 2;
#pragma unroll
    for (int nt = 0; nt < 4; nt++)
#pragma unroll
        for (int hf = 0; hf < 2; hf++) {
            int bh = wm * 16 + (lane >> 2) + hf * 8;
            int d = wn * 32 + nt * 8 + (lane & 3) * 2;
            int b = bh >> 4, h = bh & 15;
            size_t o = ((size_t)(b * 1024 + s)) * 1024 + h * 64 + d;
            float2 cur = *(float2*)&g_att[o];
            float v0 = cur.x + acc[0][nt][hf * 2];
            float v1 = cur.y + acc[0][nt][hf * 2 + 1];
            BF2 Hh, Ll;
            split2(v0, Hh.b[0], Ll.b[0]); split2(v1, Hh.b[1], Ll.b[1]);
            *(uint32_t*)&g_atth[o] = Hh.u;
            *(uint32_t*)&g_attl[o] = Ll.u;
        }
}

// ---------------- G7: out = att @ Wp^T + bp ----------------
__global__ __launch_bounds__(256) void g7_out(const float* __restrict__ bp, float* __restrict__ out) {
    extern __shared__ char sm[];
    constexpr int AB = 128 * 72 * 2;
    char *aH = sm, *aL = sm + AB, *bH = sm + 2 * AB, *bL = sm + 3 * AB;
    uint32_t aHu = smem_u32(aH), aLu = smem_u32(aL), bHu = smem_u32(bH), bLu = smem_u32(bL);
    int m0 = blockIdx.y * 128, n0 = blockIdx.x * 128;
    const __nv_bfloat16* Bh = g_wth + (size_t)3 * 1048576 + (size_t)n0 * 1024;
    const __nv_bfloat16* Bl = g_wtl + (size_t)3 * 1048576 + (size_t)n0 * 1024;
    float acc[4][4][4] = {};
    for (int c = 0; c < 16; c++) {
        load_pair<128, 64>(aH, aL, g_atth + (size_t)m0 * 1024 + c * 64,
                           g_attl + (size_t)m0 * 1024 + c * 64, 1024);
        load_pair<128, 64>(bH, bL, Bh + c * 64, Bl + c * 64, 1024);
        __syncthreads();
        mma_chunk<4, 4, 4, 72, 72, 4, false>(aHu, aLu, bHu, bLu, acc);
        __syncthreads();
    }
    int lane = threadIdx.x & 31, wid = threadIdx.x >> 5, wm = wid / 4, wn = wid % 4;
#pragma unroll
    for (int mt = 0; mt < 4; mt++)
#pragma unroll
        for (int nt = 0; nt < 4; nt++)
#pragma unroll
            for (int hf = 0; hf < 2; hf++) {
                int m = m0 + wm * 64 + mt * 16 + (lane >> 2) + hf * 8;
                int n = n0 + wn * 32 + nt * 8 + (lane & 3) * 2;
                float2 bb = *(const float2*)&bp[n];
                float2 vv;
                vv.x = acc[mt][nt][hf * 2] + bb.x;
                vv.y = acc[mt][nt][hf * 2 + 1] + bb.y;
                *(float2*)&out[(size_t)m * 1024 + n] = vv;
            }
}

// ---------------- launch ----------------
extern "C" void kernel_launch(void* const* d_in, const int* in_sizes, int n_in,
                              void* d_out, int out_size) {
    const float* queries     = (const float*)d_in[0];
    const float* keys        = (const float*)d_in[1];
    const float* values      = (const float*)d_in[2];
    const float* edges_key   = (const float*)d_in[3];
    const float* edges_value = (const float*)d_in[4];
    const float* attn_bias   = (const float*)d_in[5];
    const float* Wq = (const float*)d_in[6];  const float* bq = (const float*)d_in[7];
    const float* Wk = (const float*)d_in[8];  const float* bk = (const float*)d_in[9];
    const float* Wv = (const float*)d_in[10]; const float* bv = (const float*)d_in[11];
    const float* Wp = (const float*)d_in[12]; const float* bp = (const float*)d_in[13];

    cudaFuncSetAttribute(g1_qkv,    cudaFuncAttributeMaxDynamicSharedMemorySize, 73728);
    cudaFuncSetAttribute(g2_logits, cudaFuncAttributeMaxDynamicSharedMemorySize, 73728);
    cudaFuncSetAttribute(k3_edge,   cudaFuncAttributeMaxDynamicSharedMemorySize, 55296);
    cudaFuncSetAttribute(g5_pv,     cudaFuncAttributeMaxDynamicSharedMemorySize, 55296);
    cudaFuncSetAttribute(k6_ev,     cudaFuncAttributeMaxDynamicSharedMemorySize, 71680);
    cudaFuncSetAttribute(g7_out,    cudaFuncAttributeMaxDynamicSharedMemorySize, 73728);

    c0_wt<<<dim3(32, 32, 4), 256>>>(Wq, Wk, Wv, Wp);
    c1_x<<<dim3(4096, 3), 256>>>(queries, keys, values);
    g1_qkv<<<dim3(8, 32, 3), 256, 73728>>>(bq, bk, bv);
    c2_vt<<<dim3(16, 64), 256>>>();
    g2_logits<<<dim3(8, 8, 64), 256, 73728>>>(attn_bias);
    k3_edge<<<dim3(8, 1024), 256, 55296>>>(edges_key);
    k4_softmax<<<65536, 256>>>();
    g5_pv<<<dim3(8, 64), 256, 55296>>>();
    k6_ev<<<1024, 256, 71680>>>(edges_value);
    g7_out<<<dim3(8, 32), 256, 73728>>>(bp, (float*)d_out);
}

// round 5
// speedup vs baseline: 1.8809x; 1.0511x over previous
#include <cuda_runtime.h>
#include <cuda_bf16.h>
#include <cuda_fp16.h>
#include <cstdint>

// B=4, S=1024, E=1024, H=16, D=64, BH=64.
// mma.sync m16n8k16 (compute_103-safe). bf16 2-term split for projections/logits,
// single-fp16 softmax weights + fp16-split V/EV for the PV/EV GEMMs.

#define DI __device__ __forceinline__

// ---------------- device scratch ----------------
__device__ __align__(128) float g_w[67108864];                 // fp32 logits [bh][s][t]
__device__ __align__(128) __half g_wf[67108864];               // fp16 softmax weights
__device__ __align__(128) float g_att[4194304];                // fp32 att [b*s][h*d]
__device__ __align__(128) __nv_bfloat16 g_xh[3*4194304], g_xl[3*4194304];   // X hi/lo
__device__ __align__(128) __nv_bfloat16 g_wth[4*1048576], g_wtl[4*1048576]; // W^T hi/lo
__device__ __align__(128) __nv_bfloat16 g_qh[4194304], g_ql[4194304];       // [bh][s][d]
__device__ __align__(128) __nv_bfloat16 g_kh[4194304], g_kl[4194304];       // [bh][t][d]
__device__ __align__(128) __half g_vh[4194304], g_vl[4194304];              // [bh][s][d] fp16
__device__ __align__(128) __half g_vth[4194304], g_vtl[4194304];            // [bh][d][t] fp16
__device__ __align__(128) __nv_bfloat16 g_atth[4194304], g_attl[4194304];

// ---------------- helpers ----------------
union BF2 { __nv_bfloat16 b[2]; uint32_t u; };
union BF4 { __nv_bfloat16 b[4]; uint2 u; };
union HF4 { __half b[4]; uint2 u; };

DI void split2(float v, __nv_bfloat16& h, __nv_bfloat16& l) {
    h = __float2bfloat16(v);
    l = __float2bfloat16(v - __bfloat162float(h));
}
DI void split2h(float v, __half& h, __half& l) {
    h = __float2half_rn(v);
    l = __float2half_rn(v - __half2float(h));
}
DI uint32_t smem_u32(const void* p) {
    uint32_t a;
    asm("{ .reg .u64 t; cvta.to.shared.u64 t, %1; cvt.u32.u64 %0, t; }" : "=r"(a) : "l"(p));
    return a;
}
DI void ldsm4(uint32_t* r, uint32_t a) {
    asm volatile("ldmatrix.sync.aligned.m8n8.x4.shared.b16 {%0,%1,%2,%3}, [%4];"
        : "=r"(r[0]), "=r"(r[1]), "=r"(r[2]), "=r"(r[3]) : "r"(a));
}
DI void ldsm4t(uint32_t* r, uint32_t a) {
    asm volatile("ldmatrix.sync.aligned.m8n8.x4.trans.shared.b16 {%0,%1,%2,%3}, [%4];"
        : "=r"(r[0]), "=r"(r[1]), "=r"(r[2]), "=r"(r[3]) : "r"(a));
}
DI void mma16816(float* d, const uint32_t* a, const uint32_t* b) {
    asm volatile("mma.sync.aligned.m16n8k16.row.col.f32.bf16.bf16.f32 "
        "{%0,%1,%2,%3}, {%4,%5,%6,%7}, {%8,%9}, {%0,%1,%2,%3};"
        : "+f"(d[0]), "+f"(d[1]), "+f"(d[2]), "+f"(d[3])
        : "r"(a[0]), "r"(a[1]), "r"(a[2]), "r"(a[3]), "r"(b[0]), "r"(b[1]));
}
DI void mma16816h(float* d, const uint32_t* a, const uint32_t* b) {
    asm volatile("mma.sync.aligned.m16n8k16.row.col.f32.f16.f16.f32 "
        "{%0,%1,%2,%3}, {%4,%5,%6,%7}, {%8,%9}, {%0,%1,%2,%3};"
        : "+f"(d[0]), "+f"(d[1]), "+f"(d[2]), "+f"(d[3])
        : "r"(a[0]), "r"(a[1]), "r"(a[2]), "r"(a[3]), "r"(b[0]), "r"(b[1]));
}

// hi/lo tile loader (any 16-bit type): ROWS x KC -> padded smem (stride KC+8)
template <int ROWS, int KC, typename T>
DI void load_pair(char* sH, char* sL, const T* Gh, const T* Gl, size_t ldg) {
    constexpr int SA = KC + 8;
#pragma unroll 4
    for (int i = threadIdx.x; i < ROWS * KC / 8; i += 256) {
        int r = i / (KC / 8), c = (i % (KC / 8)) * 8;
        int so = (r * SA + c) * 2;
        *(uint4*)(sH + so) = *(const uint4*)(Gh + (size_t)r * ldg + c);
        *(uint4*)(sL + so) = *(const uint4*)(Gl + (size_t)r * ldg + c);
    }
}
// single 16-bit tile loader
template <int ROWS, int KC, typename T>
DI void load_one(char* s, const T* G, size_t ldg) {
    constexpr int SA = KC + 8;
#pragma unroll 4
    for (int i = threadIdx.x; i < ROWS * KC / 8; i += 256) {
        int r = i / (KC / 8), c = (i % (KC / 8)) * 8;
        *(uint4*)(s + (r * SA + c) * 2) = *(const uint4*)(G + (size_t)r * ldg + c);
    }
}
// fp32 tile loader with on-the-fly bf16 hi/lo split
template <int ROWS, int KC>
DI void load_split(char* sH, char* sL, const float* G, size_t ldg) {
    constexpr int SA = KC + 8;
#pragma unroll 4
    for (int i = threadIdx.x; i < ROWS * KC / 4; i += 256) {
        int r = i / (KC / 4), c = (i % (KC / 4)) * 4;
        float4 v = *(const float4*)(G + (size_t)r * ldg + c);
        BF4 Hh, Ll;
        split2(v.x, Hh.b[0], Ll.b[0]); split2(v.y, Hh.b[1], Ll.b[1]);
        split2(v.z, Hh.b[2], Ll.b[2]); split2(v.w, Hh.b[3], Ll.b[3]);
        int so = (r * SA + c) * 2;
        *(uint2*)(sH + so) = Hh.u;
        *(uint2*)(sL + so) = Ll.u;
    }
}
// fp32 tile loader with on-the-fly fp16 hi/lo split
template <int ROWS, int KC>
DI void load_split_h(char* sH, char* sL, const float* G, size_t ldg) {
    constexpr int SA = KC + 8;
#pragma unroll 4
    for (int i = threadIdx.x; i < ROWS * KC / 4; i += 256) {
        int r = i / (KC / 4), c = (i % (KC / 4)) * 4;
        float4 v = *(const float4*)(G + (size_t)r * ldg + c);
        HF4 Hh, Ll;
        split2h(v.x, Hh.b[0], Ll.b[0]); split2h(v.y, Hh.b[1], Ll.b[1]);
        split2h(v.z, Hh.b[2], Ll.b[2]); split2h(v.w, Hh.b[3], Ll.b[3]);
        int so = (r * SA + c) * 2;
        *(uint2*)(sH + so) = Hh.u;
        *(uint2*)(sL + so) = Ll.u;
    }
}

// bf16 split-3 MMA chunk
template <int WN, int MT, int NT, int SA, int SB, int KSTEPS, bool BT>
DI void mma_chunk(uint32_t aH, uint32_t aL, uint32_t bH, uint32_t bL, float (&acc)[MT][NT][4]) {
    int lane = threadIdx.x & 31, wid = threadIdx.x >> 5;
    int wm = wid / WN, wn = wid % WN;
#pragma unroll
    for (int kk = 0; kk < KSTEPS; kk++) {
        uint32_t ah[MT][4], al[MT][4], bh[NT][2], bl[NT][2];
#pragma unroll
        for (int mt = 0; mt < MT; mt++) {
            uint32_t off = (uint32_t)(((wm * MT * 16 + mt * 16 + (lane & 15)) * SA
                                       + kk * 16 + (lane >> 4) * 8) * 2);
            ldsm4(ah[mt], aH + off);
            ldsm4(al[mt], aL + off);
        }
#pragma unroll
        for (int nt = 0; nt < NT; nt += 2) {
            uint32_t off;
            if (BT)
                off = (uint32_t)(((kk * 16 + (lane & 15)) * SB
                                  + wn * NT * 8 + nt * 8 + (lane >> 4) * 8) * 2);
            else
                off = (uint32_t)(((wn * NT * 8 + nt * 8 + ((lane >> 4) << 3) + (lane & 7)) * SB
                                  + kk * 16 + (((lane >> 3) & 1) << 3)) * 2);
            uint32_t r[4];
            if (BT) ldsm4t(r, bH + off); else ldsm4(r, bH + off);
            bh[nt][0] = r[0]; bh[nt][1] = r[1]; bh[nt + 1][0] = r[2]; bh[nt + 1][1] = r[3];
            if (BT) ldsm4t(r, bL + off); else ldsm4(r, bL + off);
            bl[nt][0] = r[0]; bl[nt][1] = r[1]; bl[nt + 1][0] = r[2]; bl[nt + 1][1] = r[3];
        }
#pragma unroll
        for (int mt = 0; mt < MT; mt++)
#pragma unroll
            for (int nt = 0; nt < NT; nt++) {
                mma16816(acc[mt][nt], ah[mt], bh[nt]);
                mma16816(acc[mt][nt], ah[mt], bl[nt]);
                mma16816(acc[mt][nt], al[mt], bh[nt]);
            }
    }
}

// fp16 chunk: single A, split B, 2 products
template <int WN, int MT, int NT, int SA, int SB, int KSTEPS, bool BT>
DI void mma_chunk_h(uint32_t aF, uint32_t bH, uint32_t bL, float (&acc)[MT][NT][4]) {
    int lane = threadIdx.x & 31, wid = threadIdx.x >> 5;
    int wm = wid / WN, wn = wid % WN;
#pragma unroll
    for (int kk = 0; kk < KSTEPS; kk++) {
        uint32_t af[MT][4], bh[NT][2], bl[NT][2];
#pragma unroll
        for (int mt = 0; mt < MT; mt++) {
            uint32_t off = (uint32_t)(((wm * MT * 16 + mt * 16 + (lane & 15)) * SA
                                       + kk * 16 + (lane >> 4) * 8) * 2);
            ldsm4(af[mt], aF + off);
        }
#pragma unroll
        for (int nt = 0; nt < NT; nt += 2) {
            uint32_t off;
            if (BT)
                off = (uint32_t)(((kk * 16 + (lane & 15)) * SB
                                  + wn * NT * 8 + nt * 8 + (lane >> 4) * 8) * 2);
            else
                off = (uint32_t)(((wn * NT * 8 + nt * 8 + ((lane >> 4) << 3) + (lane & 7)) * SB
                                  + kk * 16 + (((lane >> 3) & 1) << 3)) * 2);
            uint32_t r[4];
            if (BT) ldsm4t(r, bH + off); else ldsm4(r, bH + off);
            bh[nt][0] = r[0]; bh[nt][1] = r[1]; bh[nt + 1][0] = r[2]; bh[nt + 1][1] = r[3];
            if (BT) ldsm4t(r, bL + off); else ldsm4(r, bL + off);
            bl[nt][0] = r[0]; bl[nt][1] = r[1]; bl[nt + 1][0] = r[2]; bl[nt + 1][1] = r[3];
        }
#pragma unroll
        for (int mt = 0; mt < MT; mt++)
#pragma unroll
            for (int nt = 0; nt < NT; nt++) {
                mma16816h(acc[mt][nt], af[mt], bh[nt]);
                mma16816h(acc[mt][nt], af[mt], bl[nt]);
            }
    }
}

// ---------------- conversion kernels ----------------
__global__ __launch_bounds__(256) void c0_wt(const float* Wq, const float* Wk,
                                             const float* Wv, const float* Wp) {
    __shared__ float smt[32][33];
    int mat = blockIdx.z;
    const float* W = mat == 0 ? Wq : mat == 1 ? Wk : mat == 2 ? Wv : Wp;
    int nblk = blockIdx.x * 32, kblk = blockIdx.y * 32;
    for (int i = threadIdx.x; i < 1024; i += 256) {
        int r = i >> 5, c = i & 31;
        smt[r][c] = W[(size_t)(kblk + r) * 1024 + nblk + c];
    }
    __syncthreads();
    for (int i = threadIdx.x; i < 1024; i += 256) {
        int n = i >> 5, k = i & 31;
        float v = smt[k][n];
        size_t o = (size_t)mat * 1048576 + (size_t)(nblk + n) * 1024 + kblk + k;
        split2(v, g_wth[o], g_wtl[o]);
    }
}
__global__ __launch_bounds__(256) void c1_x(const float* q, const float* k, const float* v) {
    int z = blockIdx.y;
    const float* X = z == 0 ? q : z == 1 ? k : v;
    size_t idx = ((size_t)blockIdx.x * 256 + threadIdx.x) * 4;
    float4 t = *(const float4*)&X[idx];
    BF4 Hh, Ll;
    split2(t.x, Hh.b[0], Ll.b[0]); split2(t.y, Hh.b[1], Ll.b[1]);
    split2(t.z, Hh.b[2], Ll.b[2]); split2(t.w, Hh.b[3], Ll.b[3]);
    *(uint2*)&g_xh[(size_t)z * 4194304 + idx] = Hh.u;
    *(uint2*)&g_xl[(size_t)z * 4194304 + idx] = Ll.u;
}
__global__ __launch_bounds__(256) void c2_vt() {
    __shared__ __half smh[64][65], sml[64][65];
    int sblk = blockIdx.x * 64, bh = blockIdx.y;
    size_t ibase = (size_t)bh * 65536;
    for (int i = threadIdx.x; i < 4096; i += 256) {
        int s = i >> 6, d = i & 63;
        smh[s][d] = g_vh[ibase + (size_t)(sblk + s) * 64 + d];
        sml[s][d] = g_vl[ibase + (size_t)(sblk + s) * 64 + d];
    }
    __syncthreads();
    for (int i = threadIdx.x; i < 4096; i += 256) {
        int d = i >> 6, s = i & 63;
        g_vth[ibase + (size_t)d * 1024 + sblk + s] = smh[s][d];
        g_vtl[ibase + (size_t)d * 1024 + sblk + s] = sml[s][d];
    }
}

// ---------------- G1: q/k/v = X @ W^T + b ----------------
__global__ __launch_bounds__(256) void g1_qkv(const float* bq, const float* bk, const float* bv) {
    extern __shared__ char sm[];
    constexpr int AB = 128 * 72 * 2;
    char *aH = sm, *aL = sm + AB, *bH = sm + 2 * AB, *bL = sm + 3 * AB;
    uint32_t aHu = smem_u32(aH), aLu = smem_u32(aL), bHu = smem_u32(bH), bLu = smem_u32(bL);
    int z = blockIdx.z, m0 = blockIdx.y * 128, n0 = blockIdx.x * 128;
    const __nv_bfloat16* Ah = g_xh + (size_t)z * 4194304 + (size_t)m0 * 1024;
    const __nv_bfloat16* Al = g_xl + (size_t)z * 4194304 + (size_t)m0 * 1024;
    const __nv_bfloat16* Bh = g_wth + (size_t)z * 1048576 + (size_t)n0 * 1024;
    const __nv_bfloat16* Bl = g_wtl + (size_t)z * 1048576 + (size_t)n0 * 1024;
    float acc[4][4][4] = {};
    for (int c = 0; c < 16; c++) {
        load_pair<128, 64>(aH, aL, Ah + c * 64, Al + c * 64, 1024);
        load_pair<128, 64>(bH, bL, Bh + c * 64, Bl + c * 64, 1024);
        __syncthreads();
        mma_chunk<4, 4, 4, 72, 72, 4, false>(aHu, aLu, bHu, bLu, acc);
        __syncthreads();
    }
    const float* bias = z == 0 ? bq : z == 1 ? bk : bv;
    float sc = z == 0 ? 0.125f : 1.f;
    int lane = threadIdx.x & 31, wid = threadIdx.x >> 5, wm = wid / 4, wn = wid % 4;
#pragma unroll
    for (int mt = 0; mt < 4; mt++)
#pragma unroll
        for (int nt = 0; nt < 4; nt++)
#pragma unroll
            for (int hf = 0; hf < 2; hf++) {
                int m = m0 + wm * 64 + mt * 16 + (lane >> 2) + hf * 8;
                int n = n0 + wn * 32 + nt * 8 + (lane & 3) * 2;
                float v0 = (acc[mt][nt][hf * 2] + bias[n]) * sc;
                float v1 = (acc[mt][nt][hf * 2 + 1] + bias[n + 1]) * sc;
                int b = m >> 10, s = m & 1023, h = n >> 6, d = n & 63;
                size_t o = ((size_t)((b << 4) + h) * 1024 + s) * 64 + d;
                if (z == 2) {
                    union { __half b[2]; uint32_t u; } Hh, Ll;
                    split2h(v0, Hh.b[0], Ll.b[0]); split2h(v1, Hh.b[1], Ll.b[1]);
                    *(uint32_t*)&g_vh[o] = Hh.u;
                    *(uint32_t*)&g_vl[o] = Ll.u;
                } else {
                    BF2 Hh, Ll;
                    split2(v0, Hh.b[0], Ll.b[0]); split2(v1, Hh.b[1], Ll.b[1]);
                    __nv_bfloat16* dh = z == 0 ? g_qh : g_kh;
                    __nv_bfloat16* dl = z == 0 ? g_ql : g_kl;
                    *(uint32_t*)&dh[o] = Hh.u;
                    *(uint32_t*)&dl[o] = Ll.u;
                }
            }
}

// ---------------- K3: g_w = edge-key logits + attn_bias ----------------
__global__ __launch_bounds__(256) void k3_edge(const float* __restrict__ ek,
                                               const float* __restrict__ bias) {
    extern __shared__ char sm[];
    char *aH = sm, *aL = sm + 9216, *bH = sm + 18432, *bL = sm + 36864;
    uint32_t aHu = smem_u32(aH), aLu = smem_u32(aL), bHu = smem_u32(bH), bLu = smem_u32(bL);
    int s = blockIdx.y, t0 = blockIdx.x * 128;
    float acc[2][4][4] = {};
    load_pair<64, 64>(aH, aL, g_qh + (size_t)s * 64, g_ql + (size_t)s * 64, 65536);
    load_split<128, 64>(bH, bL, ek + (size_t)s * 65536 + (size_t)t0 * 64, 64);
    __syncthreads();
    mma_chunk<4, 2, 4, 72, 72, 4, false>(aHu, aLu, bHu, bLu, acc);
    int lane = threadIdx.x & 31, wid = threadIdx.x >> 5, wm = wid / 4, wn = wid % 4;
#pragma unroll
    for (int mt = 0; mt < 2; mt++)
#pragma unroll
        for (int nt = 0; nt < 4; nt++)
#pragma unroll
            for (int hf = 0; hf < 2; hf++) {
                int bh = wm * 32 + mt * 16 + (lane >> 2) + hf * 8;
                int t = t0 + wn * 32 + nt * 8 + (lane & 3) * 2;
                size_t idx = (size_t)bh * 1048576 + (size_t)s * 1024 + t;
                float2 bb = *(const float2*)&bias[idx];
                float2 o;
                o.x = acc[mt][nt][hf * 2] + bb.x;
                o.y = acc[mt][nt][hf * 2 + 1] + bb.y;
                *(float2*)&g_w[idx] = o;
            }
}

// ---------------- G2S: content logits + g_w + softmax -> fp16 w ----------------
// block: (s-tile of 32, bh). Warps split over t (8 x 16). Full row in registers.
__global__ __launch_bounds__(256) void g2s() {
    extern __shared__ char sm[];
    __shared__ float red[8][32];
    __shared__ float redc[32];
    char *qH = sm, *qL = sm + 4608, *kH = sm + 9216, *kL = sm + 27648;
    uint32_t qHu = smem_u32(qH), qLu = smem_u32(qL), kHu = smem_u32(kH), kLu = smem_u32(kL);
    int s0 = blockIdx.x * 32, bh = blockIdx.y;
    int tid = threadIdx.x, lane = tid & 31, wn = tid >> 5;

    load_pair<32, 64>(qH, qL, g_qh + (size_t)bh * 65536 + (size_t)s0 * 64,
                      g_ql + (size_t)bh * 65536 + (size_t)s0 * 64, 64);

    float acc[2][16][4] = {};
    for (int it = 0; it < 8; it++) {
        load_pair<128, 64>(kH, kL, g_kh + (size_t)bh * 65536 + (size_t)it * 8192,
                           g_kl + (size_t)bh * 65536 + (size_t)it * 8192, 64);
        __syncthreads();
#pragma unroll
        for (int kk = 0; kk < 4; kk++) {
            uint32_t ah[2][4], al[2][4], bh2[2][2], bl2[2][2];
#pragma unroll
            for (int mt = 0; mt < 2; mt++) {
                uint32_t off = (uint32_t)(((mt * 16 + (lane & 15)) * 72
                                           + kk * 16 + (lane >> 4) * 8) * 2);
                ldsm4(ah[mt], qHu + off);
                ldsm4(al[mt], qLu + off);
            }
            {
                uint32_t off = (uint32_t)(((wn * 16 + ((lane >> 4) << 3) + (lane & 7)) * 72
                                           + kk * 16 + (((lane >> 3) & 1) << 3)) * 2);
                uint32_t r[4];
                ldsm4(r, kHu + off);
                bh2[0][0] = r[0]; bh2[0][1] = r[1]; bh2[1][0] = r[2]; bh2[1][1] = r[3];
                ldsm4(r, kLu + off);
                bl2[0][0] = r[0]; bl2[0][1] = r[1]; bl2[1][0] = r[2]; bl2[1][1] = r[3];
            }
#pragma unroll
            for (int mt = 0; mt < 2; mt++)
#pragma unroll
                for (int ntl = 0; ntl < 2; ntl++) {
                    float* a = acc[mt][it * 2 + ntl];
                    mma16816(a, ah[mt], bh2[ntl]);
                    mma16816(a, ah[mt], bl2[ntl]);
                    mma16816(a, al[mt], bh2[ntl]);
                }
        }
        __syncthreads();
    }

    // add edge+bias logits from g_w
    size_t wbase = (size_t)bh * 1048576;
#pragma unroll
    for (int mt = 0; mt < 2; mt++)
#pragma unroll
        for (int ntg = 0; ntg < 16; ntg++) {
            int sl = mt * 16 + (lane >> 2);
            int t = (ntg >> 1) * 128 + wn * 16 + (ntg & 1) * 8 + (lane & 3) * 2;
            float2 e0 = *(const float2*)&g_w[wbase + (size_t)(s0 + sl) * 1024 + t];
            float2 e1 = *(const float2*)&g_w[wbase + (size_t)(s0 + sl + 8) * 1024 + t];
            acc[mt][ntg][0] += e0.x; acc[mt][ntg][1] += e0.y;
            acc[mt][ntg][2] += e1.x; acc[mt][ntg][3] += e1.y;
        }

    // row max (rows: r = mt*2+hf -> s_local = mt*16 + (lane>>2) + hf*8)
    float rv[4];
#pragma unroll
    for (int r = 0; r < 4; r++) rv[r] = -1e30f;
#pragma unroll
    for (int mt = 0; mt < 2; mt++)
#pragma unroll
        for (int ntg = 0; ntg < 16; ntg++)
#pragma unroll
            for (int e = 0; e < 4; e++) {
                int r = mt * 2 + (e >> 1);
                rv[r] = fmaxf(rv[r], acc[mt][ntg][e]);
            }
#pragma unroll
    for (int r = 0; r < 4; r++) {
        rv[r] = fmaxf(rv[r], __shfl_xor_sync(~0u, rv[r], 1));
        rv[r] = fmaxf(rv[r], __shfl_xor_sync(~0u, rv[r], 2));
    }
    if ((lane & 3) == 0)
#pragma unroll
        for (int r = 0; r < 4; r++)
            red[wn][(r >> 1) * 16 + (lane >> 2) + (r & 1) * 8] = rv[r];
    __syncthreads();
    if (tid < 32) {
        float m = red[0][tid];
#pragma unroll
        for (int w = 1; w < 8; w++) m = fmaxf(m, red[w][tid]);
        redc[tid] = m;
    }
    __syncthreads();
    float rmax[4];
#pragma unroll
    for (int r = 0; r < 4; r++) rmax[r] = redc[(r >> 1) * 16 + (lane >> 2) + (r & 1) * 8];
    __syncthreads();

    // exp + row sum
#pragma unroll
    for (int r = 0; r < 4; r++) rv[r] = 0.f;
#pragma unroll
    for (int mt = 0; mt < 2; mt++)
#pragma unroll
        for (int ntg = 0; ntg < 16; ntg++)
#pragma unroll
            for (int e = 0; e < 4; e++) {
                int r = mt * 2 + (e >> 1);
                float v = __expf(acc[mt][ntg][e] - rmax[r]);
                acc[mt][ntg][e] = v;
                rv[r] += v;
            }
#pragma unroll
    for (int r = 0; r < 4; r++) {
        rv[r] += __shfl_xor_sync(~0u, rv[r], 1);
        rv[r] += __shfl_xor_sync(~0u, rv[r], 2);
    }
    if ((lane & 3) == 0)
#pragma unroll
        for (int r = 0; r < 4; r++)
            red[wn][(r >> 1) * 16 + (lane >> 2) + (r & 1) * 8] = rv[r];
    __syncthreads();
    if (tid < 32) {
        float sval = red[0][tid];
#pragma unroll
        for (int w = 1; w < 8; w++) sval += red[w][tid];
        redc[tid] = 1.0f / sval;
    }
    __syncthreads();
    float rinv[4];
#pragma unroll
    for (int r = 0; r < 4; r++) rinv[r] = redc[(r >> 1) * 16 + (lane >> 2) + (r & 1) * 8];
    __syncthreads();  // before reusing sm as stage

    // stage fp16 weights in smem (stride 1040 halves), then coalesced store
    __half* stg = (__half*)sm;
#pragma unroll
    for (int mt = 0; mt < 2; mt++)
#pragma unroll
        for (int ntg = 0; ntg < 16; ntg++) {
            int sl = mt * 16 + (lane >> 2);
            int t = (ntg >> 1) * 128 + wn * 16 + (ntg & 1) * 8 + (lane & 3) * 2;
            *(__half2*)&stg[sl * 1040 + t] =
                __floats2half2_rn(acc[mt][ntg][0] * rinv[mt * 2],
                                  acc[mt][ntg][1] * rinv[mt * 2]);
            *(__half2*)&stg[(sl + 8) * 1040 + t] =
                __floats2half2_rn(acc[mt][ntg][2] * rinv[mt * 2 + 1],
                                  acc[mt][ntg][3] * rinv[mt * 2 + 1]);
        }
    __syncthreads();
    for (int i = tid; i < 32 * 128; i += 256) {
        int rr = i >> 7, cc = (i & 127) * 8;
        *(uint4*)&g_wf[wbase + (size_t)(s0 + rr) * 1024 + cc] = *(const uint4*)&stg[rr * 1040 + cc];
    }
}

// ---------------- G5: att = W @ V (content) ----------------
__global__ __launch_bounds__(256) void g5_pv() {
    extern __shared__ char sm[];
    char *aF = sm, *bH = sm + 18432, *bL = sm + 27648;
    uint32_t aFu = smem_u32(aF), bHu = smem_u32(bH), bLu = smem_u32(bL);
    int bh = blockIdx.y, m0 = blockIdx.x * 128;
    const __half* A = g_wf + (size_t)bh * 1048576 + (size_t)m0 * 1024;
    const __half* Bh = g_vth + (size_t)bh * 65536;
    const __half* Bl = g_vtl + (size_t)bh * 65536;
    float acc[2][4][4] = {};
    for (int c = 0; c < 16; c++) {
        load_one<128, 64>(aF, A + c * 64, 1024);
        load_pair<64, 64>(bH, bL, Bh + c * 64, Bl + c * 64, 1024);
        __syncthreads();
        mma_chunk_h<2, 2, 4, 72, 72, 4, false>(aFu, bHu, bLu, acc);
        __syncthreads();
    }
    int lane = threadIdx.x & 31, wid = threadIdx.x >> 5, wm = wid / 2, wn = wid % 2;
    int b = bh >> 4, h = bh & 15;
#pragma unroll
    for (int mt = 0; mt < 2; mt++)
#pragma unroll
        for (int nt = 0; nt < 4; nt++)
#pragma unroll
            for (int hf = 0; hf < 2; hf++) {
                int s = m0 + wm * 32 + mt * 16 + (lane >> 2) + hf * 8;
                int d = wn * 32 + nt * 8 + (lane & 3) * 2;
                size_t o = ((size_t)(b * 1024 + s)) * 1024 + h * 64 + d;
                float2 vv;
                vv.x = acc[mt][nt][hf * 2];
                vv.y = acc[mt][nt][hf * 2 + 1];
                *(float2*)&g_att[o] = vv;
            }
}

// ---------------- K6: att += W @ EV_s, emit att bf16 hi/lo ----------------
__global__ __launch_bounds__(256) void k6_ev(const float* __restrict__ ev) {
    extern __shared__ char sm[];
    char *aF = sm, *bH = sm + 17408, *bL = sm + 35840;
    uint32_t aFu = smem_u32(aF), bHu = smem_u32(bH), bLu = smem_u32(bL);
    int s = blockIdx.x;
    float acc[1][4][4] = {};
    for (int c = 0; c < 8; c++) {
        load_one<64, 128>(aF, g_wf + (size_t)s * 1024 + c * 128, 1048576);
        load_split_h<128, 64>(bH, bL, ev + (size_t)s * 65536 + (size_t)c * 8192, 64);
        __syncthreads();
        mma_chunk_h<2, 1, 4, 136, 72, 8, true>(aFu, bHu, bLu, acc);
        __syncthreads();
    }
    int lane = threadIdx.x & 31, wid = threadIdx.x >> 5, wm = wid / 2, wn = wid % 2;
#pragma unroll
    for (int nt = 0; nt < 4; nt++)
#pragma unroll
        for (int hf = 0; hf < 2; hf++) {
            int bh = wm * 16 + (lane >> 2) + hf * 8;
            int d = wn * 32 + nt * 8 + (lane & 3) * 2;
            int b = bh >> 4, h = bh & 15;
            size_t o = ((size_t)(b * 1024 + s)) * 1024 + h * 64 + d;
            float2 cur = *(float2*)&g_att[o];
            float v0 = cur.x + acc[0][nt][hf * 2];
            float v1 = cur.y + acc[0][nt][hf * 2 + 1];
            BF2 Hh, Ll;
            split2(v0, Hh.b[0], Ll.b[0]); split2(v1, Hh.b[1], Ll.b[1]);
            *(uint32_t*)&g_atth[o] = Hh.u;
            *(uint32_t*)&g_attl[o] = Ll.u;
        }
}

// ---------------- G7: out = att @ Wp^T + bp ----------------
__global__ __launch_bounds__(256) void g7_out(const float* __restrict__ bp, float* __restrict__ out) {
    extern __shared__ char sm[];
    constexpr int AB = 128 * 72 * 2;
    char *aH = sm, *aL = sm + AB, *bH = sm + 2 * AB, *bL = sm + 3 * AB;
    uint32_t aHu = smem_u32(aH), aLu = smem_u32(aL), bHu = smem_u32(bH), bLu = smem_u32(bL);
    int m0 = blockIdx.y * 128, n0 = blockIdx.x * 128;
    const __nv_bfloat16* Bh = g_wth + (size_t)3 * 1048576 + (size_t)n0 * 1024;
    const __nv_bfloat16* Bl = g_wtl + (size_t)3 * 1048576 + (size_t)n0 * 1024;
    float acc[4][4][4] = {};
    for (int c = 0; c < 16; c++) {
        load_pair<128, 64>(aH, aL, g_atth + (size_t)m0 * 1024 + c * 64,
                           g_attl + (size_t)m0 * 1024 + c * 64, 1024);
        load_pair<128, 64>(bH, bL, Bh + c * 64, Bl + c * 64, 1024);
        __syncthreads();
        mma_chunk<4, 4, 4, 72, 72, 4, false>(aHu, aLu, bHu, bLu, acc);
        __syncthreads();
    }
    int lane = threadIdx.x & 31, wid = threadIdx.x >> 5, wm = wid / 4, wn = wid % 4;
#pragma unroll
    for (int mt = 0; mt < 4; mt++)
#pragma unroll
        for (int nt = 0; nt < 4; nt++)
#pragma unroll
            for (int hf = 0; hf < 2; hf++) {
                int m = m0 + wm * 64 + mt * 16 + (lane >> 2) + hf * 8;
                int n = n0 + wn * 32 + nt * 8 + (lane & 3) * 2;
                float2 bb = *(const float2*)&bp[n];
                float2 vv;
                vv.x = acc[mt][nt][hf * 2] + bb.x;
                vv.y = acc[mt][nt][hf * 2 + 1] + bb.y;
                *(float2*)&out[(size_t)m * 1024 + n] = vv;
            }
}

// ---------------- launch ----------------
extern "C" void kernel_launch(void* const* d_in, const int* in_sizes, int n_in,
                              void* d_out, int out_size) {
    const float* queries     = (const float*)d_in[0];
    const float* keys        = (const float*)d_in[1];
    const float* values      = (const float*)d_in[2];
    const float* edges_key   = (const float*)d_in[3];
    const float* edges_value = (const float*)d_in[4];
    const float* attn_bias   = (const float*)d_in[5];
    const float* Wq = (const float*)d_in[6];  const float* bq = (const float*)d_in[7];
    const float* Wk = (const float*)d_in[8];  const float* bk = (const float*)d_in[9];
    const float* Wv = (const float*)d_in[10]; const float* bv = (const float*)d_in[11];
    const float* Wp = (const float*)d_in[12]; const float* bp = (const float*)d_in[13];

    cudaFuncSetAttribute(g1_qkv,  cudaFuncAttributeMaxDynamicSharedMemorySize, 73728);
    cudaFuncSetAttribute(k3_edge, cudaFuncAttributeMaxDynamicSharedMemorySize, 55296);
    cudaFuncSetAttribute(g2s,     cudaFuncAttributeMaxDynamicSharedMemorySize, 66560);
    cudaFuncSetAttribute(g5_pv,   cudaFuncAttributeMaxDynamicSharedMemorySize, 36864);
    cudaFuncSetAttribute(k6_ev,   cudaFuncAttributeMaxDynamicSharedMemorySize, 54272);
    cudaFuncSetAttribute(g7_out,  cudaFuncAttributeMaxDynamicSharedMemorySize, 73728);

    c0_wt<<<dim3(32, 32, 4), 256>>>(Wq, Wk, Wv, Wp);
    c1_x<<<dim3(4096, 3), 256>>>(queries, keys, values);
    g1_qkv<<<dim3(8, 32, 3), 256, 73728>>>(bq, bk, bv);
    c2_vt<<<dim3(16, 64), 256>>>();
    k3_edge<<<dim3(8, 1024), 256, 55296>>>(edges_key, attn_bias);
    g2s<<<dim3(32, 64), 256, 66560>>>();
    g5_pv<<<dim3(8, 64), 256, 36864>>>();
    k6_ev<<<1024, 256, 54272>>>(edges_value);
    g7_out<<<dim3(8, 32), 256, 73728>>>(bp, (float*)d_out);
}

// round 6
// speedup vs baseline: 2.3024x; 1.2241x over previous
#include <cuda_runtime.h>
#include <cuda_bf16.h>
#include <cuda_fp16.h>
#include <cstdint>

// B=4, S=1024, E=1024, H=16, D=64, BH=64.
// mma.sync m16n8k16 + cp.async double-buffered mainloops (g1/g2s/g5/g7).
// bf16 2-term split for projections/logits; fp16 weights + fp16-split V/EV.

#define DI __device__ __forceinline__

// ---------------- device scratch ----------------
__device__ __align__(128) float g_w[67108864];                 // fp32 logits [bh][s][t]
__device__ __align__(128) __half g_wf[67108864];               // fp16 softmax weights
__device__ __align__(128) float g_att[4194304];                // fp32 att [b*s][h*d]
__device__ __align__(128) __nv_bfloat16 g_xh[3*4194304], g_xl[3*4194304];
__device__ __align__(128) __nv_bfloat16 g_wth[4*1048576], g_wtl[4*1048576];
__device__ __align__(128) __nv_bfloat16 g_qh[4194304], g_ql[4194304];
__device__ __align__(128) __nv_bfloat16 g_kh[4194304], g_kl[4194304];
__device__ __align__(128) __half g_vh[4194304], g_vl[4194304];
__device__ __align__(128) __half g_vth[4194304], g_vtl[4194304];
__device__ __align__(128) __nv_bfloat16 g_atth[4194304], g_attl[4194304];

// ---------------- helpers ----------------
union BF2 { __nv_bfloat16 b[2]; uint32_t u; };
union BF4 { __nv_bfloat16 b[4]; uint2 u; };
union HF4 { __half b[4]; uint2 u; };

DI void split2(float v, __nv_bfloat16& h, __nv_bfloat16& l) {
    h = __float2bfloat16(v);
    l = __float2bfloat16(v - __bfloat162float(h));
}
DI void split2h(float v, __half& h, __half& l) {
    h = __float2half_rn(v);
    l = __float2half_rn(v - __half2float(h));
}
DI uint32_t smem_u32(const void* p) {
    uint32_t a;
    asm("{ .reg .u64 t; cvta.to.shared.u64 t, %1; cvt.u32.u64 %0, t; }" : "=r"(a) : "l"(p));
    return a;
}
DI void ldsm4(uint32_t* r, uint32_t a) {
    asm volatile("ldmatrix.sync.aligned.m8n8.x4.shared.b16 {%0,%1,%2,%3}, [%4];"
        : "=r"(r[0]), "=r"(r[1]), "=r"(r[2]), "=r"(r[3]) : "r"(a));
}
DI void ldsm4t(uint32_t* r, uint32_t a) {
    asm volatile("ldmatrix.sync.aligned.m8n8.x4.trans.shared.b16 {%0,%1,%2,%3}, [%4];"
        : "=r"(r[0]), "=r"(r[1]), "=r"(r[2]), "=r"(r[3]) : "r"(a));
}
DI void mma16816(float* d, const uint32_t* a, const uint32_t* b) {
    asm volatile("mma.sync.aligned.m16n8k16.row.col.f32.bf16.bf16.f32 "
        "{%0,%1,%2,%3}, {%4,%5,%6,%7}, {%8,%9}, {%0,%1,%2,%3};"
        : "+f"(d[0]), "+f"(d[1]), "+f"(d[2]), "+f"(d[3])
        : "r"(a[0]), "r"(a[1]), "r"(a[2]), "r"(a[3]), "r"(b[0]), "r"(b[1]));
}
DI void mma16816h(float* d, const uint32_t* a, const uint32_t* b) {
    asm volatile("mma.sync.aligned.m16n8k16.row.col.f32.f16.f16.f32 "
        "{%0,%1,%2,%3}, {%4,%5,%6,%7}, {%8,%9}, {%0,%1,%2,%3};"
        : "+f"(d[0]), "+f"(d[1]), "+f"(d[2]), "+f"(d[3])
        : "r"(a[0]), "r"(a[1]), "r"(a[2]), "r"(a[3]), "r"(b[0]), "r"(b[1]));
}
DI void cp16(uint32_t d, const void* s) {
    asm volatile("cp.async.cg.shared.global [%0], [%1], 16;" :: "r"(d), "l"(s));
}
DI void cp_commit() { asm volatile("cp.async.commit_group;" ::: "memory"); }
template <int N> DI void cp_wait() {
    asm volatile("cp.async.wait_group %0;" :: "n"(N) : "memory");
}

// cp.async hi/lo pair tile: ROWS x KC 16-bit -> padded smem (stride KC+8)
template <int ROWS, int KC, typename T>
DI void cp_pair(uint32_t sH, uint32_t sL, const T* Gh, const T* Gl, size_t ldg) {
    constexpr int SA = KC + 8;
#pragma unroll
    for (int i = threadIdx.x; i < ROWS * KC / 8; i += 256) {
        int r = i / (KC / 8), c = (i % (KC / 8)) * 8;
        uint32_t so = (uint32_t)(r * SA + c) * 2;
        cp16(sH + so, Gh + (size_t)r * ldg + c);
        cp16(sL + so, Gl + (size_t)r * ldg + c);
    }
}
// cp.async single tile
template <int ROWS, int KC, typename T>
DI void cp_one(uint32_t s, const T* G, size_t ldg) {
    constexpr int SA = KC + 8;
#pragma unroll
    for (int i = threadIdx.x; i < ROWS * KC / 8; i += 256) {
        int r = i / (KC / 8), c = (i % (KC / 8)) * 8;
        cp16(s + (uint32_t)(r * SA + c) * 2, G + (size_t)r * ldg + c);
    }
}
// synchronous loaders (k3/k6/g2s-q)
template <int ROWS, int KC, typename T>
DI void load_pair(char* sH, char* sL, const T* Gh, const T* Gl, size_t ldg) {
    constexpr int SA = KC + 8;
#pragma unroll 4
    for (int i = threadIdx.x; i < ROWS * KC / 8; i += 256) {
        int r = i / (KC / 8), c = (i % (KC / 8)) * 8;
        int so = (r * SA + c) * 2;
        *(uint4*)(sH + so) = *(const uint4*)(Gh + (size_t)r * ldg + c);
        *(uint4*)(sL + so) = *(const uint4*)(Gl + (size_t)r * ldg + c);
    }
}
template <int ROWS, int KC, typename T>
DI void load_one(char* s, const T* G, size_t ldg) {
    constexpr int SA = KC + 8;
#pragma unroll 4
    for (int i = threadIdx.x; i < ROWS * KC / 8; i += 256) {
        int r = i / (KC / 8), c = (i % (KC / 8)) * 8;
        *(uint4*)(s + (r * SA + c) * 2) = *(const uint4*)(G + (size_t)r * ldg + c);
    }
}
template <int ROWS, int KC>
DI void load_split(char* sH, char* sL, const float* G, size_t ldg) {
    constexpr int SA = KC + 8;
#pragma unroll 4
    for (int i = threadIdx.x; i < ROWS * KC / 4; i += 256) {
        int r = i / (KC / 4), c = (i % (KC / 4)) * 4;
        float4 v = *(const float4*)(G + (size_t)r * ldg + c);
        BF4 Hh, Ll;
        split2(v.x, Hh.b[0], Ll.b[0]); split2(v.y, Hh.b[1], Ll.b[1]);
        split2(v.z, Hh.b[2], Ll.b[2]); split2(v.w, Hh.b[3], Ll.b[3]);
        int so = (r * SA + c) * 2;
        *(uint2*)(sH + so) = Hh.u;
        *(uint2*)(sL + so) = Ll.u;
    }
}
template <int ROWS, int KC>
DI void load_split_h(char* sH, char* sL, const float* G, size_t ldg) {
    constexpr int SA = KC + 8;
#pragma unroll 4
    for (int i = threadIdx.x; i < ROWS * KC / 4; i += 256) {
        int r = i / (KC / 4), c = (i % (KC / 4)) * 4;
        float4 v = *(const float4*)(G + (size_t)r * ldg + c);
        HF4 Hh, Ll;
        split2h(v.x, Hh.b[0], Ll.b[0]); split2h(v.y, Hh.b[1], Ll.b[1]);
        split2h(v.z, Hh.b[2], Ll.b[2]); split2h(v.w, Hh.b[3], Ll.b[3]);
        int so = (r * SA + c) * 2;
        *(uint2*)(sH + so) = Hh.u;
        *(uint2*)(sL + so) = Ll.u;
    }
}

// bf16 split-3 MMA chunk
template <int WN, int MT, int NT, int SA, int SB, int KSTEPS, bool BT>
DI void mma_chunk(uint32_t aH, uint32_t aL, uint32_t bH, uint32_t bL, float (&acc)[MT][NT][4]) {
    int lane = threadIdx.x & 31, wid = threadIdx.x >> 5;
    int wm = wid / WN, wn = wid % WN;
#pragma unroll
    for (int kk = 0; kk < KSTEPS; kk++) {
        uint32_t ah[MT][4], al[MT][4], bh[NT][2], bl[NT][2];
#pragma unroll
        for (int mt = 0; mt < MT; mt++) {
            uint32_t off = (uint32_t)(((wm * MT * 16 + mt * 16 + (lane & 15)) * SA
                                       + kk * 16 + (lane >> 4) * 8) * 2);
            ldsm4(ah[mt], aH + off);
            ldsm4(al[mt], aL + off);
        }
#pragma unroll
        for (int nt = 0; nt < NT; nt += 2) {
            uint32_t off;
            if (BT)
                off = (uint32_t)(((kk * 16 + (lane & 15)) * SB
                                  + wn * NT * 8 + nt * 8 + (lane >> 4) * 8) * 2);
            else
                off = (uint32_t)(((wn * NT * 8 + nt * 8 + ((lane >> 4) << 3) + (lane & 7)) * SB
                                  + kk * 16 + (((lane >> 3) & 1) << 3)) * 2);
            uint32_t r[4];
            if (BT) ldsm4t(r, bH + off); else ldsm4(r, bH + off);
            bh[nt][0] = r[0]; bh[nt][1] = r[1]; bh[nt + 1][0] = r[2]; bh[nt + 1][1] = r[3];
            if (BT) ldsm4t(r, bL + off); else ldsm4(r, bL + off);
            bl[nt][0] = r[0]; bl[nt][1] = r[1]; bl[nt + 1][0] = r[2]; bl[nt + 1][1] = r[3];
        }
#pragma unroll
        for (int mt = 0; mt < MT; mt++)
#pragma unroll
            for (int nt = 0; nt < NT; nt++) {
                mma16816(acc[mt][nt], ah[mt], bh[nt]);
                mma16816(acc[mt][nt], ah[mt], bl[nt]);
                mma16816(acc[mt][nt], al[mt], bh[nt]);
            }
    }
}
// fp16 chunk: single A, split B
template <int WN, int MT, int NT, int SA, int SB, int KSTEPS, bool BT>
DI void mma_chunk_h(uint32_t aF, uint32_t bH, uint32_t bL, float (&acc)[MT][NT][4]) {
    int lane = threadIdx.x & 31, wid = threadIdx.x >> 5;
    int wm = wid / WN, wn = wid % WN;
#pragma unroll
    for (int kk = 0; kk < KSTEPS; kk++) {
        uint32_t af[MT][4], bh[NT][2], bl[NT][2];
#pragma unroll
        for (int mt = 0; mt < MT; mt++) {
            uint32_t off = (uint32_t)(((wm * MT * 16 + mt * 16 + (lane & 15)) * SA
                                       + kk * 16 + (lane >> 4) * 8) * 2);
            ldsm4(af[mt], aF + off);
        }
#pragma unroll
        for (int nt = 0; nt < NT; nt += 2) {
            uint32_t off;
            if (BT)
                off = (uint32_t)(((kk * 16 + (lane & 15)) * SB
                                  + wn * NT * 8 + nt * 8 + (lane >> 4) * 8) * 2);
            else
                off = (uint32_t)(((wn * NT * 8 + nt * 8 + ((lane >> 4) << 3) + (lane & 7)) * SB
                                  + kk * 16 + (((lane >> 3) & 1) << 3)) * 2);
            uint32_t r[4];
            if (BT) ldsm4t(r, bH + off); else ldsm4(r, bH + off);
            bh[nt][0] = r[0]; bh[nt][1] = r[1]; bh[nt + 1][0] = r[2]; bh[nt + 1][1] = r[3];
            if (BT) ldsm4t(r, bL + off); else ldsm4(r, bL + off);
            bl[nt][0] = r[0]; bl[nt][1] = r[1]; bl[nt + 1][0] = r[2]; bl[nt + 1][1] = r[3];
        }
#pragma unroll
        for (int mt = 0; mt < MT; mt++)
#pragma unroll
            for (int nt = 0; nt < NT; nt++) {
                mma16816h(acc[mt][nt], af[mt], bh[nt]);
                mma16816h(acc[mt][nt], af[mt], bl[nt]);
            }
    }
}

// ---------------- conversion kernels ----------------
__global__ __launch_bounds__(256) void c0_wt(const float* Wq, const float* Wk,
                                             const float* Wv, const float* Wp) {
    __shared__ float smt[32][33];
    int mat = blockIdx.z;
    const float* W = mat == 0 ? Wq : mat == 1 ? Wk : mat == 2 ? Wv : Wp;
    int nblk = blockIdx.x * 32, kblk = blockIdx.y * 32;
    for (int i = threadIdx.x; i < 1024; i += 256) {
        int r = i >> 5, c = i & 31;
        smt[r][c] = W[(size_t)(kblk + r) * 1024 + nblk + c];
    }
    __syncthreads();
    for (int i = threadIdx.x; i < 1024; i += 256) {
        int n = i >> 5, k = i & 31;
        float v = smt[k][n];
        size_t o = (size_t)mat * 1048576 + (size_t)(nblk + n) * 1024 + kblk + k;
        split2(v, g_wth[o], g_wtl[o]);
    }
}
__global__ __launch_bounds__(256) void c1_x(const float* q, const float* k, const float* v) {
    int z = blockIdx.y;
    const float* X = z == 0 ? q : z == 1 ? k : v;
    size_t idx = ((size_t)blockIdx.x * 256 + threadIdx.x) * 4;
    float4 t = *(const float4*)&X[idx];
    BF4 Hh, Ll;
    split2(t.x, Hh.b[0], Ll.b[0]); split2(t.y, Hh.b[1], Ll.b[1]);
    split2(t.z, Hh.b[2], Ll.b[2]); split2(t.w, Hh.b[3], Ll.b[3]);
    *(uint2*)&g_xh[(size_t)z * 4194304 + idx] = Hh.u;
    *(uint2*)&g_xl[(size_t)z * 4194304 + idx] = Ll.u;
}
__global__ __launch_bounds__(256) void c2_vt() {
    __shared__ __half smh[64][65], sml[64][65];
    int sblk = blockIdx.x * 64, bh = blockIdx.y;
    size_t ibase = (size_t)bh * 65536;
    for (int i = threadIdx.x; i < 4096; i += 256) {
        int s = i >> 6, d = i & 63;
        smh[s][d] = g_vh[ibase + (size_t)(sblk + s) * 64 + d];
        sml[s][d] = g_vl[ibase + (size_t)(sblk + s) * 64 + d];
    }
    __syncthreads();
    for (int i = threadIdx.x; i < 4096; i += 256) {
        int d = i >> 6, s = i & 63;
        g_vth[ibase + (size_t)d * 1024 + sblk + s] = smh[s][d];
        g_vtl[ibase + (size_t)d * 1024 + sblk + s] = sml[s][d];
    }
}

// ---------------- G1: q/k/v = X @ W^T + b (cp.async 2-stage) ----------------
__global__ __launch_bounds__(256) void g1_qkv(const float* bq, const float* bk, const float* bv) {
    extern __shared__ char sm[];
    uint32_t smb = smem_u32(sm);
    constexpr int TS = 128 * 72 * 2;       // 18432 per tile
    constexpr int STG = 4 * TS;            // 73728 per stage
    int z = blockIdx.z, m0 = blockIdx.y * 128, n0 = blockIdx.x * 128;
    const __nv_bfloat16* Ah = g_xh + (size_t)z * 4194304 + (size_t)m0 * 1024;
    const __nv_bfloat16* Al = g_xl + (size_t)z * 4194304 + (size_t)m0 * 1024;
    const __nv_bfloat16* Bh = g_wth + (size_t)z * 1048576 + (size_t)n0 * 1024;
    const __nv_bfloat16* Bl = g_wtl + (size_t)z * 1048576 + (size_t)n0 * 1024;
    float acc[4][4][4] = {};
    auto issue = [&](int c) {
        uint32_t b = smb + (uint32_t)(c & 1) * STG;
        cp_pair<128, 64>(b, b + TS, Ah + c * 64, Al + c * 64, 1024);
        cp_pair<128, 64>(b + 2 * TS, b + 3 * TS, Bh + c * 64, Bl + c * 64, 1024);
        cp_commit();
    };
    issue(0);
    for (int c = 0; c < 16; c++) {
        if (c < 15) { issue(c + 1); cp_wait<1>(); } else cp_wait<0>();
        __syncthreads();
        uint32_t b = smb + (uint32_t)(c & 1) * STG;
        mma_chunk<4, 4, 4, 72, 72, 4, false>(b, b + TS, b + 2 * TS, b + 3 * TS, acc);
        __syncthreads();
    }
    const float* bias = z == 0 ? bq : z == 1 ? bk : bv;
    float sc = z == 0 ? 0.125f : 1.f;
    int lane = threadIdx.x & 31, wid = threadIdx.x >> 5, wm = wid / 4, wn = wid % 4;
#pragma unroll
    for (int mt = 0; mt < 4; mt++)
#pragma unroll
        for (int nt = 0; nt < 4; nt++)
#pragma unroll
            for (int hf = 0; hf < 2; hf++) {
                int m = m0 + wm * 64 + mt * 16 + (lane >> 2) + hf * 8;
                int n = n0 + wn * 32 + nt * 8 + (lane & 3) * 2;
                float v0 = (acc[mt][nt][hf * 2] + bias[n]) * sc;
                float v1 = (acc[mt][nt][hf * 2 + 1] + bias[n + 1]) * sc;
                int b = m >> 10, s = m & 1023, h = n >> 6, d = n & 63;
                size_t o = ((size_t)((b << 4) + h) * 1024 + s) * 64 + d;
                if (z == 2) {
                    union { __half b[2]; uint32_t u; } Hh, Ll;
                    split2h(v0, Hh.b[0], Ll.b[0]); split2h(v1, Hh.b[1], Ll.b[1]);
                    *(uint32_t*)&g_vh[o] = Hh.u;
                    *(uint32_t*)&g_vl[o] = Ll.u;
                } else {
                    BF2 Hh, Ll;
                    split2(v0, Hh.b[0], Ll.b[0]); split2(v1, Hh.b[1], Ll.b[1]);
                    __nv_bfloat16* dh = z == 0 ? g_qh : g_kh;
                    __nv_bfloat16* dl = z == 0 ? g_ql : g_kl;
                    *(uint32_t*)&dh[o] = Hh.u;
                    *(uint32_t*)&dl[o] = Ll.u;
                }
            }
}

// ---------------- K3: g_w = edge-key logits + attn_bias ----------------
__global__ __launch_bounds__(256) void k3_edge(const float* __restrict__ ek,
                                               const float* __restrict__ bias) {
    extern __shared__ char sm[];
    char *aH = sm, *aL = sm + 9216, *bH = sm + 18432, *bL = sm + 36864;
    uint32_t aHu = smem_u32(aH), aLu = smem_u32(aL), bHu = smem_u32(bH), bLu = smem_u32(bL);
    int s = blockIdx.y, t0 = blockIdx.x * 128;
    float acc[2][4][4] = {};
    load_pair<64, 64>(aH, aL, g_qh + (size_t)s * 64, g_ql + (size_t)s * 64, 65536);
    load_split<128, 64>(bH, bL, ek + (size_t)s * 65536 + (size_t)t0 * 64, 64);
    __syncthreads();
    mma_chunk<4, 2, 4, 72, 72, 4, false>(aHu, aLu, bHu, bLu, acc);
    int lane = threadIdx.x & 31, wid = threadIdx.x >> 5, wm = wid / 4, wn = wid % 4;
#pragma unroll
    for (int mt = 0; mt < 2; mt++)
#pragma unroll
        for (int nt = 0; nt < 4; nt++)
#pragma unroll
            for (int hf = 0; hf < 2; hf++) {
                int bh = wm * 32 + mt * 16 + (lane >> 2) + hf * 8;
                int t = t0 + wn * 32 + nt * 8 + (lane & 3) * 2;
                size_t idx = (size_t)bh * 1048576 + (size_t)s * 1024 + t;
                float2 bb = *(const float2*)&bias[idx];
                float2 o;
                o.x = acc[mt][nt][hf * 2] + bb.x;
                o.y = acc[mt][nt][hf * 2 + 1] + bb.y;
                *(float2*)&g_w[idx] = o;
            }
}

// ---------------- G2S: content logits + g_w + softmax -> fp16 w (cp.async) ----------------
__global__ __launch_bounds__(256) void g2s() {
    extern __shared__ char sm[];
    __shared__ float red[8][32];
    __shared__ float redc[32];
    constexpr int KTS = 128 * 72 * 2;       // 18432 per k tile
    constexpr int KSTG = 2 * KTS;           // hi+lo per stage
    char *qH = sm, *qL = sm + 4608;
    uint32_t smb = smem_u32(sm);
    uint32_t qHu = smb, qLu = smb + 4608;
    int s0 = blockIdx.x * 32, bh = blockIdx.y;
    int tid = threadIdx.x, lane = tid & 31, wn = tid >> 5;

    auto issueK = [&](int it) {
        uint32_t b = smb + 9216 + (uint32_t)(it & 1) * KSTG;
        cp_pair<128, 64>(b, b + KTS, g_kh + (size_t)bh * 65536 + (size_t)it * 8192,
                         g_kl + (size_t)bh * 65536 + (size_t)it * 8192, 64);
        cp_commit();
    };
    issueK(0);
    load_pair<32, 64>(qH, qL, g_qh + (size_t)bh * 65536 + (size_t)s0 * 64,
                      g_ql + (size_t)bh * 65536 + (size_t)s0 * 64, 64);

    float acc[2][16][4] = {};
    for (int it = 0; it < 8; it++) {
        if (it < 7) { issueK(it + 1); cp_wait<1>(); } else cp_wait<0>();
        __syncthreads();
        uint32_t kHu = smb + 9216 + (uint32_t)(it & 1) * KSTG, kLu = kHu + KTS;
#pragma unroll
        for (int kk = 0; kk < 4; kk++) {
            uint32_t ah[2][4], al[2][4], bh2[2][2], bl2[2][2];
#pragma unroll
            for (int mt = 0; mt < 2; mt++) {
                uint32_t off = (uint32_t)(((mt * 16 + (lane & 15)) * 72
                                           + kk * 16 + (lane >> 4) * 8) * 2);
                ldsm4(ah[mt], qHu + off);
                ldsm4(al[mt], qLu + off);
            }
            {
                uint32_t off = (uint32_t)(((wn * 16 + ((lane >> 4) << 3) + (lane & 7)) * 72
                                           + kk * 16 + (((lane >> 3) & 1) << 3)) * 2);
                uint32_t r[4];
                ldsm4(r, kHu + off);
                bh2[0][0] = r[0]; bh2[0][1] = r[1]; bh2[1][0] = r[2]; bh2[1][1] = r[3];
                ldsm4(r, kLu + off);
                bl2[0][0] = r[0]; bl2[0][1] = r[1]; bl2[1][0] = r[2]; bl2[1][1] = r[3];
            }
#pragma unroll
            for (int mt = 0; mt < 2; mt++)
#pragma unroll
                for (int ntl = 0; ntl < 2; ntl++) {
                    float* a = acc[mt][it * 2 + ntl];
                    mma16816(a, ah[mt], bh2[ntl]);
                    mma16816(a, ah[mt], bl2[ntl]);
                    mma16816(a, al[mt], bh2[ntl]);
                }
        }
        __syncthreads();
    }

    size_t wbase = (size_t)bh * 1048576;
#pragma unroll
    for (int mt = 0; mt < 2; mt++)
#pragma unroll
        for (int ntg = 0; ntg < 16; ntg++) {
            int sl = mt * 16 + (lane >> 2);
            int t = (ntg >> 1) * 128 + wn * 16 + (ntg & 1) * 8 + (lane & 3) * 2;
            float2 e0 = *(const float2*)&g_w[wbase + (size_t)(s0 + sl) * 1024 + t];
            float2 e1 = *(const float2*)&g_w[wbase + (size_t)(s0 + sl + 8) * 1024 + t];
            acc[mt][ntg][0] += e0.x; acc[mt][ntg][1] += e0.y;
            acc[mt][ntg][2] += e1.x; acc[mt][ntg][3] += e1.y;
        }

    float rv[4];
#pragma unroll
    for (int r = 0; r < 4; r++) rv[r] = -1e30f;
#pragma unroll
    for (int mt = 0; mt < 2; mt++)
#pragma unroll
        for (int ntg = 0; ntg < 16; ntg++)
#pragma unroll
            for (int e = 0; e < 4; e++) {
                int r = mt * 2 + (e >> 1);
                rv[r] = fmaxf(rv[r], acc[mt][ntg][e]);
            }
#pragma unroll
    for (int r = 0; r < 4; r++) {
        rv[r] = fmaxf(rv[r], __shfl_xor_sync(~0u, rv[r], 1));
        rv[r] = fmaxf(rv[r], __shfl_xor_sync(~0u, rv[r], 2));
    }
    if ((lane & 3) == 0)
#pragma unroll
        for (int r = 0; r < 4; r++)
            red[wn][(r >> 1) * 16 + (lane >> 2) + (r & 1) * 8] = rv[r];
    __syncthreads();
    if (tid < 32) {
        float m = red[0][tid];
#pragma unroll
        for (int w = 1; w < 8; w++) m = fmaxf(m, red[w][tid]);
        redc[tid] = m;
    }
    __syncthreads();
    float rmax[4];
#pragma unroll
    for (int r = 0; r < 4; r++) rmax[r] = redc[(r >> 1) * 16 + (lane >> 2) + (r & 1) * 8];
    __syncthreads();

#pragma unroll
    for (int r = 0; r < 4; r++) rv[r] = 0.f;
#pragma unroll
    for (int mt = 0; mt < 2; mt++)
#pragma unroll
        for (int ntg = 0; ntg < 16; ntg++)
#pragma unroll
            for (int e = 0; e < 4; e++) {
                int r = mt * 2 + (e >> 1);
                float v = __expf(acc[mt][ntg][e] - rmax[r]);
                acc[mt][ntg][e] = v;
                rv[r] += v;
            }
#pragma unroll
    for (int r = 0; r < 4; r++) {
        rv[r] += __shfl_xor_sync(~0u, rv[r], 1);
        rv[r] += __shfl_xor_sync(~0u, rv[r], 2);
    }
    if ((lane & 3) == 0)
#pragma unroll
        for (int r = 0; r < 4; r++)
            red[wn][(r >> 1) * 16 + (lane >> 2) + (r & 1) * 8] = rv[r];
    __syncthreads();
    if (tid < 32) {
        float sval = red[0][tid];
#pragma unroll
        for (int w = 1; w < 8; w++) sval += red[w][tid];
        redc[tid] = 1.0f / sval;
    }
    __syncthreads();
    float rinv[4];
#pragma unroll
    for (int r = 0; r < 4; r++) rinv[r] = redc[(r >> 1) * 16 + (lane >> 2) + (r & 1) * 8];
    __syncthreads();

    __half* stg = (__half*)sm;
#pragma unroll
    for (int mt = 0; mt < 2; mt++)
#pragma unroll
        for (int ntg = 0; ntg < 16; ntg++) {
            int sl = mt * 16 + (lane >> 2);
            int t = (ntg >> 1) * 128 + wn * 16 + (ntg & 1) * 8 + (lane & 3) * 2;
            *(__half2*)&stg[sl * 1040 + t] =
                __floats2half2_rn(acc[mt][ntg][0] * rinv[mt * 2],
                                  acc[mt][ntg][1] * rinv[mt * 2]);
            *(__half2*)&stg[(sl + 8) * 1040 + t] =
                __floats2half2_rn(acc[mt][ntg][2] * rinv[mt * 2 + 1],
                                  acc[mt][ntg][3] * rinv[mt * 2 + 1]);
        }
    __syncthreads();
    for (int i = tid; i < 32 * 128; i += 256) {
        int rr = i >> 7, cc = (i & 127) * 8;
        *(uint4*)&g_wf[wbase + (size_t)(s0 + rr) * 1024 + cc] = *(const uint4*)&stg[rr * 1040 + cc];
    }
}

// ---------------- G5: att = W @ V (cp.async 2-stage) ----------------
__global__ __launch_bounds__(256) void g5_pv() {
    extern __shared__ char sm[];
    uint32_t smb = smem_u32(sm);
    constexpr int ATS = 128 * 72 * 2;       // 18432
    constexpr int BTS = 64 * 72 * 2;        // 9216
    constexpr int STG = ATS + 2 * BTS;      // 36864
    int bh = blockIdx.y, m0 = blockIdx.x * 128;
    const __half* A = g_wf + (size_t)bh * 1048576 + (size_t)m0 * 1024;
    const __half* Bh = g_vth + (size_t)bh * 65536;
    const __half* Bl = g_vtl + (size_t)bh * 65536;
    float acc[2][4][4] = {};
    auto issue = [&](int c) {
        uint32_t b = smb + (uint32_t)(c & 1) * STG;
        cp_one<128, 64>(b, A + c * 64, 1024);
        cp_pair<64, 64>(b + ATS, b + ATS + BTS, Bh + c * 64, Bl + c * 64, 1024);
        cp_commit();
    };
    issue(0);
    for (int c = 0; c < 16; c++) {
        if (c < 15) { issue(c + 1); cp_wait<1>(); } else cp_wait<0>();
        __syncthreads();
        uint32_t b = smb + (uint32_t)(c & 1) * STG;
        mma_chunk_h<2, 2, 4, 72, 72, 4, false>(b, b + ATS, b + ATS + BTS, acc);
        __syncthreads();
    }
    int lane = threadIdx.x & 31, wid = threadIdx.x >> 5, wm = wid / 2, wn = wid % 2;
    int b = bh >> 4, h = bh & 15;
#pragma unroll
    for (int mt = 0; mt < 2; mt++)
#pragma unroll
        for (int nt = 0; nt < 4; nt++)
#pragma unroll
            for (int hf = 0; hf < 2; hf++) {
                int s = m0 + wm * 32 + mt * 16 + (lane >> 2) + hf * 8;
                int d = wn * 32 + nt * 8 + (lane & 3) * 2;
                size_t o = ((size_t)(b * 1024 + s)) * 1024 + h * 64 + d;
                float2 vv;
                vv.x = acc[mt][nt][hf * 2];
                vv.y = acc[mt][nt][hf * 2 + 1];
                *(float2*)&g_att[o] = vv;
            }
}

// ---------------- K6: att += W @ EV_s, emit att bf16 hi/lo ----------------
__global__ __launch_bounds__(256) void k6_ev(const float* __restrict__ ev) {
    extern __shared__ char sm[];
    char *aF = sm, *bH = sm + 17408, *bL = sm + 35840;
    uint32_t aFu = smem_u32(aF), bHu = smem_u32(bH), bLu = smem_u32(bL);
    int s = blockIdx.x;
    float acc[1][4][4] = {};
    for (int c = 0; c < 8; c++) {
        load_one<64, 128>(aF, g_wf + (size_t)s * 1024 + c * 128, 1048576);
        load_split_h<128, 64>(bH, bL, ev + (size_t)s * 65536 + (size_t)c * 8192, 64);
        __syncthreads();
        mma_chunk_h<2, 1, 4, 136, 72, 8, true>(aFu, bHu, bLu, acc);
        __syncthreads();
    }
    int lane = threadIdx.x & 31, wid = threadIdx.x >> 5, wm = wid / 2, wn = wid % 2;
#pragma unroll
    for (int nt = 0; nt < 4; nt++)
#pragma unroll
        for (int hf = 0; hf < 2; hf++) {
            int bh = wm * 16 + (lane >> 2) + hf * 8;
            int d = wn * 32 + nt * 8 + (lane & 3) * 2;
            int b = bh >> 4, h = bh & 15;
            size_t o = ((size_t)(b * 1024 + s)) * 1024 + h * 64 + d;
            float2 cur = *(float2*)&g_att[o];
            float v0 = cur.x + acc[0][nt][hf * 2];
            float v1 = cur.y + acc[0][nt][hf * 2 + 1];
            BF2 Hh, Ll;
            split2(v0, Hh.b[0], Ll.b[0]); split2(v1, Hh.b[1], Ll.b[1]);
            *(uint32_t*)&g_atth[o] = Hh.u;
            *(uint32_t*)&g_attl[o] = Ll.u;
        }
}

// ---------------- G7: out = att @ Wp^T + bp (cp.async 2-stage) ----------------
__global__ __launch_bounds__(256) void g7_out(const float* __restrict__ bp, float* __restrict__ out) {
    extern __shared__ char sm[];
    uint32_t smb = smem_u32(sm);
    constexpr int TS = 128 * 72 * 2;
    constexpr int STG = 4 * TS;
    int m0 = blockIdx.y * 128, n0 = blockIdx.x * 128;
    const __nv_bfloat16* Bh = g_wth + (size_t)3 * 1048576 + (size_t)n0 * 1024;
    const __nv_bfloat16* Bl = g_wtl + (size_t)3 * 1048576 + (size_t)n0 * 1024;
    float acc[4][4][4] = {};
    auto issue = [&](int c) {
        uint32_t b = smb + (uint32_t)(c & 1) * STG;
        cp_pair<128, 64>(b, b + TS, g_atth + (size_t)m0 * 1024 + c * 64,
                         g_attl + (size_t)m0 * 1024 + c * 64, 1024);
        cp_pair<128, 64>(b + 2 * TS, b + 3 * TS, Bh + c * 64, Bl + c * 64, 1024);
        cp_commit();
    };
    issue(0);
    for (int c = 0; c < 16; c++) {
        if (c < 15) { issue(c + 1); cp_wait<1>(); } else cp_wait<0>();
        __syncthreads();
        uint32_t b = smb + (uint32_t)(c & 1) * STG;
        mma_chunk<4, 4, 4, 72, 72, 4, false>(b, b + TS, b + 2 * TS, b + 3 * TS, acc);
        __syncthreads();
    }
    int lane = threadIdx.x & 31, wid = threadIdx.x >> 5, wm = wid / 4, wn = wid % 4;
#pragma unroll
    for (int mt = 0; mt < 4; mt++)
#pragma unroll
        for (int nt = 0; nt < 4; nt++)
#pragma unroll
            for (int hf = 0; hf < 2; hf++) {
                int m = m0 + wm * 64 + mt * 16 + (lane >> 2) + hf * 8;
                int n = n0 + wn * 32 + nt * 8 + (lane & 3) * 2;
                float2 bb = *(const float2*)&bp[n];
                float2 vv;
                vv.x = acc[mt][nt][hf * 2] + bb.x;
                vv.y = acc[mt][nt][hf * 2 + 1] + bb.y;
                *(float2*)&out[(size_t)m * 1024 + n] = vv;
            }
}

// ---------------- launch ----------------
extern "C" void kernel_launch(void* const* d_in, const int* in_sizes, int n_in,
                              void* d_out, int out_size) {
    const float* queries     = (const float*)d_in[0];
    const float* keys        = (const float*)d_in[1];
    const float* values      = (const float*)d_in[2];
    const float* edges_key   = (const float*)d_in[3];
    const float* edges_value = (const float*)d_in[4];
    const float* attn_bias   = (const float*)d_in[5];
    const float* Wq = (const float*)d_in[6];  const float* bq = (const float*)d_in[7];
    const float* Wk = (const float*)d_in[8];  const float* bk = (const float*)d_in[9];
    const float* Wv = (const float*)d_in[10]; const float* bv = (const float*)d_in[11];
    const float* Wp = (const float*)d_in[12]; const float* bp = (const float*)d_in[13];

    cudaFuncSetAttribute(g1_qkv,  cudaFuncAttributeMaxDynamicSharedMemorySize, 147456);
    cudaFuncSetAttribute(k3_edge, cudaFuncAttributeMaxDynamicSharedMemorySize, 55296);
    cudaFuncSetAttribute(g2s,     cudaFuncAttributeMaxDynamicSharedMemorySize, 82944);
    cudaFuncSetAttribute(g5_pv,   cudaFuncAttributeMaxDynamicSharedMemorySize, 73728);
    cudaFuncSetAttribute(k6_ev,   cudaFuncAttributeMaxDynamicSharedMemorySize, 54272);
    cudaFuncSetAttribute(g7_out,  cudaFuncAttributeMaxDynamicSharedMemorySize, 147456);

    c0_wt<<<dim3(32, 32, 4), 256>>>(Wq, Wk, Wv, Wp);
    c1_x<<<dim3(4096, 3), 256>>>(queries, keys, values);
    g1_qkv<<<dim3(8, 32, 3), 256, 147456>>>(bq, bk, bv);
    c2_vt<<<dim3(16, 64), 256>>>();
    k3_edge<<<dim3(8, 1024), 256, 55296>>>(edges_key, attn_bias);
    g2s<<<dim3(32, 64), 256, 82944>>>();
    g5_pv<<<dim3(8, 64), 256, 73728>>>();
    k6_ev<<<1024, 256, 54272>>>(edges_value);
    g7_out<<<dim3(8, 32), 256, 147456>>>(bp, (float*)d_out);
}

// round 7
// speedup vs baseline: 2.7633x; 1.2002x over previous
#include <cuda_runtime.h>
#include <cuda_bf16.h>
#include <cuda_fp16.h>
#include <cstdint>

// B=4, S=1024, E=1024, H=16, D=64, BH=64.
// fp16 scheme: g1/g7 use fp16 hi/lo split A x single-fp16 B (2 products);
// logits/PV/EV GEMMs use single-fp16 operands (1 product). cp.async pipelines.

#define DI __device__ __forceinline__

// ---------------- device scratch ----------------
__device__ __align__(128) float g_w[67108864];                  // fp32 edge+bias logits [bh][s][t]
__device__ __align__(128) __half g_wf[67108864];                // fp16 softmax weights
__device__ __align__(128) float g_att[4194304];                 // fp32 att [b*s][h*d]
__device__ __align__(128) __half g_xh[3*4194304], g_xl[3*4194304];  // X fp16 hi/lo
__device__ __align__(128) __half g_wtf[4*1048576];              // W^T fp16 single [mat][n][k]
__device__ __align__(128) __half g_qf[4194304];                 // [bh][s][d] scaled q
__device__ __align__(128) __half g_kf[4194304];                 // [bh][t][d]
__device__ __align__(128) __half g_vf[4194304];                 // [bh][s][d]
__device__ __align__(128) __half g_vtf[4194304];                // [bh][d][t]
__device__ __align__(128) __half g_atth[4194304], g_attl[4194304];  // att fp16 hi/lo

// ---------------- helpers ----------------
union HF2 { __half b[2]; uint32_t u; };
union HF4 { __half b[4]; uint2 u; };

DI void split2h(float v, __half& h, __half& l) {
    h = __float2half_rn(v);
    l = __float2half_rn(v - __half2float(h));
}
DI uint32_t smem_u32(const void* p) {
    uint32_t a;
    asm("{ .reg .u64 t; cvta.to.shared.u64 t, %1; cvt.u32.u64 %0, t; }" : "=r"(a) : "l"(p));
    return a;
}
DI void ldsm4(uint32_t* r, uint32_t a) {
    asm volatile("ldmatrix.sync.aligned.m8n8.x4.shared.b16 {%0,%1,%2,%3}, [%4];"
        : "=r"(r[0]), "=r"(r[1]), "=r"(r[2]), "=r"(r[3]) : "r"(a));
}
DI void ldsm4t(uint32_t* r, uint32_t a) {
    asm volatile("ldmatrix.sync.aligned.m8n8.x4.trans.shared.b16 {%0,%1,%2,%3}, [%4];"
        : "=r"(r[0]), "=r"(r[1]), "=r"(r[2]), "=r"(r[3]) : "r"(a));
}
DI void mma16816h(float* d, const uint32_t* a, const uint32_t* b) {
    asm volatile("mma.sync.aligned.m16n8k16.row.col.f32.f16.f16.f32 "
        "{%0,%1,%2,%3}, {%4,%5,%6,%7}, {%8,%9}, {%0,%1,%2,%3};"
        : "+f"(d[0]), "+f"(d[1]), "+f"(d[2]), "+f"(d[3])
        : "r"(a[0]), "r"(a[1]), "r"(a[2]), "r"(a[3]), "r"(b[0]), "r"(b[1]));
}
DI void cp16(uint32_t d, const void* s) {
    asm volatile("cp.async.cg.shared.global [%0], [%1], 16;" :: "r"(d), "l"(s));
}
DI void cp_commit() { asm volatile("cp.async.commit_group;" ::: "memory"); }
template <int N> DI void cp_wait() {
    asm volatile("cp.async.wait_group %0;" :: "n"(N) : "memory");
}

// cp.async pair (hi/lo) tile: ROWS x KC 16-bit -> padded smem (stride KC+8)
template <int ROWS, int KC, typename T>
DI void cp_pair(uint32_t sH, uint32_t sL, const T* Gh, const T* Gl, size_t ldg) {
    constexpr int SA = KC + 8;
#pragma unroll
    for (int i = threadIdx.x; i < ROWS * KC / 8; i += 256) {
        int r = i / (KC / 8), c = (i % (KC / 8)) * 8;
        uint32_t so = (uint32_t)(r * SA + c) * 2;
        cp16(sH + so, Gh + (size_t)r * ldg + c);
        cp16(sL + so, Gl + (size_t)r * ldg + c);
    }
}
template <int ROWS, int KC, typename T>
DI void cp_one(uint32_t s, const T* G, size_t ldg) {
    constexpr int SA = KC + 8;
#pragma unroll
    for (int i = threadIdx.x; i < ROWS * KC / 8; i += 256) {
        int r = i / (KC / 8), c = (i % (KC / 8)) * 8;
        cp16(s + (uint32_t)(r * SA + c) * 2, G + (size_t)r * ldg + c);
    }
}
// synchronous single 16-bit tile loader
template <int ROWS, int KC, typename T>
DI void load_one(char* s, const T* G, size_t ldg) {
    constexpr int SA = KC + 8;
#pragma unroll 4
    for (int i = threadIdx.x; i < ROWS * KC / 8; i += 256) {
        int r = i / (KC / 8), c = (i % (KC / 8)) * 8;
        *(uint4*)(s + (r * SA + c) * 2) = *(const uint4*)(G + (size_t)r * ldg + c);
    }
}
// fp32 -> single fp16 converting loader
template <int ROWS, int KC>
DI void load_cvt_h(char* s, const float* G, size_t ldg) {
    constexpr int SA = KC + 8;
#pragma unroll 4
    for (int i = threadIdx.x; i < ROWS * KC / 4; i += 256) {
        int r = i / (KC / 4), c = (i % (KC / 4)) * 4;
        float4 v = *(const float4*)(G + (size_t)r * ldg + c);
        HF4 Hh;
        Hh.b[0] = __float2half_rn(v.x); Hh.b[1] = __float2half_rn(v.y);
        Hh.b[2] = __float2half_rn(v.z); Hh.b[3] = __float2half_rn(v.w);
        *(uint2*)(s + (r * SA + c) * 2) = Hh.u;
    }
}

// fp16 chunk: A hi/lo split, B single -> 2 products
template <int WN, int MT, int NT, int SA, int SB, int KSTEPS>
DI void mma_chunk_h2(uint32_t aH, uint32_t aL, uint32_t bF, float (&acc)[MT][NT][4]) {
    int lane = threadIdx.x & 31, wid = threadIdx.x >> 5;
    int wm = wid / WN, wn = wid % WN;
#pragma unroll
    for (int kk = 0; kk < KSTEPS; kk++) {
        uint32_t ah[MT][4], al[MT][4], bf[NT][2];
#pragma unroll
        for (int mt = 0; mt < MT; mt++) {
            uint32_t off = (uint32_t)(((wm * MT * 16 + mt * 16 + (lane & 15)) * SA
                                       + kk * 16 + (lane >> 4) * 8) * 2);
            ldsm4(ah[mt], aH + off);
            ldsm4(al[mt], aL + off);
        }
#pragma unroll
        for (int nt = 0; nt < NT; nt += 2) {
            uint32_t off = (uint32_t)(((wn * NT * 8 + nt * 8 + ((lane >> 4) << 3) + (lane & 7)) * SB
                                       + kk * 16 + (((lane >> 3) & 1) << 3)) * 2);
            uint32_t r[4];
            ldsm4(r, bF + off);
            bf[nt][0] = r[0]; bf[nt][1] = r[1]; bf[nt + 1][0] = r[2]; bf[nt + 1][1] = r[3];
        }
#pragma unroll
        for (int mt = 0; mt < MT; mt++)
#pragma unroll
            for (int nt = 0; nt < NT; nt++) {
                mma16816h(acc[mt][nt], ah[mt], bf[nt]);
                mma16816h(acc[mt][nt], al[mt], bf[nt]);
            }
    }
}
// fp16 chunk: A single, B single -> 1 product
template <int WN, int MT, int NT, int SA, int SB, int KSTEPS, bool BT>
DI void mma_chunk_h1(uint32_t aF, uint32_t bF, float (&acc)[MT][NT][4]) {
    int lane = threadIdx.x & 31, wid = threadIdx.x >> 5;
    int wm = wid / WN, wn = wid % WN;
#pragma unroll
    for (int kk = 0; kk < KSTEPS; kk++) {
        uint32_t af[MT][4], bf[NT][2];
#pragma unroll
        for (int mt = 0; mt < MT; mt++) {
            uint32_t off = (uint32_t)(((wm * MT * 16 + mt * 16 + (lane & 15)) * SA
                                       + kk * 16 + (lane >> 4) * 8) * 2);
            ldsm4(af[mt], aF + off);
        }
#pragma unroll
        for (int nt = 0; nt < NT; nt += 2) {
            uint32_t off;
            if (BT)
                off = (uint32_t)(((kk * 16 + (lane & 15)) * SB
                                  + wn * NT * 8 + nt * 8 + (lane >> 4) * 8) * 2);
            else
                off = (uint32_t)(((wn * NT * 8 + nt * 8 + ((lane >> 4) << 3) + (lane & 7)) * SB
                                  + kk * 16 + (((lane >> 3) & 1) << 3)) * 2);
            uint32_t r[4];
            if (BT) ldsm4t(r, bF + off); else ldsm4(r, bF + off);
            bf[nt][0] = r[0]; bf[nt][1] = r[1]; bf[nt + 1][0] = r[2]; bf[nt + 1][1] = r[3];
        }
#pragma unroll
        for (int mt = 0; mt < MT; mt++)
#pragma unroll
            for (int nt = 0; nt < NT; nt++)
                mma16816h(acc[mt][nt], af[mt], bf[nt]);
    }
}

// ---------------- conversion kernels ----------------
__global__ __launch_bounds__(256) void c0_wt(const float* Wq, const float* Wk,
                                             const float* Wv, const float* Wp) {
    __shared__ float smt[32][33];
    int mat = blockIdx.z;
    const float* W = mat == 0 ? Wq : mat == 1 ? Wk : mat == 2 ? Wv : Wp;
    int nblk = blockIdx.x * 32, kblk = blockIdx.y * 32;
    for (int i = threadIdx.x; i < 1024; i += 256) {
        int r = i >> 5, c = i & 31;
        smt[r][c] = W[(size_t)(kblk + r) * 1024 + nblk + c];
    }
    __syncthreads();
    for (int i = threadIdx.x; i < 1024; i += 256) {
        int n = i >> 5, k = i & 31;
        size_t o = (size_t)mat * 1048576 + (size_t)(nblk + n) * 1024 + kblk + k;
        g_wtf[o] = __float2half_rn(smt[k][n]);
    }
}
__global__ __launch_bounds__(256) void c1_x(const float* q, const float* k, const float* v) {
    int z = blockIdx.y;
    const float* X = z == 0 ? q : z == 1 ? k : v;
    size_t idx = ((size_t)blockIdx.x * 256 + threadIdx.x) * 4;
    float4 t = *(const float4*)&X[idx];
    HF4 Hh, Ll;
    split2h(t.x, Hh.b[0], Ll.b[0]); split2h(t.y, Hh.b[1], Ll.b[1]);
    split2h(t.z, Hh.b[2], Ll.b[2]); split2h(t.w, Hh.b[3], Ll.b[3]);
    *(uint2*)&g_xh[(size_t)z * 4194304 + idx] = Hh.u;
    *(uint2*)&g_xl[(size_t)z * 4194304 + idx] = Ll.u;
}
__global__ __launch_bounds__(256) void c2_vt() {
    __shared__ __half smh[64][65];
    int sblk = blockIdx.x * 64, bh = blockIdx.y;
    size_t ibase = (size_t)bh * 65536;
    for (int i = threadIdx.x; i < 4096; i += 256) {
        int s = i >> 6, d = i & 63;
        smh[s][d] = g_vf[ibase + (size_t)(sblk + s) * 64 + d];
    }
    __syncthreads();
    for (int i = threadIdx.x; i < 4096; i += 256) {
        int d = i >> 6, s = i & 63;
        g_vtf[ibase + (size_t)d * 1024 + sblk + s] = smh[s][d];
    }
}

// ---------------- G1: q/k/v = X @ W^T + b (A split2 x B single, cp.async) ----------------
__global__ __launch_bounds__(256) void g1_qkv(const float* bq, const float* bk, const float* bv) {
    extern __shared__ char sm[];
    uint32_t smb = smem_u32(sm);
    constexpr int TS = 128 * 72 * 2;       // 18432 per tile
    constexpr int STG = 3 * TS;            // A hi + A lo + B
    int z = blockIdx.z, m0 = blockIdx.y * 128, n0 = blockIdx.x * 128;
    const __half* Ah = g_xh + (size_t)z * 4194304 + (size_t)m0 * 1024;
    const __half* Al = g_xl + (size_t)z * 4194304 + (size_t)m0 * 1024;
    const __half* Bf = g_wtf + (size_t)z * 1048576 + (size_t)n0 * 1024;
    float acc[4][4][4] = {};
    auto issue = [&](int c) {
        uint32_t b = smb + (uint32_t)(c & 1) * STG;
        cp_pair<128, 64>(b, b + TS, Ah + c * 64, Al + c * 64, 1024);
        cp_one<128, 64>(b + 2 * TS, Bf + c * 64, 1024);
        cp_commit();
    };
    issue(0);
    for (int c = 0; c < 16; c++) {
        if (c < 15) { issue(c + 1); cp_wait<1>(); } else cp_wait<0>();
        __syncthreads();
        uint32_t b = smb + (uint32_t)(c & 1) * STG;
        mma_chunk_h2<4, 4, 4, 72, 72, 4>(b, b + TS, b + 2 * TS, acc);
        __syncthreads();
    }
    const float* bias = z == 0 ? bq : z == 1 ? bk : bv;
    float sc = z == 0 ? 0.125f : 1.f;
    __half* dst = z == 0 ? g_qf : z == 1 ? g_kf : g_vf;
    int lane = threadIdx.x & 31, wid = threadIdx.x >> 5, wm = wid / 4, wn = wid % 4;
#pragma unroll
    for (int mt = 0; mt < 4; mt++)
#pragma unroll
        for (int nt = 0; nt < 4; nt++)
#pragma unroll
            for (int hf = 0; hf < 2; hf++) {
                int m = m0 + wm * 64 + mt * 16 + (lane >> 2) + hf * 8;
                int n = n0 + wn * 32 + nt * 8 + (lane & 3) * 2;
                float v0 = (acc[mt][nt][hf * 2] + bias[n]) * sc;
                float v1 = (acc[mt][nt][hf * 2 + 1] + bias[n + 1]) * sc;
                int b = m >> 10, s = m & 1023, h = n >> 6, d = n & 63;
                size_t o = ((size_t)((b << 4) + h) * 1024 + s) * 64 + d;
                HF2 P;
                P.b[0] = __float2half_rn(v0); P.b[1] = __float2half_rn(v1);
                *(uint32_t*)&dst[o] = P.u;
            }
}

// ---------------- K3: g_w = edge-key logits + attn_bias (1 product) ----------------
__global__ __launch_bounds__(256) void k3_edge(const float* __restrict__ ek,
                                               const float* __restrict__ bias) {
    extern __shared__ char sm[];
    char *aF = sm, *bF = sm + 9216;
    uint32_t aFu = smem_u32(aF), bFu = smem_u32(bF);
    int s = blockIdx.y, t0 = blockIdx.x * 128;
    float acc[2][4][4] = {};
    load_one<64, 64>(aF, g_qf + (size_t)s * 64, 65536);
    load_cvt_h<128, 64>(bF, ek + (size_t)s * 65536 + (size_t)t0 * 64, 64);
    __syncthreads();
    mma_chunk_h1<4, 2, 4, 72, 72, 4, false>(aFu, bFu, acc);
    int lane = threadIdx.x & 31, wid = threadIdx.x >> 5, wm = wid / 4, wn = wid % 4;
#pragma unroll
    for (int mt = 0; mt < 2; mt++)
#pragma unroll
        for (int nt = 0; nt < 4; nt++)
#pragma unroll
            for (int hf = 0; hf < 2; hf++) {
                int bh = wm * 32 + mt * 16 + (lane >> 2) + hf * 8;
                int t = t0 + wn * 32 + nt * 8 + (lane & 3) * 2;
                size_t idx = (size_t)bh * 1048576 + (size_t)s * 1024 + t;
                float2 bb = *(const float2*)&bias[idx];
                float2 o;
                o.x = acc[mt][nt][hf * 2] + bb.x;
                o.y = acc[mt][nt][hf * 2 + 1] + bb.y;
                *(float2*)&g_w[idx] = o;
            }
}

// ---------------- G2S: content logits + g_w + softmax -> fp16 w ----------------
__global__ __launch_bounds__(256) void g2s() {
    extern __shared__ char sm[];
    __shared__ float red[8][32];
    __shared__ float redc[32];
    constexpr int KTS = 128 * 72 * 2;       // 18432 per k stage
    uint32_t smb = smem_u32(sm);
    uint32_t qFu = smb;
    int s0 = blockIdx.x * 32, bh = blockIdx.y;
    int tid = threadIdx.x, lane = tid & 31, wn = tid >> 5;

    auto issueK = [&](int it) {
        uint32_t b = smb + 4608 + (uint32_t)(it & 1) * KTS;
        cp_one<128, 64>(b, g_kf + (size_t)bh * 65536 + (size_t)it * 8192, 64);
        cp_commit();
    };
    issueK(0);
    load_one<32, 64>(sm, g_qf + (size_t)bh * 65536 + (size_t)s0 * 64, 64);

    float acc[2][16][4] = {};
    for (int it = 0; it < 8; it++) {
        if (it < 7) { issueK(it + 1); cp_wait<1>(); } else cp_wait<0>();
        __syncthreads();
        uint32_t kFu = smb + 4608 + (uint32_t)(it & 1) * KTS;
#pragma unroll
        for (int kk = 0; kk < 4; kk++) {
            uint32_t ah[2][4], bf2[2][2];
#pragma unroll
            for (int mt = 0; mt < 2; mt++) {
                uint32_t off = (uint32_t)(((mt * 16 + (lane & 15)) * 72
                                           + kk * 16 + (lane >> 4) * 8) * 2);
                ldsm4(ah[mt], qFu + off);
            }
            {
                uint32_t off = (uint32_t)(((wn * 16 + ((lane >> 4) << 3) + (lane & 7)) * 72
                                           + kk * 16 + (((lane >> 3) & 1) << 3)) * 2);
                uint32_t r[4];
                ldsm4(r, kFu + off);
                bf2[0][0] = r[0]; bf2[0][1] = r[1]; bf2[1][0] = r[2]; bf2[1][1] = r[3];
            }
#pragma unroll
            for (int mt = 0; mt < 2; mt++)
#pragma unroll
                for (int ntl = 0; ntl < 2; ntl++)
                    mma16816h(acc[mt][it * 2 + ntl], ah[mt], bf2[ntl]);
        }
        __syncthreads();
    }

    size_t wbase = (size_t)bh * 1048576;
#pragma unroll
    for (int mt = 0; mt < 2; mt++)
#pragma unroll
        for (int ntg = 0; ntg < 16; ntg++) {
            int sl = mt * 16 + (lane >> 2);
            int t = (ntg >> 1) * 128 + wn * 16 + (ntg & 1) * 8 + (lane & 3) * 2;
            float2 e0 = *(const float2*)&g_w[wbase + (size_t)(s0 + sl) * 1024 + t];
            float2 e1 = *(const float2*)&g_w[wbase + (size_t)(s0 + sl + 8) * 1024 + t];
            acc[mt][ntg][0] += e0.x; acc[mt][ntg][1] += e0.y;
            acc[mt][ntg][2] += e1.x; acc[mt][ntg][3] += e1.y;
        }

    float rv[4];
#pragma unroll
    for (int r = 0; r < 4; r++) rv[r] = -1e30f;
#pragma unroll
    for (int mt = 0; mt < 2; mt++)
#pragma unroll
        for (int ntg = 0; ntg < 16; ntg++)
#pragma unroll
            for (int e = 0; e < 4; e++) {
                int r = mt * 2 + (e >> 1);
                rv[r] = fmaxf(rv[r], acc[mt][ntg][e]);
            }
#pragma unroll
    for (int r = 0; r < 4; r++) {
        rv[r] = fmaxf(rv[r], __shfl_xor_sync(~0u, rv[r], 1));
        rv[r] = fmaxf(rv[r], __shfl_xor_sync(~0u, rv[r], 2));
    }
    if ((lane & 3) == 0)
#pragma unroll
        for (int r = 0; r < 4; r++)
            red[wn][(r >> 1) * 16 + (lane >> 2) + (r & 1) * 8] = rv[r];
    __syncthreads();
    if (tid < 32) {
        float m = red[0][tid];
#pragma unroll
        for (int w = 1; w < 8; w++) m = fmaxf(m, red[w][tid]);
        redc[tid] = m;
    }
    __syncthreads();
    float rmax[4];
#pragma unroll
    for (int r = 0; r < 4; r++) rmax[r] = redc[(r >> 1) * 16 + (lane >> 2) + (r & 1) * 8];
    __syncthreads();

#pragma unroll
    for (int r = 0; r < 4; r++) rv[r] = 0.f;
#pragma unroll
    for (int mt = 0; mt < 2; mt++)
#pragma unroll
        for (int ntg = 0; ntg < 16; ntg++)
#pragma unroll
            for (int e = 0; e < 4; e++) {
                int r = mt * 2 + (e >> 1);
                float v = __expf(acc[mt][ntg][e] - rmax[r]);
                acc[mt][ntg][e] = v;
                rv[r] += v;
            }
#pragma unroll
    for (int r = 0; r < 4; r++) {
        rv[r] += __shfl_xor_sync(~0u, rv[r], 1);
        rv[r] += __shfl_xor_sync(~0u, rv[r], 2);
    }
    if ((lane & 3) == 0)
#pragma unroll
        for (int r = 0; r < 4; r++)
            red[wn][(r >> 1) * 16 + (lane >> 2) + (r & 1) * 8] = rv[r];
    __syncthreads();
    if (tid < 32) {
        float sval = red[0][tid];
#pragma unroll
        for (int w = 1; w < 8; w++) sval += red[w][tid];
        redc[tid] = 1.0f / sval;
    }
    __syncthreads();
    float rinv[4];
#pragma unroll
    for (int r = 0; r < 4; r++) rinv[r] = redc[(r >> 1) * 16 + (lane >> 2) + (r & 1) * 8];
    __syncthreads();

    __half* stg = (__half*)sm;
#pragma unroll
    for (int mt = 0; mt < 2; mt++)
#pragma unroll
        for (int ntg = 0; ntg < 16; ntg++) {
            int sl = mt * 16 + (lane >> 2);
            int t = (ntg >> 1) * 128 + wn * 16 + (ntg & 1) * 8 + (lane & 3) * 2;
            *(__half2*)&stg[sl * 1040 + t] =
                __floats2half2_rn(acc[mt][ntg][0] * rinv[mt * 2],
                                  acc[mt][ntg][1] * rinv[mt * 2]);
            *(__half2*)&stg[(sl + 8) * 1040 + t] =
                __floats2half2_rn(acc[mt][ntg][2] * rinv[mt * 2 + 1],
                                  acc[mt][ntg][3] * rinv[mt * 2 + 1]);
        }
    __syncthreads();
    for (int i = tid; i < 32 * 128; i += 256) {
        int rr = i >> 7, cc = (i & 127) * 8;
        *(uint4*)&g_wf[wbase + (size_t)(s0 + rr) * 1024 + cc] = *(const uint4*)&stg[rr * 1040 + cc];
    }
}

// ---------------- G5: att = W @ V (1 product, cp.async) ----------------
__global__ __launch_bounds__(256) void g5_pv() {
    extern __shared__ char sm[];
    uint32_t smb = smem_u32(sm);
    constexpr int ATS = 128 * 72 * 2;       // 18432
    constexpr int BTS = 64 * 72 * 2;        // 9216
    constexpr int STG = ATS + BTS;          // 27648
    int bh = blockIdx.y, m0 = blockIdx.x * 128;
    const __half* A = g_wf + (size_t)bh * 1048576 + (size_t)m0 * 1024;
    const __half* Bf = g_vtf + (size_t)bh * 65536;
    float acc[2][4][4] = {};
    auto issue = [&](int c) {
        uint32_t b = smb + (uint32_t)(c & 1) * STG;
        cp_one<128, 64>(b, A + c * 64, 1024);
        cp_one<64, 64>(b + ATS, Bf + c * 64, 1024);
        cp_commit();
    };
    issue(0);
    for (int c = 0; c < 16; c++) {
        if (c < 15) { issue(c + 1); cp_wait<1>(); } else cp_wait<0>();
        __syncthreads();
        uint32_t b = smb + (uint32_t)(c & 1) * STG;
        mma_chunk_h1<2, 2, 4, 72, 72, 4, false>(b, b + ATS, acc);
        __syncthreads();
    }
    int lane = threadIdx.x & 31, wid = threadIdx.x >> 5, wm = wid / 2, wn = wid % 2;
    int b = bh >> 4, h = bh & 15;
#pragma unroll
    for (int mt = 0; mt < 2; mt++)
#pragma unroll
        for (int nt = 0; nt < 4; nt++)
#pragma unroll
            for (int hf = 0; hf < 2; hf++) {
                int s = m0 + wm * 32 + mt * 16 + (lane >> 2) + hf * 8;
                int d = wn * 32 + nt * 8 + (lane & 3) * 2;
                size_t o = ((size_t)(b * 1024 + s)) * 1024 + h * 64 + d;
                float2 vv;
                vv.x = acc[mt][nt][hf * 2];
                vv.y = acc[mt][nt][hf * 2 + 1];
                *(float2*)&g_att[o] = vv;
            }
}

// ---------------- K6: att += W @ EV_s, emit att fp16 hi/lo (1 product) ----------------
__global__ __launch_bounds__(256) void k6_ev(const float* __restrict__ ev) {
    extern __shared__ char sm[];
    char *aF = sm, *bF = sm + 17408;
    uint32_t aFu = smem_u32(aF), bFu = smem_u32(bF);
    int s = blockIdx.x;
    float acc[1][4][4] = {};
    for (int c = 0; c < 8; c++) {
        load_one<64, 128>(aF, g_wf + (size_t)s * 1024 + c * 128, 1048576);
        load_cvt_h<128, 64>(bF, ev + (size_t)s * 65536 + (size_t)c * 8192, 64);
        __syncthreads();
        mma_chunk_h1<2, 1, 4, 136, 72, 8, true>(aFu, bFu, acc);
        __syncthreads();
    }
    int lane = threadIdx.x & 31, wid = threadIdx.x >> 5, wm = wid / 2, wn = wid % 2;
#pragma unroll
    for (int nt = 0; nt < 4; nt++)
#pragma unroll
        for (int hf = 0; hf < 2; hf++) {
            int bh = wm * 16 + (lane >> 2) + hf * 8;
            int d = wn * 32 + nt * 8 + (lane & 3) * 2;
            int b = bh >> 4, h = bh & 15;
            size_t o = ((size_t)(b * 1024 + s)) * 1024 + h * 64 + d;
            float2 cur = *(float2*)&g_att[o];
            float v0 = cur.x + acc[0][nt][hf * 2];
            float v1 = cur.y + acc[0][nt][hf * 2 + 1];
            HF2 Hh, Ll;
            split2h(v0, Hh.b[0], Ll.b[0]); split2h(v1, Hh.b[1], Ll.b[1]);
            *(uint32_t*)&g_atth[o] = Hh.u;
            *(uint32_t*)&g_attl[o] = Ll.u;
        }
}

// ---------------- G7: out = att @ Wp^T + bp (A split2 x B single) ----------------
__global__ __launch_bounds__(256) void g7_out(const float* __restrict__ bp, float* __restrict__ out) {
    extern __shared__ char sm[];
    uint32_t smb = smem_u32(sm);
    constexpr int TS = 128 * 72 * 2;
    constexpr int STG = 3 * TS;
    int m0 = blockIdx.y * 128, n0 = blockIdx.x * 128;
    const __half* Bf = g_wtf + (size_t)3 * 1048576 + (size_t)n0 * 1024;
    float acc[4][4][4] = {};
    auto issue = [&](int c) {
        uint32_t b = smb + (uint32_t)(c & 1) * STG;
        cp_pair<128, 64>(b, b + TS, g_atth + (size_t)m0 * 1024 + c * 64,
                         g_attl + (size_t)m0 * 1024 + c * 64, 1024);
        cp_one<128, 64>(b + 2 * TS, Bf + c * 64, 1024);
        cp_commit();
    };
    issue(0);
    for (int c = 0; c < 16; c++) {
        if (c < 15) { issue(c + 1); cp_wait<1>(); } else cp_wait<0>();
        __syncthreads();
        uint32_t b = smb + (uint32_t)(c & 1) * STG;
        mma_chunk_h2<4, 4, 4, 72, 72, 4>(b, b + TS, b + 2 * TS, acc);
        __syncthreads();
    }
    int lane = threadIdx.x & 31, wid = threadIdx.x >> 5, wm = wid / 4, wn = wid % 4;
#pragma unroll
    for (int mt = 0; mt < 4; mt++)
#pragma unroll
        for (int nt = 0; nt < 4; nt++)
#pragma unroll
            for (int hf = 0; hf < 2; hf++) {
                int m = m0 + wm * 64 + mt * 16 + (lane >> 2) + hf * 8;
                int n = n0 + wn * 32 + nt * 8 + (lane & 3) * 2;
                float2 bb = *(const float2*)&bp[n];
                float2 vv;
                vv.x = acc[mt][nt][hf * 2] + bb.x;
                vv.y = acc[mt][nt][hf * 2 + 1] + bb.y;
                *(float2*)&out[(size_t)m * 1024 + n] = vv;
            }
}

// ---------------- launch ----------------
extern "C" void kernel_launch(void* const* d_in, const int* in_sizes, int n_in,
                              void* d_out, int out_size) {
    const float* queries     = (const float*)d_in[0];
    const float* keys        = (const float*)d_in[1];
    const float* values      = (const float*)d_in[2];
    const float* edges_key   = (const float*)d_in[3];
    const float* edges_value = (const float*)d_in[4];
    const float* attn_bias   = (const float*)d_in[5];
    const float* Wq = (const float*)d_in[6];  const float* bq = (const float*)d_in[7];
    const float* Wk = (const float*)d_in[8];  const float* bk = (const float*)d_in[9];
    const float* Wv = (const float*)d_in[10]; const float* bv = (const float*)d_in[11];
    const float* Wp = (const float*)d_in[12]; const float* bp = (const float*)d_in[13];

    cudaFuncSetAttribute(g1_qkv,  cudaFuncAttributeMaxDynamicSharedMemorySize, 110592);
    cudaFuncSetAttribute(k3_edge, cudaFuncAttributeMaxDynamicSharedMemorySize, 27648);
    cudaFuncSetAttribute(g2s,     cudaFuncAttributeMaxDynamicSharedMemorySize, 66560);
    cudaFuncSetAttribute(g5_pv,   cudaFuncAttributeMaxDynamicSharedMemorySize, 55296);
    cudaFuncSetAttribute(k6_ev,   cudaFuncAttributeMaxDynamicSharedMemorySize, 35840);
    cudaFuncSetAttribute(g7_out,  cudaFuncAttributeMaxDynamicSharedMemorySize, 110592);

    c0_wt<<<dim3(32, 32, 4), 256>>>(Wq, Wk, Wv, Wp);
    c1_x<<<dim3(4096, 3), 256>>>(queries, keys, values);
    g1_qkv<<<dim3(8, 32, 3), 256, 110592>>>(bq, bk, bv);
    c2_vt<<<dim3(16, 64), 256>>>();
    k3_edge<<<dim3(8, 1024), 256, 27648>>>(edges_key, attn_bias);
    g2s<<<dim3(32, 64), 256, 66560>>>();
    g5_pv<<<dim3(8, 64), 256, 55296>>>();
    k6_ev<<<1024, 256, 35840>>>(edges_value);
    g7_out<<<dim3(8, 32), 256, 110592>>>(bp, (float*)d_out);
}

// round 8
// speedup vs baseline: 3.2186x; 1.1647x over previous
#include <cuda_runtime.h>
#include <cuda_bf16.h>
#include <cuda_fp16.h>
#include <cstdint>

// B=4, S=1024, E=1024, H=16, D=64, BH=64.
// All GEMMs single-fp16 x single-fp16 mma.sync m16n8k16 (1 product),
// fp32 accum, cp.async double-buffered mainloops. fp32 kept only for the
// edge+bias logits intermediate (g_w) and att accumulator (g_att).

#define DI __device__ __forceinline__

// ---------------- device scratch ----------------
__device__ __align__(128) float g_w[67108864];                  // fp32 edge+bias logits [bh][s][t]
__device__ __align__(128) __half g_wf[67108864];                // fp16 softmax weights
__device__ __align__(128) float g_att[4194304];                 // fp32 att [b*s][h*d]
__device__ __align__(128) __half g_xf[3*4194304];               // X fp16 [z][m][k]
__device__ __align__(128) __half g_wtf[4*1048576];              // W^T fp16 [mat][n][k]
__device__ __align__(128) __half g_qf[4194304];                 // [bh][s][d] scaled q
__device__ __align__(128) __half g_kf[4194304];                 // [bh][t][d]
__device__ __align__(128) __half g_vf[4194304];                 // [bh][s][d]
__device__ __align__(128) __half g_vtf[4194304];                // [bh][d][t]
__device__ __align__(128) __half g_attf[4194304];               // att fp16 [b*s][h*d]

// ---------------- helpers ----------------
union HF2 { __half b[2]; uint32_t u; };
union HF4 { __half b[4]; uint2 u; };

DI uint32_t smem_u32(const void* p) {
    uint32_t a;
    asm("{ .reg .u64 t; cvta.to.shared.u64 t, %1; cvt.u32.u64 %0, t; }" : "=r"(a) : "l"(p));
    return a;
}
DI void ldsm4(uint32_t* r, uint32_t a) {
    asm volatile("ldmatrix.sync.aligned.m8n8.x4.shared.b16 {%0,%1,%2,%3}, [%4];"
        : "=r"(r[0]), "=r"(r[1]), "=r"(r[2]), "=r"(r[3]) : "r"(a));
}
DI void ldsm4t(uint32_t* r, uint32_t a) {
    asm volatile("ldmatrix.sync.aligned.m8n8.x4.trans.shared.b16 {%0,%1,%2,%3}, [%4];"
        : "=r"(r[0]), "=r"(r[1]), "=r"(r[2]), "=r"(r[3]) : "r"(a));
}
DI void mma16816h(float* d, const uint32_t* a, const uint32_t* b) {
    asm volatile("mma.sync.aligned.m16n8k16.row.col.f32.f16.f16.f32 "
        "{%0,%1,%2,%3}, {%4,%5,%6,%7}, {%8,%9}, {%0,%1,%2,%3};"
        : "+f"(d[0]), "+f"(d[1]), "+f"(d[2]), "+f"(d[3])
        : "r"(a[0]), "r"(a[1]), "r"(a[2]), "r"(a[3]), "r"(b[0]), "r"(b[1]));
}
DI void cp16(uint32_t d, const void* s) {
    asm volatile("cp.async.cg.shared.global [%0], [%1], 16;" :: "r"(d), "l"(s));
}
DI void cp_commit() { asm volatile("cp.async.commit_group;" ::: "memory"); }
template <int N> DI void cp_wait() {
    asm volatile("cp.async.wait_group %0;" :: "n"(N) : "memory");
}

// cp.async single tile: ROWS x KC 16-bit -> padded smem (stride KC+8)
template <int ROWS, int KC, typename T>
DI void cp_one(uint32_t s, const T* G, size_t ldg) {
    constexpr int SA = KC + 8;
#pragma unroll
    for (int i = threadIdx.x; i < ROWS * KC / 8; i += 256) {
        int r = i / (KC / 8), c = (i % (KC / 8)) * 8;
        cp16(s + (uint32_t)(r * SA + c) * 2, G + (size_t)r * ldg + c);
    }
}
// synchronous single 16-bit tile loader
template <int ROWS, int KC, typename T>
DI void load_one(char* s, const T* G, size_t ldg) {
    constexpr int SA = KC + 8;
#pragma unroll 4
    for (int i = threadIdx.x; i < ROWS * KC / 8; i += 256) {
        int r = i / (KC / 8), c = (i % (KC / 8)) * 8;
        *(uint4*)(s + (r * SA + c) * 2) = *(const uint4*)(G + (size_t)r * ldg + c);
    }
}
// fp32 -> single fp16 converting loader
template <int ROWS, int KC>
DI void load_cvt_h(char* s, const float* G, size_t ldg) {
    constexpr int SA = KC + 8;
#pragma unroll 4
    for (int i = threadIdx.x; i < ROWS * KC / 4; i += 256) {
        int r = i / (KC / 4), c = (i % (KC / 4)) * 4;
        float4 v = *(const float4*)(G + (size_t)r * ldg + c);
        HF4 Hh;
        Hh.b[0] = __float2half_rn(v.x); Hh.b[1] = __float2half_rn(v.y);
        Hh.b[2] = __float2half_rn(v.z); Hh.b[3] = __float2half_rn(v.w);
        *(uint2*)(s + (r * SA + c) * 2) = Hh.u;
    }
}

// fp16 chunk: A single, B single -> 1 product
template <int WN, int MT, int NT, int SA, int SB, int KSTEPS, bool BT>
DI void mma_chunk_h1(uint32_t aF, uint32_t bF, float (&acc)[MT][NT][4]) {
    int lane = threadIdx.x & 31, wid = threadIdx.x >> 5;
    int wm = wid / WN, wn = wid % WN;
#pragma unroll
    for (int kk = 0; kk < KSTEPS; kk++) {
        uint32_t af[MT][4], bf[NT][2];
#pragma unroll
        for (int mt = 0; mt < MT; mt++) {
            uint32_t off = (uint32_t)(((wm * MT * 16 + mt * 16 + (lane & 15)) * SA
                                       + kk * 16 + (lane >> 4) * 8) * 2);
            ldsm4(af[mt], aF + off);
        }
#pragma unroll
        for (int nt = 0; nt < NT; nt += 2) {
            uint32_t off;
            if (BT)
                off = (uint32_t)(((kk * 16 + (lane & 15)) * SB
                                  + wn * NT * 8 + nt * 8 + (lane >> 4) * 8) * 2);
            else
                off = (uint32_t)(((wn * NT * 8 + nt * 8 + ((lane >> 4) << 3) + (lane & 7)) * SB
                                  + kk * 16 + (((lane >> 3) & 1) << 3)) * 2);
            uint32_t r[4];
            if (BT) ldsm4t(r, bF + off); else ldsm4(r, bF + off);
            bf[nt][0] = r[0]; bf[nt][1] = r[1]; bf[nt + 1][0] = r[2]; bf[nt + 1][1] = r[3];
        }
#pragma unroll
        for (int mt = 0; mt < MT; mt++)
#pragma unroll
            for (int nt = 0; nt < NT; nt++)
                mma16816h(acc[mt][nt], af[mt], bf[nt]);
    }
}

// ---------------- conversion kernels ----------------
__global__ __launch_bounds__(256) void c0_wt(const float* Wq, const float* Wk,
                                             const float* Wv, const float* Wp) {
    __shared__ float smt[32][33];
    int mat = blockIdx.z;
    const float* W = mat == 0 ? Wq : mat == 1 ? Wk : mat == 2 ? Wv : Wp;
    int nblk = blockIdx.x * 32, kblk = blockIdx.y * 32;
    for (int i = threadIdx.x; i < 1024; i += 256) {
        int r = i >> 5, c = i & 31;
        smt[r][c] = W[(size_t)(kblk + r) * 1024 + nblk + c];
    }
    __syncthreads();
    for (int i = threadIdx.x; i < 1024; i += 256) {
        int n = i >> 5, k = i & 31;
        size_t o = (size_t)mat * 1048576 + (size_t)(nblk + n) * 1024 + kblk + k;
        g_wtf[o] = __float2half_rn(smt[k][n]);
    }
}
__global__ __launch_bounds__(256) void c1_x(const float* q, const float* k, const float* v) {
    int z = blockIdx.y;
    const float* X = z == 0 ? q : z == 1 ? k : v;
    size_t idx = ((size_t)blockIdx.x * 256 + threadIdx.x) * 4;
    float4 t = *(const float4*)&X[idx];
    HF4 Hh;
    Hh.b[0] = __float2half_rn(t.x); Hh.b[1] = __float2half_rn(t.y);
    Hh.b[2] = __float2half_rn(t.z); Hh.b[3] = __float2half_rn(t.w);
    *(uint2*)&g_xf[(size_t)z * 4194304 + idx] = Hh.u;
}
__global__ __launch_bounds__(256) void c2_vt() {
    __shared__ __half smh[64][65];
    int sblk = blockIdx.x * 64, bh = blockIdx.y;
    size_t ibase = (size_t)bh * 65536;
    for (int i = threadIdx.x; i < 4096; i += 256) {
        int s = i >> 6, d = i & 63;
        smh[s][d] = g_vf[ibase + (size_t)(sblk + s) * 64 + d];
    }
    __syncthreads();
    for (int i = threadIdx.x; i < 4096; i += 256) {
        int d = i >> 6, s = i & 63;
        g_vtf[ibase + (size_t)d * 1024 + sblk + s] = smh[s][d];
    }
}

// ---------------- G1: q/k/v = X @ W^T + b (1 product, cp.async) ----------------
__global__ __launch_bounds__(256) void g1_qkv(const float* bq, const float* bk, const float* bv) {
    extern __shared__ char sm[];
    uint32_t smb = smem_u32(sm);
    constexpr int TS = 128 * 72 * 2;       // 18432 per tile
    constexpr int STG = 2 * TS;            // A + B
    int z = blockIdx.z, m0 = blockIdx.y * 128, n0 = blockIdx.x * 128;
    const __half* Af = g_xf + (size_t)z * 4194304 + (size_t)m0 * 1024;
    const __half* Bf = g_wtf + (size_t)z * 1048576 + (size_t)n0 * 1024;
    float acc[4][4][4] = {};
    auto issue = [&](int c) {
        uint32_t b = smb + (uint32_t)(c & 1) * STG;
        cp_one<128, 64>(b, Af + c * 64, 1024);
        cp_one<128, 64>(b + TS, Bf + c * 64, 1024);
        cp_commit();
    };
    issue(0);
    for (int c = 0; c < 16; c++) {
        if (c < 15) { issue(c + 1); cp_wait<1>(); } else cp_wait<0>();
        __syncthreads();
        uint32_t b = smb + (uint32_t)(c & 1) * STG;
        mma_chunk_h1<4, 4, 4, 72, 72, 4, false>(b, b + TS, acc);
        __syncthreads();
    }
    const float* bias = z == 0 ? bq : z == 1 ? bk : bv;
    float sc = z == 0 ? 0.125f : 1.f;
    __half* dst = z == 0 ? g_qf : z == 1 ? g_kf : g_vf;
    int lane = threadIdx.x & 31, wid = threadIdx.x >> 5, wm = wid / 4, wn = wid % 4;
#pragma unroll
    for (int mt = 0; mt < 4; mt++)
#pragma unroll
        for (int nt = 0; nt < 4; nt++)
#pragma unroll
            for (int hf = 0; hf < 2; hf++) {
                int m = m0 + wm * 64 + mt * 16 + (lane >> 2) + hf * 8;
                int n = n0 + wn * 32 + nt * 8 + (lane & 3) * 2;
                float v0 = (acc[mt][nt][hf * 2] + bias[n]) * sc;
                float v1 = (acc[mt][nt][hf * 2 + 1] + bias[n + 1]) * sc;
                int b = m >> 10, s = m & 1023, h = n >> 6, d = n & 63;
                size_t o = ((size_t)((b << 4) + h) * 1024 + s) * 64 + d;
                HF2 P;
                P.b[0] = __float2half_rn(v0); P.b[1] = __float2half_rn(v1);
                *(uint32_t*)&dst[o] = P.u;
            }
}

// ---------------- K3: g_w = edge-key logits + attn_bias (1 product) ----------------
__global__ __launch_bounds__(256) void k3_edge(const float* __restrict__ ek,
                                               const float* __restrict__ bias) {
    extern __shared__ char sm[];
    char *aF = sm, *bF = sm + 9216;
    uint32_t aFu = smem_u32(aF), bFu = smem_u32(bF);
    int s = blockIdx.y, t0 = blockIdx.x * 128;
    float acc[2][4][4] = {};
    load_one<64, 64>(aF, g_qf + (size_t)s * 64, 65536);
    load_cvt_h<128, 64>(bF, ek + (size_t)s * 65536 + (size_t)t0 * 64, 64);
    __syncthreads();
    mma_chunk_h1<4, 2, 4, 72, 72, 4, false>(aFu, bFu, acc);
    int lane = threadIdx.x & 31, wid = threadIdx.x >> 5, wm = wid / 4, wn = wid % 4;
#pragma unroll
    for (int mt = 0; mt < 2; mt++)
#pragma unroll
        for (int nt = 0; nt < 4; nt++)
#pragma unroll
            for (int hf = 0; hf < 2; hf++) {
                int bh = wm * 32 + mt * 16 + (lane >> 2) + hf * 8;
                int t = t0 + wn * 32 + nt * 8 + (lane & 3) * 2;
                size_t idx = (size_t)bh * 1048576 + (size_t)s * 1024 + t;
                float2 bb = *(const float2*)&bias[idx];
                float2 o;
                o.x = acc[mt][nt][hf * 2] + bb.x;
                o.y = acc[mt][nt][hf * 2 + 1] + bb.y;
                *(float2*)&g_w[idx] = o;
            }
}

// ---------------- G2S: content logits + g_w + softmax -> fp16 w ----------------
__global__ __launch_bounds__(256) void g2s() {
    extern __shared__ char sm[];
    __shared__ float red[8][32];
    __shared__ float redc[32];
    constexpr int KTS = 128 * 72 * 2;       // 18432 per k stage
    uint32_t smb = smem_u32(sm);
    uint32_t qFu = smb;
    int s0 = blockIdx.x * 32, bh = blockIdx.y;
    int tid = threadIdx.x, lane = tid & 31, wn = tid >> 5;

    auto issueK = [&](int it) {
        uint32_t b = smb + 4608 + (uint32_t)(it & 1) * KTS;
        cp_one<128, 64>(b, g_kf + (size_t)bh * 65536 + (size_t)it * 8192, 64);
        cp_commit();
    };
    issueK(0);
    load_one<32, 64>(sm, g_qf + (size_t)bh * 65536 + (size_t)s0 * 64, 64);

    float acc[2][16][4] = {};
    for (int it = 0; it < 8; it++) {
        if (it < 7) { issueK(it + 1); cp_wait<1>(); } else cp_wait<0>();
        __syncthreads();
        uint32_t kFu = smb + 4608 + (uint32_t)(it & 1) * KTS;
#pragma unroll
        for (int kk = 0; kk < 4; kk++) {
            uint32_t ah[2][4], bf2[2][2];
#pragma unroll
            for (int mt = 0; mt < 2; mt++) {
                uint32_t off = (uint32_t)(((mt * 16 + (lane & 15)) * 72
                                           + kk * 16 + (lane >> 4) * 8) * 2);
                ldsm4(ah[mt], qFu + off);
            }
            {
                uint32_t off = (uint32_t)(((wn * 16 + ((lane >> 4) << 3) + (lane & 7)) * 72
                                           + kk * 16 + (((lane >> 3) & 1) << 3)) * 2);
                uint32_t r[4];
                ldsm4(r, kFu + off);
                bf2[0][0] = r[0]; bf2[0][1] = r[1]; bf2[1][0] = r[2]; bf2[1][1] = r[3];
            }
#pragma unroll
            for (int mt = 0; mt < 2; mt++)
#pragma unroll
                for (int ntl = 0; ntl < 2; ntl++)
                    mma16816h(acc[mt][it * 2 + ntl], ah[mt], bf2[ntl]);
        }
        __syncthreads();
    }

    size_t wbase = (size_t)bh * 1048576;
#pragma unroll
    for (int mt = 0; mt < 2; mt++)
#pragma unroll
        for (int ntg = 0; ntg < 16; ntg++) {
            int sl = mt * 16 + (lane >> 2);
            int t = (ntg >> 1) * 128 + wn * 16 + (ntg & 1) * 8 + (lane & 3) * 2;
            float2 e0 = *(const float2*)&g_w[wbase + (size_t)(s0 + sl) * 1024 + t];
            float2 e1 = *(const float2*)&g_w[wbase + (size_t)(s0 + sl + 8) * 1024 + t];
            acc[mt][ntg][0] += e0.x; acc[mt][ntg][1] += e0.y;
            acc[mt][ntg][2] += e1.x; acc[mt][ntg][3] += e1.y;
        }

    float rv[4];
#pragma unroll
    for (int r = 0; r < 4; r++) rv[r] = -1e30f;
#pragma unroll
    for (int mt = 0; mt < 2; mt++)
#pragma unroll
        for (int ntg = 0; ntg < 16; ntg++)
#pragma unroll
            for (int e = 0; e < 4; e++) {
                int r = mt * 2 + (e >> 1);
                rv[r] = fmaxf(rv[r], acc[mt][ntg][e]);
            }
#pragma unroll
    for (int r = 0; r < 4; r++) {
        rv[r] = fmaxf(rv[r], __shfl_xor_sync(~0u, rv[r], 1));
        rv[r] = fmaxf(rv[r], __shfl_xor_sync(~0u, rv[r], 2));
    }
    if ((lane & 3) == 0)
#pragma unroll
        for (int r = 0; r < 4; r++)
            red[wn][(r >> 1) * 16 + (lane >> 2) + (r & 1) * 8] = rv[r];
    __syncthreads();
    if (tid < 32) {
        float m = red[0][tid];
#pragma unroll
        for (int w = 1; w < 8; w++) m = fmaxf(m, red[w][tid]);
        redc[tid] = m;
    }
    __syncthreads();
    float rmax[4];
#pragma unroll
    for (int r = 0; r < 4; r++) rmax[r] = redc[(r >> 1) * 16 + (lane >> 2) + (r & 1) * 8];
    __syncthreads();

#pragma unroll
    for (int r = 0; r < 4; r++) rv[r] = 0.f;
#pragma unroll
    for (int mt = 0; mt < 2; mt++)
#pragma unroll
        for (int ntg = 0; ntg < 16; ntg++)
#pragma unroll
            for (int e = 0; e < 4; e++) {
                int r = mt * 2 + (e >> 1);
                float v = __expf(acc[mt][ntg][e] - rmax[r]);
                acc[mt][ntg][e] = v;
                rv[r] += v;
            }
#pragma unroll
    for (int r = 0; r < 4; r++) {
        rv[r] += __shfl_xor_sync(~0u, rv[r], 1);
        rv[r] += __shfl_xor_sync(~0u, rv[r], 2);
    }
    if ((lane & 3) == 0)
#pragma unroll
        for (int r = 0; r < 4; r++)
            red[wn][(r >> 1) * 16 + (lane >> 2) + (r & 1) * 8] = rv[r];
    __syncthreads();
    if (tid < 32) {
        float sval = red[0][tid];
#pragma unroll
        for (int w = 1; w < 8; w++) sval += red[w][tid];
        redc[tid] = 1.0f / sval;
    }
    __syncthreads();
    float rinv[4];
#pragma unroll
    for (int r = 0; r < 4; r++) rinv[r] = redc[(r >> 1) * 16 + (lane >> 2) + (r & 1) * 8];
    __syncthreads();

    __half* stg = (__half*)sm;
#pragma unroll
    for (int mt = 0; mt < 2; mt++)
#pragma unroll
        for (int ntg = 0; ntg < 16; ntg++) {
            int sl = mt * 16 + (lane >> 2);
            int t = (ntg >> 1) * 128 + wn * 16 + (ntg & 1) * 8 + (lane & 3) * 2;
            *(__half2*)&stg[sl * 1040 + t] =
                __floats2half2_rn(acc[mt][ntg][0] * rinv[mt * 2],
                                  acc[mt][ntg][1] * rinv[mt * 2]);
            *(__half2*)&stg[(sl + 8) * 1040 + t] =
                __floats2half2_rn(acc[mt][ntg][2] * rinv[mt * 2 + 1],
                                  acc[mt][ntg][3] * rinv[mt * 2 + 1]);
        }
    __syncthreads();
    for (int i = tid; i < 32 * 128; i += 256) {
        int rr = i >> 7, cc = (i & 127) * 8;
        *(uint4*)&g_wf[wbase + (size_t)(s0 + rr) * 1024 + cc] = *(const uint4*)&stg[rr * 1040 + cc];
    }
}

// ---------------- G5: att = W @ V (1 product, cp.async) ----------------
__global__ __launch_bounds__(256) void g5_pv() {
    extern __shared__ char sm[];
    uint32_t smb = smem_u32(sm);
    constexpr int ATS = 128 * 72 * 2;       // 18432
    constexpr int BTS = 64 * 72 * 2;        // 9216
    constexpr int STG = ATS + BTS;          // 27648
    int bh = blockIdx.y, m0 = blockIdx.x * 128;
    const __half* A = g_wf + (size_t)bh * 1048576 + (size_t)m0 * 1024;
    const __half* Bf = g_vtf + (size_t)bh * 65536;
    float acc[2][4][4] = {};
    auto issue = [&](int c) {
        uint32_t b = smb + (uint32_t)(c & 1) * STG;
        cp_one<128, 64>(b, A + c * 64, 1024);
        cp_one<64, 64>(b + ATS, Bf + c * 64, 1024);
        cp_commit();
    };
    issue(0);
    for (int c = 0; c < 16; c++) {
        if (c < 15) { issue(c + 1); cp_wait<1>(); } else cp_wait<0>();
        __syncthreads();
        uint32_t b = smb + (uint32_t)(c & 1) * STG;
        mma_chunk_h1<2, 2, 4, 72, 72, 4, false>(b, b + ATS, acc);
        __syncthreads();
    }
    int lane = threadIdx.x & 31, wid = threadIdx.x >> 5, wm = wid / 2, wn = wid % 2;
    int b = bh >> 4, h = bh & 15;
#pragma unroll
    for (int mt = 0; mt < 2; mt++)
#pragma unroll
        for (int nt = 0; nt < 4; nt++)
#pragma unroll
            for (int hf = 0; hf < 2; hf++) {
                int s = m0 + wm * 32 + mt * 16 + (lane >> 2) + hf * 8;
                int d = wn * 32 + nt * 8 + (lane & 3) * 2;
                size_t o = ((size_t)(b * 1024 + s)) * 1024 + h * 64 + d;
                float2 vv;
                vv.x = acc[mt][nt][hf * 2];
                vv.y = acc[mt][nt][hf * 2 + 1];
                *(float2*)&g_att[o] = vv;
            }
}

// ---------------- K6: att += W @ EV_s, emit att fp16 (1 product) ----------------
__global__ __launch_bounds__(256) void k6_ev(const float* __restrict__ ev) {
    extern __shared__ char sm[];
    char *aF = sm, *bF = sm + 17408;
    uint32_t aFu = smem_u32(aF), bFu = smem_u32(bF);
    int s = blockIdx.x;
    float acc[1][4][4] = {};
    for (int c = 0; c < 8; c++) {
        load_one<64, 128>(aF, g_wf + (size_t)s * 1024 + c * 128, 1048576);
        load_cvt_h<128, 64>(bF, ev + (size_t)s * 65536 + (size_t)c * 8192, 64);
        __syncthreads();
        mma_chunk_h1<2, 1, 4, 136, 72, 8, true>(aFu, bFu, acc);
        __syncthreads();
    }
    int lane = threadIdx.x & 31, wid = threadIdx.x >> 5, wm = wid / 2, wn = wid % 2;
#pragma unroll
    for (int nt = 0; nt < 4; nt++)
#pragma unroll
        for (int hf = 0; hf < 2; hf++) {
            int bh = wm * 16 + (lane >> 2) + hf * 8;
            int d = wn * 32 + nt * 8 + (lane & 3) * 2;
            int b = bh >> 4, h = bh & 15;
            size_t o = ((size_t)(b * 1024 + s)) * 1024 + h * 64 + d;
            float2 cur = *(float2*)&g_att[o];
            HF2 P;
            P.b[0] = __float2half_rn(cur.x + acc[0][nt][hf * 2]);
            P.b[1] = __float2half_rn(cur.y + acc[0][nt][hf * 2 + 1]);
            *(uint32_t*)&g_attf[o] = P.u;
        }
}

// ---------------- G7: out = att @ Wp^T + bp (1 product, cp.async) ----------------
__global__ __launch_bounds__(256) void g7_out(const float* __restrict__ bp, float* __restrict__ out) {
    extern __shared__ char sm[];
    uint32_t smb = smem_u32(sm);
    constexpr int TS = 128 * 72 * 2;
    constexpr int STG = 2 * TS;
    int m0 = blockIdx.y * 128, n0 = blockIdx.x * 128;
    const __half* Bf = g_wtf + (size_t)3 * 1048576 + (size_t)n0 * 1024;
    float acc[4][4][4] = {};
    auto issue = [&](int c) {
        uint32_t b = smb + (uint32_t)(c & 1) * STG;
        cp_one<128, 64>(b, g_attf + (size_t)m0 * 1024 + c * 64, 1024);
        cp_one<128, 64>(b + TS, Bf + c * 64, 1024);
        cp_commit();
    };
    issue(0);
    for (int c = 0; c < 16; c++) {
        if (c < 15) { issue(c + 1); cp_wait<1>(); } else cp_wait<0>();
        __syncthreads();
        uint32_t b = smb + (uint32_t)(c & 1) * STG;
        mma_chunk_h1<4, 4, 4, 72, 72, 4, false>(b, b + TS, acc);
        __syncthreads();
    }
    int lane = threadIdx.x & 31, wid = threadIdx.x >> 5, wm = wid / 4, wn = wid % 4;
#pragma unroll
    for (int mt = 0; mt < 4; mt++)
#pragma unroll
        for (int nt = 0; nt < 4; nt++)
#pragma unroll
            for (int hf = 0; hf < 2; hf++) {
                int m = m0 + wm * 64 + mt * 16 + (lane >> 2) + hf * 8;
                int n = n0 + wn * 32 + nt * 8 + (lane & 3) * 2;
                float2 bb = *(const float2*)&bp[n];
                float2 vv;
                vv.x = acc[mt][nt][hf * 2] + bb.x;
                vv.y = acc[mt][nt][hf * 2 + 1] + bb.y;
                *(float2*)&out[(size_t)m * 1024 + n] = vv;
            }
}

// ---------------- launch ----------------
extern "C" void kernel_launch(void* const* d_in, const int* in_sizes, int n_in,
                              void* d_out, int out_size) {
    const float* queries     = (const float*)d_in[0];
    const float* keys        = (const float*)d_in[1];
    const float* values      = (const float*)d_in[2];
    const float* edges_key   = (const float*)d_in[3];
    const float* edges_value = (const float*)d_in[4];
    const float* attn_bias   = (const float*)d_in[5];
    const float* Wq = (const float*)d_in[6];  const float* bq = (const float*)d_in[7];
    const float* Wk = (const float*)d_in[8];  const float* bk = (const float*)d_in[9];
    const float* Wv = (const float*)d_in[10]; const float* bv = (const float*)d_in[11];
    const float* Wp = (const float*)d_in[12]; const float* bp = (const float*)d_in[13];

    cudaFuncSetAttribute(g1_qkv,  cudaFuncAttributeMaxDynamicSharedMemorySize, 73728);
    cudaFuncSetAttribute(k3_edge, cudaFuncAttributeMaxDynamicSharedMemorySize, 27648);
    cudaFuncSetAttribute(g2s,     cudaFuncAttributeMaxDynamicSharedMemorySize, 66560);
    cudaFuncSetAttribute(g5_pv,   cudaFuncAttributeMaxDynamicSharedMemorySize, 55296);
    cudaFuncSetAttribute(k6_ev,   cudaFuncAttributeMaxDynamicSharedMemorySize, 35840);
    cudaFuncSetAttribute(g7_out,  cudaFuncAttributeMaxDynamicSharedMemorySize, 73728);

    c0_wt<<<dim3(32, 32, 4), 256>>>(Wq, Wk, Wv, Wp);
    c1_x<<<dim3(4096, 3), 256>>>(queries, keys, values);
    g1_qkv<<<dim3(8, 32, 3), 256, 73728>>>(bq, bk, bv);
    c2_vt<<<dim3(16, 64), 256>>>();
    k3_edge<<<dim3(8, 1024), 256, 27648>>>(edges_key, attn_bias);
    g2s<<<dim3(32, 64), 256, 66560>>>();
    g5_pv<<<dim3(8, 64), 256, 55296>>>();
    k6_ev<<<1024, 256, 35840>>>(edges_value);
    g7_out<<<dim3(8, 32), 256, 73728>>>(bp, (float*)d_out);
}

// round 9
// speedup vs baseline: 3.6258x; 1.1265x over previous
#include <cuda_runtime.h>
#include <cuda_bf16.h>
#include <cuda_fp16.h>
#include <cstdint>

// B=4, S=1024, E=1024, H=16, D=64, BH=64.
// All GEMMs single-fp16 mma.sync m16n8k16, fp32 accum, cp.async pipelines.
// Edge logits + softmax weights stored fp16 in [s][bh][t] layout; attn_bias
// (fp32) added in g2s. No fp32 logits intermediate.

#define DI __device__ __forceinline__

// ---------------- device scratch ----------------
__device__ __align__(128) __half g_we[67108864];                // fp16 edge logits [s][bh][t]
__device__ __align__(128) __half g_wf[67108864];                // fp16 softmax weights [s][bh][t]
__device__ __align__(128) float g_att[4194304];                 // fp32 att [b*s][h*d]
__device__ __align__(128) __half g_xf[3*4194304];               // X fp16 [z][m][k]
__device__ __align__(128) __half g_wtf[4*1048576];              // W^T fp16 [mat][n][k]
__device__ __align__(128) __half g_qf[4194304];                 // [bh][s][d] scaled q
__device__ __align__(128) __half g_kf[4194304];                 // [bh][t][d]
__device__ __align__(128) __half g_vf[4194304];                 // [bh][s][d]
__device__ __align__(128) __half g_vtf[4194304];                // [bh][d][t]
__device__ __align__(128) __half g_attf[4194304];               // att fp16 [b*s][h*d]

// ---------------- helpers ----------------
union HF2 { __half b[2]; uint32_t u; };
union HF4 { __half b[4]; uint2 u; };

DI uint32_t smem_u32(const void* p) {
    uint32_t a;
    asm("{ .reg .u64 t; cvta.to.shared.u64 t, %1; cvt.u32.u64 %0, t; }" : "=r"(a) : "l"(p));
    return a;
}
DI void ldsm4(uint32_t* r, uint32_t a) {
    asm volatile("ldmatrix.sync.aligned.m8n8.x4.shared.b16 {%0,%1,%2,%3}, [%4];"
        : "=r"(r[0]), "=r"(r[1]), "=r"(r[2]), "=r"(r[3]) : "r"(a));
}
DI void ldsm4t(uint32_t* r, uint32_t a) {
    asm volatile("ldmatrix.sync.aligned.m8n8.x4.trans.shared.b16 {%0,%1,%2,%3}, [%4];"
        : "=r"(r[0]), "=r"(r[1]), "=r"(r[2]), "=r"(r[3]) : "r"(a));
}
DI void mma16816h(float* d, const uint32_t* a, const uint32_t* b) {
    asm volatile("mma.sync.aligned.m16n8k16.row.col.f32.f16.f16.f32 "
        "{%0,%1,%2,%3}, {%4,%5,%6,%7}, {%8,%9}, {%0,%1,%2,%3};"
        : "+f"(d[0]), "+f"(d[1]), "+f"(d[2]), "+f"(d[3])
        : "r"(a[0]), "r"(a[1]), "r"(a[2]), "r"(a[3]), "r"(b[0]), "r"(b[1]));
}
DI void cp16(uint32_t d, const void* s) {
    asm volatile("cp.async.cg.shared.global [%0], [%1], 16;" :: "r"(d), "l"(s));
}
DI void cp_commit() { asm volatile("cp.async.commit_group;" ::: "memory"); }
template <int N> DI void cp_wait() {
    asm volatile("cp.async.wait_group %0;" :: "n"(N) : "memory");
}

// cp.async single tile: ROWS x KC 16-bit -> padded smem (stride KC+8)
template <int ROWS, int KC, typename T>
DI void cp_one(uint32_t s, const T* G, size_t ldg) {
    constexpr int SA = KC + 8;
#pragma unroll
    for (int i = threadIdx.x; i < ROWS * KC / 8; i += 256) {
        int r = i / (KC / 8), c = (i % (KC / 8)) * 8;
        cp16(s + (uint32_t)(r * SA + c) * 2, G + (size_t)r * ldg + c);
    }
}
// synchronous single 16-bit tile loader
template <int ROWS, int KC, typename T>
DI void load_one(char* s, const T* G, size_t ldg) {
    constexpr int SA = KC + 8;
#pragma unroll 4
    for (int i = threadIdx.x; i < ROWS * KC / 8; i += 256) {
        int r = i / (KC / 8), c = (i % (KC / 8)) * 8;
        *(uint4*)(s + (r * SA + c) * 2) = *(const uint4*)(G + (size_t)r * ldg + c);
    }
}
// fp32 -> single fp16 converting loader
template <int ROWS, int KC>
DI void load_cvt_h(char* s, const float* G, size_t ldg) {
    constexpr int SA = KC + 8;
#pragma unroll 4
    for (int i = threadIdx.x; i < ROWS * KC / 4; i += 256) {
        int r = i / (KC / 4), c = (i % (KC / 4)) * 4;
        float4 v = *(const float4*)(G + (size_t)r * ldg + c);
        HF4 Hh;
        Hh.b[0] = __float2half_rn(v.x); Hh.b[1] = __float2half_rn(v.y);
        Hh.b[2] = __float2half_rn(v.z); Hh.b[3] = __float2half_rn(v.w);
        *(uint2*)(s + (r * SA + c) * 2) = Hh.u;
    }
}

// fp16 chunk: A single, B single -> 1 product
template <int WN, int MT, int NT, int SA, int SB, int KSTEPS, bool BT>
DI void mma_chunk_h1(uint32_t aF, uint32_t bF, float (&acc)[MT][NT][4]) {
    int lane = threadIdx.x & 31, wid = threadIdx.x >> 5;
    int wm = wid / WN, wn = wid % WN;
#pragma unroll
    for (int kk = 0; kk < KSTEPS; kk++) {
        uint32_t af[MT][4], bf[NT][2];
#pragma unroll
        for (int mt = 0; mt < MT; mt++) {
            uint32_t off = (uint32_t)(((wm * MT * 16 + mt * 16 + (lane & 15)) * SA
                                       + kk * 16 + (lane >> 4) * 8) * 2);
            ldsm4(af[mt], aF + off);
        }
#pragma unroll
        for (int nt = 0; nt < NT; nt += 2) {
            uint32_t off;
            if (BT)
                off = (uint32_t)(((kk * 16 + (lane & 15)) * SB
                                  + wn * NT * 8 + nt * 8 + (lane >> 4) * 8) * 2);
            else
                off = (uint32_t)(((wn * NT * 8 + nt * 8 + ((lane >> 4) << 3) + (lane & 7)) * SB
                                  + kk * 16 + (((lane >> 3) & 1) << 3)) * 2);
            uint32_t r[4];
            if (BT) ldsm4t(r, bF + off); else ldsm4(r, bF + off);
            bf[nt][0] = r[0]; bf[nt][1] = r[1]; bf[nt + 1][0] = r[2]; bf[nt + 1][1] = r[3];
        }
#pragma unroll
        for (int mt = 0; mt < MT; mt++)
#pragma unroll
            for (int nt = 0; nt < NT; nt++)
                mma16816h(acc[mt][nt], af[mt], bf[nt]);
    }
}

// ---------------- conversion kernels ----------------
__global__ __launch_bounds__(256) void c0_wt(const float* Wq, const float* Wk,
                                             const float* Wv, const float* Wp) {
    __shared__ float smt[32][33];
    int mat = blockIdx.z;
    const float* W = mat == 0 ? Wq : mat == 1 ? Wk : mat == 2 ? Wv : Wp;
    int nblk = blockIdx.x * 32, kblk = blockIdx.y * 32;
    for (int i = threadIdx.x; i < 1024; i += 256) {
        int r = i >> 5, c = i & 31;
        smt[r][c] = W[(size_t)(kblk + r) * 1024 + nblk + c];
    }
    __syncthreads();
    for (int i = threadIdx.x; i < 1024; i += 256) {
        int n = i >> 5, k = i & 31;
        size_t o = (size_t)mat * 1048576 + (size_t)(nblk + n) * 1024 + kblk + k;
        g_wtf[o] = __float2half_rn(smt[k][n]);
    }
}
__global__ __launch_bounds__(256) void c1_x(const float* q, const float* k, const float* v) {
    int z = blockIdx.y;
    const float* X = z == 0 ? q : z == 1 ? k : v;
    size_t idx = ((size_t)blockIdx.x * 256 + threadIdx.x) * 4;
    float4 t = *(const float4*)&X[idx];
    HF4 Hh;
    Hh.b[0] = __float2half_rn(t.x); Hh.b[1] = __float2half_rn(t.y);
    Hh.b[2] = __float2half_rn(t.z); Hh.b[3] = __float2half_rn(t.w);
    *(uint2*)&g_xf[(size_t)z * 4194304 + idx] = Hh.u;
}
__global__ __launch_bounds__(256) void c2_vt() {
    __shared__ __half smh[64][65];
    int sblk = blockIdx.x * 64, bh = blockIdx.y;
    size_t ibase = (size_t)bh * 65536;
    for (int i = threadIdx.x; i < 4096; i += 256) {
        int s = i >> 6, d = i & 63;
        smh[s][d] = g_vf[ibase + (size_t)(sblk + s) * 64 + d];
    }
    __syncthreads();
    for (int i = threadIdx.x; i < 4096; i += 256) {
        int d = i >> 6, s = i & 63;
        g_vtf[ibase + (size_t)d * 1024 + sblk + s] = smh[s][d];
    }
}

// ---------------- G1: q/k/v = X @ W^T + b (1 product, cp.async) ----------------
__global__ __launch_bounds__(256) void g1_qkv(const float* bq, const float* bk, const float* bv) {
    extern __shared__ char sm[];
    uint32_t smb = smem_u32(sm);
    constexpr int TS = 128 * 72 * 2;       // 18432 per tile
    constexpr int STG = 2 * TS;            // A + B
    int z = blockIdx.z, m0 = blockIdx.y * 128, n0 = blockIdx.x * 128;
    const __half* Af = g_xf + (size_t)z * 4194304 + (size_t)m0 * 1024;
    const __half* Bf = g_wtf + (size_t)z * 1048576 + (size_t)n0 * 1024;
    float acc[4][4][4] = {};
    auto issue = [&](int c) {
        uint32_t b = smb + (uint32_t)(c & 1) * STG;
        cp_one<128, 64>(b, Af + c * 64, 1024);
        cp_one<128, 64>(b + TS, Bf + c * 64, 1024);
        cp_commit();
    };
    issue(0);
    for (int c = 0; c < 16; c++) {
        if (c < 15) { issue(c + 1); cp_wait<1>(); } else cp_wait<0>();
        __syncthreads();
        uint32_t b = smb + (uint32_t)(c & 1) * STG;
        mma_chunk_h1<4, 4, 4, 72, 72, 4, false>(b, b + TS, acc);
        __syncthreads();
    }
    const float* bias = z == 0 ? bq : z == 1 ? bk : bv;
    float sc = z == 0 ? 0.125f : 1.f;
    __half* dst = z == 0 ? g_qf : z == 1 ? g_kf : g_vf;
    int lane = threadIdx.x & 31, wid = threadIdx.x >> 5, wm = wid / 4, wn = wid % 4;
#pragma unroll
    for (int mt = 0; mt < 4; mt++)
#pragma unroll
        for (int nt = 0; nt < 4; nt++)
#pragma unroll
            for (int hf = 0; hf < 2; hf++) {
                int m = m0 + wm * 64 + mt * 16 + (lane >> 2) + hf * 8;
                int n = n0 + wn * 32 + nt * 8 + (lane & 3) * 2;
                float v0 = (acc[mt][nt][hf * 2] + bias[n]) * sc;
                float v1 = (acc[mt][nt][hf * 2 + 1] + bias[n + 1]) * sc;
                int b = m >> 10, s = m & 1023, h = n >> 6, d = n & 63;
                size_t o = ((size_t)((b << 4) + h) * 1024 + s) * 64 + d;
                HF2 P;
                P.b[0] = __float2half_rn(v0); P.b[1] = __float2half_rn(v1);
                *(uint32_t*)&dst[o] = P.u;
            }
}

// ---------------- K3: g_we[s][bh][t] = fp16 edge-key logits ----------------
__global__ __launch_bounds__(256) void k3_edge(const float* __restrict__ ek) {
    extern __shared__ char sm[];
    char *aF = sm, *bF = sm + 9216;
    uint32_t aFu = smem_u32(aF), bFu = smem_u32(bF);
    int s = blockIdx.y, t0 = blockIdx.x * 128;
    float acc[2][4][4] = {};
    load_one<64, 64>(aF, g_qf + (size_t)s * 64, 65536);
    load_cvt_h<128, 64>(bF, ek + (size_t)s * 65536 + (size_t)t0 * 64, 64);
    __syncthreads();
    mma_chunk_h1<4, 2, 4, 72, 72, 4, false>(aFu, bFu, acc);
    int lane = threadIdx.x & 31, wid = threadIdx.x >> 5, wm = wid / 4, wn = wid % 4;
    size_t sbase = (size_t)s * 65536;
#pragma unroll
    for (int mt = 0; mt < 2; mt++)
#pragma unroll
        for (int nt = 0; nt < 4; nt++)
#pragma unroll
            for (int hf = 0; hf < 2; hf++) {
                int bh = wm * 32 + mt * 16 + (lane >> 2) + hf * 8;
                int t = t0 + wn * 32 + nt * 8 + (lane & 3) * 2;
                HF2 P;
                P.b[0] = __float2half_rn(acc[mt][nt][hf * 2]);
                P.b[1] = __float2half_rn(acc[mt][nt][hf * 2 + 1]);
                *(uint32_t*)&g_we[sbase + (size_t)bh * 1024 + t] = P.u;
            }
}

// ---------------- G2S: content logits + bias + edge + softmax -> fp16 w [s][bh][t] ----------------
__global__ __launch_bounds__(256) void g2s(const float* __restrict__ attn_bias) {
    extern __shared__ char sm[];
    __shared__ float red[8][32];
    __shared__ float redc[32];
    constexpr int KTS = 128 * 72 * 2;       // 18432 per k stage
    uint32_t smb = smem_u32(sm);
    uint32_t qFu = smb;
    int s0 = blockIdx.x * 32, bh = blockIdx.y;
    int tid = threadIdx.x, lane = tid & 31, wn = tid >> 5;

    auto issueK = [&](int it) {
        uint32_t b = smb + 4608 + (uint32_t)(it & 1) * KTS;
        cp_one<128, 64>(b, g_kf + (size_t)bh * 65536 + (size_t)it * 8192, 64);
        cp_commit();
    };
    issueK(0);
    load_one<32, 64>(sm, g_qf + (size_t)bh * 65536 + (size_t)s0 * 64, 64);

    float acc[2][16][4] = {};
    for (int it = 0; it < 8; it++) {
        if (it < 7) { issueK(it + 1); cp_wait<1>(); } else cp_wait<0>();
        __syncthreads();
        uint32_t kFu = smb + 4608 + (uint32_t)(it & 1) * KTS;
#pragma unroll
        for (int kk = 0; kk < 4; kk++) {
            uint32_t ah[2][4], bf2[2][2];
#pragma unroll
            for (int mt = 0; mt < 2; mt++) {
                uint32_t off = (uint32_t)(((mt * 16 + (lane & 15)) * 72
                                           + kk * 16 + (lane >> 4) * 8) * 2);
                ldsm4(ah[mt], qFu + off);
            }
            {
                uint32_t off = (uint32_t)(((wn * 16 + ((lane >> 4) << 3) + (lane & 7)) * 72
                                           + kk * 16 + (((lane >> 3) & 1) << 3)) * 2);
                uint32_t r[4];
                ldsm4(r, kFu + off);
                bf2[0][0] = r[0]; bf2[0][1] = r[1]; bf2[1][0] = r[2]; bf2[1][1] = r[3];
            }
#pragma unroll
            for (int mt = 0; mt < 2; mt++)
#pragma unroll
                for (int ntl = 0; ntl < 2; ntl++)
                    mma16816h(acc[mt][it * 2 + ntl], ah[mt], bf2[ntl]);
        }
        __syncthreads();
    }

    // add attn_bias (fp32, [bh][s][t]) + edge logits (fp16, [s][bh][t])
    size_t bbase = (size_t)bh * 1048576;
#pragma unroll
    for (int mt = 0; mt < 2; mt++)
#pragma unroll
        for (int ntg = 0; ntg < 16; ntg++) {
            int sl = mt * 16 + (lane >> 2);
            int t = (ntg >> 1) * 128 + wn * 16 + (ntg & 1) * 8 + (lane & 3) * 2;
            float2 b0 = *(const float2*)&attn_bias[bbase + (size_t)(s0 + sl) * 1024 + t];
            float2 b1 = *(const float2*)&attn_bias[bbase + (size_t)(s0 + sl + 8) * 1024 + t];
            HF2 e0, e1;
            e0.u = *(const uint32_t*)&g_we[(size_t)(s0 + sl) * 65536 + (size_t)bh * 1024 + t];
            e1.u = *(const uint32_t*)&g_we[(size_t)(s0 + sl + 8) * 65536 + (size_t)bh * 1024 + t];
            acc[mt][ntg][0] += b0.x + __half2float(e0.b[0]);
            acc[mt][ntg][1] += b0.y + __half2float(e0.b[1]);
            acc[mt][ntg][2] += b1.x + __half2float(e1.b[0]);
            acc[mt][ntg][3] += b1.y + __half2float(e1.b[1]);
        }

    float rv[4];
#pragma unroll
    for (int r = 0; r < 4; r++) rv[r] = -1e30f;
#pragma unroll
    for (int mt = 0; mt < 2; mt++)
#pragma unroll
        for (int ntg = 0; ntg < 16; ntg++)
#pragma unroll
            for (int e = 0; e < 4; e++) {
                int r = mt * 2 + (e >> 1);
                rv[r] = fmaxf(rv[r], acc[mt][ntg][e]);
            }
#pragma unroll
    for (int r = 0; r < 4; r++) {
        rv[r] = fmaxf(rv[r], __shfl_xor_sync(~0u, rv[r], 1));
        rv[r] = fmaxf(rv[r], __shfl_xor_sync(~0u, rv[r], 2));
    }
    if ((lane & 3) == 0)
#pragma unroll
        for (int r = 0; r < 4; r++)
            red[wn][(r >> 1) * 16 + (lane >> 2) + (r & 1) * 8] = rv[r];
    __syncthreads();
    if (tid < 32) {
        float m = red[0][tid];
#pragma unroll
        for (int w = 1; w < 8; w++) m = fmaxf(m, red[w][tid]);
        redc[tid] = m;
    }
    __syncthreads();
    float rmax[4];
#pragma unroll
    for (int r = 0; r < 4; r++) rmax[r] = redc[(r >> 1) * 16 + (lane >> 2) + (r & 1) * 8];
    __syncthreads();

#pragma unroll
    for (int r = 0; r < 4; r++) rv[r] = 0.f;
#pragma unroll
    for (int mt = 0; mt < 2; mt++)
#pragma unroll
        for (int ntg = 0; ntg < 16; ntg++)
#pragma unroll
            for (int e = 0; e < 4; e++) {
                int r = mt * 2 + (e >> 1);
                float v = __expf(acc[mt][ntg][e] - rmax[r]);
                acc[mt][ntg][e] = v;
                rv[r] += v;
            }
#pragma unroll
    for (int r = 0; r < 4; r++) {
        rv[r] += __shfl_xor_sync(~0u, rv[r], 1);
        rv[r] += __shfl_xor_sync(~0u, rv[r], 2);
    }
    if ((lane & 3) == 0)
#pragma unroll
        for (int r = 0; r < 4; r++)
            red[wn][(r >> 1) * 16 + (lane >> 2) + (r & 1) * 8] = rv[r];
    __syncthreads();
    if (tid < 32) {
        float sval = red[0][tid];
#pragma unroll
        for (int w = 1; w < 8; w++) sval += red[w][tid];
        redc[tid] = 1.0f / sval;
    }
    __syncthreads();
    float rinv[4];
#pragma unroll
    for (int r = 0; r < 4; r++) rinv[r] = redc[(r >> 1) * 16 + (lane >> 2) + (r & 1) * 8];
    __syncthreads();

    __half* stg = (__half*)sm;
#pragma unroll
    for (int mt = 0; mt < 2; mt++)
#pragma unroll
        for (int ntg = 0; ntg < 16; ntg++) {
            int sl = mt * 16 + (lane >> 2);
            int t = (ntg >> 1) * 128 + wn * 16 + (ntg & 1) * 8 + (lane & 3) * 2;
            *(__half2*)&stg[sl * 1040 + t] =
                __floats2half2_rn(acc[mt][ntg][0] * rinv[mt * 2],
                                  acc[mt][ntg][1] * rinv[mt * 2]);
            *(__half2*)&stg[(sl + 8) * 1040 + t] =
                __floats2half2_rn(acc[mt][ntg][2] * rinv[mt * 2 + 1],
                                  acc[mt][ntg][3] * rinv[mt * 2 + 1]);
        }
    __syncthreads();
    for (int i = tid; i < 32 * 128; i += 256) {
        int rr = i >> 7, cc = (i & 127) * 8;
        *(uint4*)&g_wf[(size_t)(s0 + rr) * 65536 + (size_t)bh * 1024 + cc] =
            *(const uint4*)&stg[rr * 1040 + cc];
    }
}

// ---------------- G5: att = W @ V (1 product, cp.async) ----------------
__global__ __launch_bounds__(256) void g5_pv() {
    extern __shared__ char sm[];
    uint32_t smb = smem_u32(sm);
    constexpr int ATS = 128 * 72 * 2;       // 18432
    constexpr int BTS = 64 * 72 * 2;        // 9216
    constexpr int STG = ATS + BTS;          // 27648
    int bh = blockIdx.y, m0 = blockIdx.x * 128;
    const __half* A = g_wf + (size_t)m0 * 65536 + (size_t)bh * 1024;  // [s][bh][t]
    const __half* Bf = g_vtf + (size_t)bh * 65536;
    float acc[2][4][4] = {};
    auto issue = [&](int c) {
        uint32_t b = smb + (uint32_t)(c & 1) * STG;
        cp_one<128, 64>(b, A + c * 64, 65536);
        cp_one<64, 64>(b + ATS, Bf + c * 64, 1024);
        cp_commit();
    };
    issue(0);
    for (int c = 0; c < 16; c++) {
        if (c < 15) { issue(c + 1); cp_wait<1>(); } else cp_wait<0>();
        __syncthreads();
        uint32_t b = smb + (uint32_t)(c & 1) * STG;
        mma_chunk_h1<2, 2, 4, 72, 72, 4, false>(b, b + ATS, acc);
        __syncthreads();
    }
    int lane = threadIdx.x & 31, wid = threadIdx.x >> 5, wm = wid / 2, wn = wid % 2;
    int b = bh >> 4, h = bh & 15;
#pragma unroll
    for (int mt = 0; mt < 2; mt++)
#pragma unroll
        for (int nt = 0; nt < 4; nt++)
#pragma unroll
            for (int hf = 0; hf < 2; hf++) {
                int s = m0 + wm * 32 + mt * 16 + (lane >> 2) + hf * 8;
                int d = wn * 32 + nt * 8 + (lane & 3) * 2;
                size_t o = ((size_t)(b * 1024 + s)) * 1024 + h * 64 + d;
                float2 vv;
                vv.x = acc[mt][nt][hf * 2];
                vv.y = acc[mt][nt][hf * 2 + 1];
                *(float2*)&g_att[o] = vv;
            }
}

// ---------------- K6: att += W @ EV_s (pipelined ev stream) ----------------
__global__ __launch_bounds__(256) void k6_ev(const float* __restrict__ ev) {
    extern __shared__ char sm[];
    char *aF = sm, *bFh = sm + 17408;
    uint32_t aFu = smem_u32(aF), bFu = smem_u32(bFh);
    uint32_t brawu = smem_u32(sm + 35840);
    int s = blockIdx.x;
    const float* evs = ev + (size_t)s * 65536;
    float acc[1][4][4] = {};
    auto issueB = [&](int c) {
        uint32_t dst = brawu + (uint32_t)(c & 1) * 32768;
        const float* src = evs + (size_t)c * 8192;   // contiguous 32KB chunk
#pragma unroll
        for (int i = threadIdx.x; i < 2048; i += 256)
            cp16(dst + (uint32_t)i * 16, src + i * 4);
        cp_commit();
    };
    issueB(0);
    for (int c = 0; c < 8; c++) {
        // A chunk: w[all 64 bh][t chunk] — contiguous [s][bh][t] layout
        load_one<64, 128>(aF, g_wf + (size_t)s * 65536 + c * 128, 1024);
        if (c < 7) { issueB(c + 1); cp_wait<1>(); } else cp_wait<0>();
        __syncthreads();
        // convert raw fp32 ev chunk -> padded fp16 tile [128 t][64 d] (SB=72)
        const float* bw = (const float*)(sm + 35840 + (c & 1) * 32768);
#pragma unroll
        for (int i = threadIdx.x; i < 2048; i += 256) {
            int r = i >> 4, cc = (i & 15) * 4;
            float4 v = *(const float4*)(bw + r * 64 + cc);
            HF4 Hh;
            Hh.b[0] = __float2half_rn(v.x); Hh.b[1] = __float2half_rn(v.y);
            Hh.b[2] = __float2half_rn(v.z); Hh.b[3] = __float2half_rn(v.w);
            *(uint2*)(bFh + (r * 72 + cc) * 2) = Hh.u;
        }
        __syncthreads();
        mma_chunk_h1<2, 1, 4, 136, 72, 8, true>(aFu, bFu, acc);
        __syncthreads();
    }
    int lane = threadIdx.x & 31, wid = threadIdx.x >> 5, wm = wid / 2, wn = wid % 2;
#pragma unroll
    for (int nt = 0; nt < 4; nt++)
#pragma unroll
        for (int hf = 0; hf < 2; hf++) {
            int bh = wm * 16 + (lane >> 2) + hf * 8;
            int d = wn * 32 + nt * 8 + (lane & 3) * 2;
            int b = bh >> 4, h = bh & 15;
            size_t o = ((size_t)(b * 1024 + s)) * 1024 + h * 64 + d;
            float2 cur = *(float2*)&g_att[o];
            HF2 P;
            P.b[0] = __float2half_rn(cur.x + acc[0][nt][hf * 2]);
            P.b[1] = __float2half_rn(cur.y + acc[0][nt][hf * 2 + 1]);
            *(uint32_t*)&g_attf[o] = P.u;
        }
}

// ---------------- G7: out = att @ Wp^T + bp (1 product, cp.async) ----------------
__global__ __launch_bounds__(256) void g7_out(const float* __restrict__ bp, float* __restrict__ out) {
    extern __shared__ char sm[];
    uint32_t smb = smem_u32(sm);
    constexpr int TS = 128 * 72 * 2;
    constexpr int STG = 2 * TS;
    int m0 = blockIdx.y * 128, n0 = blockIdx.x * 128;
    const __half* Bf = g_wtf + (size_t)3 * 1048576 + (size_t)n0 * 1024;
    float acc[4][4][4] = {};
    auto issue = [&](int c) {
        uint32_t b = smb + (uint32_t)(c & 1) * STG;
        cp_one<128, 64>(b, g_attf + (size_t)m0 * 1024 + c * 64, 1024);
        cp_one<128, 64>(b + TS, Bf + c * 64, 1024);
        cp_commit();
    };
    issue(0);
    for (int c = 0; c < 16; c++) {
        if (c < 15) { issue(c + 1); cp_wait<1>(); } else cp_wait<0>();
        __syncthreads();
        uint32_t b = smb + (uint32_t)(c & 1) * STG;
        mma_chunk_h1<4, 4, 4, 72, 72, 4, false>(b, b + TS, acc);
        __syncthreads();
    }
    int lane = threadIdx.x & 31, wid = threadIdx.x >> 5, wm = wid / 4, wn = wid % 4;
#pragma unroll
    for (int mt = 0; mt < 4; mt++)
#pragma unroll
        for (int nt = 0; nt < 4; nt++)
#pragma unroll
            for (int hf = 0; hf < 2; hf++) {
                int m = m0 + wm * 64 + mt * 16 + (lane >> 2) + hf * 8;
                int n = n0 + wn * 32 + nt * 8 + (lane & 3) * 2;
                float2 bb = *(const float2*)&bp[n];
                float2 vv;
                vv.x = acc[mt][nt][hf * 2] + bb.x;
                vv.y = acc[mt][nt][hf * 2 + 1] + bb.y;
                *(float2*)&out[(size_t)m * 1024 + n] = vv;
            }
}

// ---------------- launch ----------------
extern "C" void kernel_launch(void* const* d_in, const int* in_sizes, int n_in,
                              void* d_out, int out_size) {
    const float* queries     = (const float*)d_in[0];
    const float* keys        = (const float*)d_in[1];
    const float* values      = (const float*)d_in[2];
    const float* edges_key   = (const float*)d_in[3];
    const float* edges_value = (const float*)d_in[4];
    const float* attn_bias   = (const float*)d_in[5];
    const float* Wq = (const float*)d_in[6];  const float* bq = (const float*)d_in[7];
    const float* Wk = (const float*)d_in[8];  const float* bk = (const float*)d_in[9];
    const float* Wv = (const float*)d_in[10]; const float* bv = (const float*)d_in[11];
    const float* Wp = (const float*)d_in[12]; const float* bp = (const float*)d_in[13];

    cudaFuncSetAttribute(g1_qkv,  cudaFuncAttributeMaxDynamicSharedMemorySize, 73728);
    cudaFuncSetAttribute(k3_edge, cudaFuncAttributeMaxDynamicSharedMemorySize, 27648);
    cudaFuncSetAttribute(g2s,     cudaFuncAttributeMaxDynamicSharedMemorySize, 66560);
    cudaFuncSetAttribute(g5_pv,   cudaFuncAttributeMaxDynamicSharedMemorySize, 55296);
    cudaFuncSetAttribute(k6_ev,   cudaFuncAttributeMaxDynamicSharedMemorySize, 101376);
    cudaFuncSetAttribute(g7_out,  cudaFuncAttributeMaxDynamicSharedMemorySize, 73728);

    c0_wt<<<dim3(32, 32, 4), 256>>>(Wq, Wk, Wv, Wp);
    c1_x<<<dim3(4096, 3), 256>>>(queries, keys, values);
    g1_qkv<<<dim3(8, 32, 3), 256, 73728>>>(bq, bk, bv);
    c2_vt<<<dim3(16, 64), 256>>>();
    k3_edge<<<dim3(8, 1024), 256, 27648>>>(edges_key);
    g2s<<<dim3(32, 64), 256, 66560>>>(attn_bias);
    g5_pv<<<dim3(8, 64), 256, 55296>>>();
    k6_ev<<<1024, 256, 101376>>>(edges_value);
    g7_out<<<dim3(8, 32), 256, 73728>>>(bp, (float*)d_out);
}